// round 5
// baseline (speedup 1.0000x reference)
#include <cuda_runtime.h>
#include <math.h>
#include <stdint.h>

#define D_MODEL 1024
#define N_HEADS 16
#define D_KH    64
#define B_SZ    4
#define T_SEQ   2048
#define M_ROWS  (B_SZ * T_SEQ)   // 8192

// Scratch (allocation-free rule: __device__ globals)
__device__ float g_Q[M_ROWS * D_MODEL];
__device__ float g_K[M_ROWS * D_MODEL];
__device__ float g_V[M_ROWS * D_MODEL];
__device__ float g_O[M_ROWS * D_MODEL];

// ---------------------------------------------------------------------------
// Helpers: tf32 mma (3x error-compensated) + cp.async
// ---------------------------------------------------------------------------
__device__ __forceinline__ void mma8(float d[4], const float a[4], const float b[2]) {
    const uint32_t* A = reinterpret_cast<const uint32_t*>(a);
    const uint32_t* B = reinterpret_cast<const uint32_t*>(b);
    asm volatile(
        "mma.sync.aligned.m16n8k8.row.col.f32.tf32.tf32.f32 "
        "{%0,%1,%2,%3}, {%4,%5,%6,%7}, {%8,%9}, {%0,%1,%2,%3};\n"
        : "+f"(d[0]), "+f"(d[1]), "+f"(d[2]), "+f"(d[3])
        : "r"(A[0]), "r"(A[1]), "r"(A[2]), "r"(A[3]), "r"(B[0]), "r"(B[1]));
}

// d += ah*bh + al*bh + ah*bl   (3xTF32: near-fp32 accuracy)
__device__ __forceinline__ void mma3(float d[4], const float ah[4], const float al[4],
                                     const float bh[2], const float bl[2]) {
    mma8(d, ah, bh);
    mma8(d, al, bh);
    mma8(d, ah, bl);
}

__device__ __forceinline__ void split2(float x, float& hi, float& lo) {
    uint32_t hb, lb;
    asm("cvt.rna.tf32.f32 %0, %1;" : "=r"(hb) : "f"(x));
    hi = __uint_as_float(hb);
    float l = x - hi;
    asm("cvt.rna.tf32.f32 %0, %1;" : "=r"(lb) : "f"(l));
    lo = __uint_as_float(lb);
}

__device__ __forceinline__ void cpa16(void* smem_ptr, const void* gptr) {
    uint32_t s = (uint32_t)__cvta_generic_to_shared(smem_ptr);
    asm volatile("cp.async.cg.shared.global [%0], [%1], 16;\n" :: "r"(s), "l"(gptr));
}
__device__ __forceinline__ void cpa_commit() {
    asm volatile("cp.async.commit_group;\n");
}
template <int N>
__device__ __forceinline__ void cpa_wait() {
    asm volatile("cp.async.wait_group %0;\n" :: "n"(N));
}

// ---------------------------------------------------------------------------
// GEMM: C[m][n] = sum_k A[m][k]*Bw[n][k] + bias[n]   (3xTF32 tensor cores)
// 128x128x32 tiles, 256 threads, 8 warps (2m x 4n), warp tile 64x32.
// Smem stride 36 floats -> fragment LDS bank = 4g+q = lane (conflict-free).
// ---------------------------------------------------------------------------
#define GBK     32
#define GSTRIDE 36
#define GTILE   (128 * GSTRIDE)   // floats per buffer per tensor

__global__ void __launch_bounds__(256) gemm_bt_bias(
    const float* __restrict__ A, const float* __restrict__ Bw,
    const float* __restrict__ bias, float* __restrict__ C,
    int M, int N, int K)
{
    extern __shared__ float sm[];
    float* As = sm;               // 2 buffers
    float* Bs = sm + 2 * GTILE;   // 2 buffers

    const int tid  = threadIdx.x;
    const int lane = tid & 31;
    const int wid  = tid >> 5;
    const int g    = lane >> 2;
    const int q    = lane & 3;
    const int wm   = wid >> 2;    // 0..1
    const int wn   = wid & 3;     // 0..3
    const int bm   = blockIdx.y * 128;
    const int bn   = blockIdx.x * 128;

    float acc[4][4][4] = {};

    auto issue = [&](int t, int buf) {
        const int k0 = t * GBK;
        float* ad = As + buf * GTILE;
        float* bd = Bs + buf * GTILE;
#pragma unroll
        for (int i = 0; i < 4; i++) {
            int idx = tid + i * 256;          // 1024 float4s per tensor
            int row = idx >> 3;
            int c4  = idx & 7;
            cpa16(&ad[row * GSTRIDE + c4 * 4],
                  &A[(size_t)(bm + row) * K + k0 + c4 * 4]);
            cpa16(&bd[row * GSTRIDE + c4 * 4],
                  &Bw[(size_t)(bn + row) * K + k0 + c4 * 4]);
        }
    };

    const int NT = K / GBK;   // 32
    issue(0, 0);
    cpa_commit();

    for (int t = 0; t < NT; t++) {
        if (t + 1 < NT) {
            issue(t + 1, (t + 1) & 1);
            cpa_commit();
            cpa_wait<1>();
        } else {
            cpa_wait<0>();
        }
        __syncthreads();

        const float* as = As + (t & 1) * GTILE;
        const float* bs = Bs + (t & 1) * GTILE;
#pragma unroll
        for (int ks = 0; ks < 4; ks++) {
            const int kb = ks * 8;
            float ah[4][4], al[4][4];
#pragma unroll
            for (int mt = 0; mt < 4; mt++) {
                int base = (wm * 64 + mt * 16 + g) * GSTRIDE + kb + q;
                split2(as[base],                  ah[mt][0], al[mt][0]);
                split2(as[base + 8 * GSTRIDE],    ah[mt][1], al[mt][1]);
                split2(as[base + 4],              ah[mt][2], al[mt][2]);
                split2(as[base + 8 * GSTRIDE + 4],ah[mt][3], al[mt][3]);
            }
            float bh[4][2], bl[4][2];
#pragma unroll
            for (int nt = 0; nt < 4; nt++) {
                int base = (wn * 32 + nt * 8 + g) * GSTRIDE + kb + q;
                split2(bs[base],     bh[nt][0], bl[nt][0]);
                split2(bs[base + 4], bh[nt][1], bl[nt][1]);
            }
#pragma unroll
            for (int mt = 0; mt < 4; mt++)
#pragma unroll
                for (int nt = 0; nt < 4; nt++)
                    mma3(acc[mt][nt], ah[mt], al[mt], bh[nt], bl[nt]);
        }
        __syncthreads();
    }

    // epilogue
#pragma unroll
    for (int mt = 0; mt < 4; mt++) {
        int row0 = bm + wm * 64 + mt * 16 + g;
#pragma unroll
        for (int nt = 0; nt < 4; nt++) {
            int col = bn + wn * 32 + nt * 8 + 2 * q;
            float b0 = bias[col], b1 = bias[col + 1];
            float2 r0 = { acc[mt][nt][0] + b0, acc[mt][nt][1] + b1 };
            float2 r1 = { acc[mt][nt][2] + b0, acc[mt][nt][3] + b1 };
            *(float2*)&C[(size_t)row0 * N + col]       = r0;
            *(float2*)&C[(size_t)(row0 + 8) * N + col] = r1;
        }
    }
}

// ---------------------------------------------------------------------------
// Causal flash attention, 3xTF32 tensor cores.
// Grid (T/64, B*H). 128 threads = 4 warps; each warp owns 16 query rows.
// Q hi/lo fragments hoisted to registers; K/V double-buffered via cp.async;
// P routed through padded smem (stride 76 -> conflict-free frag reloads).
// ---------------------------------------------------------------------------
#define QSTR 68
#define KSTR 68
#define VSTR 72
#define PSTR 76
#define Q_OFF 0
#define P_OFF (64 * QSTR)                     // 4352
#define K_OFF (P_OFF + 64 * PSTR)             // 9216
#define V_OFF (K_OFF + 2 * 64 * KSTR)         // 17920
#define ATTN_SMEM_FLOATS (V_OFF + 2 * 64 * VSTR)  // 27136
#define KBUF(b) (K_OFF + (b) * 64 * KSTR)
#define VBUF(b) (V_OFF + (b) * 64 * VSTR)

__global__ void __launch_bounds__(128) attn_causal()
{
    extern __shared__ float sm[];

    const int qb = blockIdx.x;          // query block (64 rows)
    const int bh = blockIdx.y;
    const int b  = bh / N_HEADS;
    const int h  = bh % N_HEADS;

    const int tid  = threadIdx.x;
    const int lane = tid & 31;
    const int wq   = tid >> 5;          // warp -> 16-row slice
    const int g    = lane >> 2;
    const int q    = lane & 3;

    const float scale = 0.125f;

    const float* Qg = g_Q + (size_t)(b * T_SEQ) * D_MODEL + h * D_KH;
    const float* Kg = g_K + (size_t)(b * T_SEQ) * D_MODEL + h * D_KH;
    const float* Vg = g_V + (size_t)(b * T_SEQ) * D_MODEL + h * D_KH;

    auto stage_kv = [&](int kb, int buf) {
        float* kd = sm + KBUF(buf);
        float* vd = sm + VBUF(buf);
#pragma unroll
        for (int i = 0; i < 8; i++) {
            int idx = tid + i * 128;    // 1024 float4s
            int row = idx >> 4;
            int c4  = idx & 15;
            cpa16(&kd[row * KSTR + c4 * 4],
                  &Kg[(size_t)(kb * 64 + row) * D_MODEL + c4 * 4]);
            cpa16(&vd[row * VSTR + c4 * 4],
                  &Vg[(size_t)(kb * 64 + row) * D_MODEL + c4 * 4]);
        }
    };

    // stage Q (group 0), stage KV block 0 (group 1)
    {
        float* qd = sm + Q_OFF;
#pragma unroll
        for (int i = 0; i < 8; i++) {
            int idx = tid + i * 128;
            int row = idx >> 4;
            int c4  = idx & 15;
            cpa16(&qd[row * QSTR + c4 * 4],
                  &Qg[(size_t)(qb * 64 + row) * D_MODEL + c4 * 4]);
        }
        cpa_commit();
        stage_kv(0, 0);
        cpa_commit();
    }

    // wait for Q, load + split Q fragments (held for the whole kernel)
    cpa_wait<1>();
    __syncthreads();
    float qh[8][4], ql[8][4];
    {
        const float* qs = sm + Q_OFF;
#pragma unroll
        for (int kt = 0; kt < 8; kt++) {
            int base = (wq * 16 + g) * QSTR + kt * 8 + q;
            split2(qs[base],                 qh[kt][0], ql[kt][0]);
            split2(qs[base + 8 * QSTR],      qh[kt][1], ql[kt][1]);
            split2(qs[base + 4],             qh[kt][2], ql[kt][2]);
            split2(qs[base + 8 * QSTR + 4],  qh[kt][3], ql[kt][3]);
        }
    }

    float of[8][4] = {};
    float m0 = -INFINITY, m1 = -INFINITY, l0 = 0.f, l1 = 0.f;

    for (int kb = 0; kb <= qb; kb++) {
        if (kb + 1 <= qb) {
            stage_kv(kb + 1, (kb + 1) & 1);
            cpa_commit();
            cpa_wait<1>();
        } else {
            cpa_wait<0>();
        }
        __syncthreads();

        const float* ks = sm + KBUF(kb & 1);
        const float* vs = sm + VBUF(kb & 1);

        // S = Q K^T  (16x64 per warp), 3xTF32
        float sf[8][4] = {};
#pragma unroll
        for (int kt = 0; kt < 8; kt++) {
#pragma unroll
            for (int nt = 0; nt < 8; nt++) {
                float bhf[2], blf[2];
                int base = (nt * 8 + g) * KSTR + kt * 8 + q;
                split2(ks[base],     bhf[0], blf[0]);
                split2(ks[base + 4], bhf[1], blf[1]);
                mma3(sf[nt], qh[kt], ql[kt], bhf, blf);
            }
        }

        // mask (diagonal block only) + scale
        if (kb == qb) {
            int r0 = wq * 16 + g, r1 = r0 + 8;
#pragma unroll
            for (int nt = 0; nt < 8; nt++) {
                int c0 = nt * 8 + 2 * q, c1 = c0 + 1;
                if (c0 > r0) sf[nt][0] = -INFINITY;
                if (c1 > r0) sf[nt][1] = -INFINITY;
                if (c0 > r1) sf[nt][2] = -INFINITY;
                if (c1 > r1) sf[nt][3] = -INFINITY;
            }
        }
#pragma unroll
        for (int nt = 0; nt < 8; nt++) {
            sf[nt][0] *= scale; sf[nt][1] *= scale;
            sf[nt][2] *= scale; sf[nt][3] *= scale;
        }

        // online softmax (rows g and g+8 of the warp's 16)
        float mx0 = -INFINITY, mx1 = -INFINITY;
#pragma unroll
        for (int nt = 0; nt < 8; nt++) {
            mx0 = fmaxf(mx0, fmaxf(sf[nt][0], sf[nt][1]));
            mx1 = fmaxf(mx1, fmaxf(sf[nt][2], sf[nt][3]));
        }
        mx0 = fmaxf(mx0, __shfl_xor_sync(0xffffffffu, mx0, 1));
        mx0 = fmaxf(mx0, __shfl_xor_sync(0xffffffffu, mx0, 2));
        mx1 = fmaxf(mx1, __shfl_xor_sync(0xffffffffu, mx1, 1));
        mx1 = fmaxf(mx1, __shfl_xor_sync(0xffffffffu, mx1, 2));

        float mn0 = fmaxf(m0, mx0), mn1 = fmaxf(m1, mx1);
        float c0 = __expf(m0 - mn0), c1 = __expf(m1 - mn1);
        m0 = mn0; m1 = mn1;

        float ls0 = 0.f, ls1 = 0.f;
        float* ps = sm + P_OFF;
#pragma unroll
        for (int nt = 0; nt < 8; nt++) {
            float p0 = __expf(sf[nt][0] - mn0);
            float p1 = __expf(sf[nt][1] - mn0);
            float p2 = __expf(sf[nt][2] - mn1);
            float p3 = __expf(sf[nt][3] - mn1);
            ls0 += p0 + p1; ls1 += p2 + p3;
            int col = nt * 8 + 2 * q;
            *(float2*)&ps[(wq * 16 + g) * PSTR + col]     = make_float2(p0, p1);
            *(float2*)&ps[(wq * 16 + g + 8) * PSTR + col] = make_float2(p2, p3);
            of[nt][0] *= c0; of[nt][1] *= c0;
            of[nt][2] *= c1; of[nt][3] *= c1;
        }
        ls0 += __shfl_xor_sync(0xffffffffu, ls0, 1);
        ls0 += __shfl_xor_sync(0xffffffffu, ls0, 2);
        ls1 += __shfl_xor_sync(0xffffffffu, ls1, 1);
        ls1 += __shfl_xor_sync(0xffffffffu, ls1, 2);
        l0 = l0 * c0 + ls0;
        l1 = l1 * c1 + ls1;
        __syncwarp();

        // O += P V  (3xTF32)
#pragma unroll
        for (int jt = 0; jt < 8; jt++) {
            float pah[4], pal[4];
            int pb = (wq * 16 + g) * PSTR + jt * 8 + q;
            split2(ps[pb],                pah[0], pal[0]);
            split2(ps[pb + 8 * PSTR],     pah[1], pal[1]);
            split2(ps[pb + 4],            pah[2], pal[2]);
            split2(ps[pb + 8 * PSTR + 4], pah[3], pal[3]);
#pragma unroll
            for (int nt = 0; nt < 8; nt++) {
                float vbh[2], vbl[2];
                int base = (jt * 8 + q) * VSTR + nt * 8 + g;
                split2(vs[base],            vbh[0], vbl[0]);
                split2(vs[base + 4 * VSTR], vbh[1], vbl[1]);
                mma3(of[nt], pah, pal, vbh, vbl);
            }
        }
        __syncthreads();
    }

    // normalize + store (heads re-merged)
    float inv0 = 1.0f / l0, inv1 = 1.0f / l1;
    int row0 = qb * 64 + wq * 16 + g;
    float* dst0 = g_O + (size_t)(b * T_SEQ + row0) * D_MODEL + h * D_KH;
    float* dst1 = dst0 + 8 * D_MODEL;
#pragma unroll
    for (int nt = 0; nt < 8; nt++) {
        int col = nt * 8 + 2 * q;
        *(float2*)&dst0[col] = make_float2(of[nt][0] * inv0, of[nt][1] * inv0);
        *(float2*)&dst1[col] = make_float2(of[nt][2] * inv1, of[nt][3] * inv1);
    }
}

// ---------------------------------------------------------------------------
extern "C" void kernel_launch(void* const* d_in, const int* in_sizes, int n_in,
                              void* d_out, int out_size)
{
    const float* q   = (const float*)d_in[0];
    const float* k   = (const float*)d_in[1];
    const float* v   = (const float*)d_in[2];
    // d_in[3] = mask (bool causal tril) — causality hardcoded in attn_causal
    const float* W_q = (const float*)d_in[4];
    const float* b_q = (const float*)d_in[5];
    const float* W_k = (const float*)d_in[6];
    const float* b_k = (const float*)d_in[7];
    const float* W_v = (const float*)d_in[8];
    const float* b_v = (const float*)d_in[9];
    const float* W_o = (const float*)d_in[10];
    const float* b_o = (const float*)d_in[11];
    float* out = (float*)d_out;

    float *pQ, *pK, *pV, *pO;
    cudaGetSymbolAddress((void**)&pQ, g_Q);
    cudaGetSymbolAddress((void**)&pK, g_K);
    cudaGetSymbolAddress((void**)&pV, g_V);
    cudaGetSymbolAddress((void**)&pO, g_O);

    const int gemm_smem = 4 * GTILE * (int)sizeof(float);          // 73728
    const int attn_smem = ATTN_SMEM_FLOATS * (int)sizeof(float);   // 108544
    cudaFuncSetAttribute(gemm_bt_bias, cudaFuncAttributeMaxDynamicSharedMemorySize,
                         gemm_smem);
    cudaFuncSetAttribute(attn_causal, cudaFuncAttributeMaxDynamicSharedMemorySize,
                         attn_smem);

    dim3 gGrid(D_MODEL / 128, M_ROWS / 128);   // (8, 64)
    gemm_bt_bias<<<gGrid, 256, gemm_smem>>>(q, W_q, b_q, pQ, M_ROWS, D_MODEL, D_MODEL);
    gemm_bt_bias<<<gGrid, 256, gemm_smem>>>(k, W_k, b_k, pK, M_ROWS, D_MODEL, D_MODEL);
    gemm_bt_bias<<<gGrid, 256, gemm_smem>>>(v, W_v, b_v, pV, M_ROWS, D_MODEL, D_MODEL);

    dim3 aGrid(T_SEQ / 64, B_SZ * N_HEADS);    // (32, 64)
    attn_causal<<<aGrid, 128, attn_smem>>>();

    gemm_bt_bias<<<gGrid, 256, gemm_smem>>>(pO, W_o, b_o, out, M_ROWS, D_MODEL, D_MODEL);
}

// round 6
// speedup vs baseline: 1.7010x; 1.7010x over previous
#include <cuda_runtime.h>
#include <cuda_bf16.h>
#include <math.h>
#include <stdint.h>

#define D_MODEL 1024
#define N_HEADS 16
#define B_SZ    4
#define T_SEQ   2048
#define M_ROWS  8192

typedef unsigned int u32;

// bf16 hi/lo scratch (allocation-free rule: __device__ globals)
__device__ __nv_bfloat16 g_iqh[M_ROWS * D_MODEL], g_iql[M_ROWS * D_MODEL];
__device__ __nv_bfloat16 g_ikh[M_ROWS * D_MODEL], g_ikl[M_ROWS * D_MODEL];
__device__ __nv_bfloat16 g_ivh[M_ROWS * D_MODEL], g_ivl[M_ROWS * D_MODEL];
__device__ __nv_bfloat16 g_wqh[D_MODEL * D_MODEL], g_wql[D_MODEL * D_MODEL];
__device__ __nv_bfloat16 g_wkh[D_MODEL * D_MODEL], g_wkl[D_MODEL * D_MODEL];
__device__ __nv_bfloat16 g_wvh[D_MODEL * D_MODEL], g_wvl[D_MODEL * D_MODEL];
__device__ __nv_bfloat16 g_woh[D_MODEL * D_MODEL], g_wol[D_MODEL * D_MODEL];
__device__ __nv_bfloat16 g_pqh[M_ROWS * D_MODEL], g_pql[M_ROWS * D_MODEL];
__device__ __nv_bfloat16 g_pkh[M_ROWS * D_MODEL], g_pkl[M_ROWS * D_MODEL];
__device__ float         g_V  [M_ROWS * D_MODEL];
__device__ __nv_bfloat16 g_vth[M_ROWS * D_MODEL], g_vtl[M_ROWS * D_MODEL]; // [bh][64][2048]
__device__ __nv_bfloat16 g_aoh[M_ROWS * D_MODEL], g_aol[M_ROWS * D_MODEL];

// ---------------------------------------------------------------------------
// pack bf16x2 hi/lo split of (x0,x1): lower half = x0 (even index)
__device__ __forceinline__ void bsplit2(float x0, float x1, u32& hi, u32& lo) {
    u32 h;
    asm("cvt.rn.bf16x2.f32 %0, %1, %2;" : "=r"(h) : "f"(x1), "f"(x0));
    float h0 = __uint_as_float(h << 16);
    float h1 = __uint_as_float(h & 0xffff0000u);
    u32 l;
    float r0 = x0 - h0, r1 = x1 - h1;
    asm("cvt.rn.bf16x2.f32 %0, %1, %2;" : "=r"(l) : "f"(r1), "f"(r0));
    hi = h; lo = l;
}

__device__ __forceinline__ void bmma(float d[4], const u32 a[4], u32 b0, u32 b1) {
    asm volatile(
        "mma.sync.aligned.m16n8k16.row.col.f32.bf16.bf16.f32 "
        "{%0,%1,%2,%3}, {%4,%5,%6,%7}, {%8,%9}, {%0,%1,%2,%3};\n"
        : "+f"(d[0]), "+f"(d[1]), "+f"(d[2]), "+f"(d[3])
        : "r"(a[0]), "r"(a[1]), "r"(a[2]), "r"(a[3]), "r"(b0), "r"(b1));
}

__device__ __forceinline__ void cpa16(void* smem_ptr, const void* gptr) {
    u32 s = (u32)__cvta_generic_to_shared(smem_ptr);
    asm volatile("cp.async.cg.shared.global [%0], [%1], 16;\n" :: "r"(s), "l"(gptr));
}
__device__ __forceinline__ void cpa_commit() { asm volatile("cp.async.commit_group;\n"); }
template <int N>
__device__ __forceinline__ void cpa_wait() { asm volatile("cp.async.wait_group %0;\n" :: "n"(N)); }

// ---------------------------------------------------------------------------
__global__ void __launch_bounds__(256) split_kernel(
    const float4* __restrict__ src, u32* __restrict__ dh, u32* __restrict__ dl, int n4)
{
    int i = blockIdx.x * 256 + threadIdx.x;
    if (i >= n4) return;
    float4 v = src[i];
    u32 h0, l0, h1, l1;
    bsplit2(v.x, v.y, h0, l0);
    bsplit2(v.z, v.w, h1, l1);
    dh[2 * i] = h0; dh[2 * i + 1] = h1;
    dl[2 * i] = l0; dl[2 * i + 1] = l1;
}

// transpose + split V per head: g_V[b][t][h*64+d] -> vth/vtl[bh][d][t]
__global__ void __launch_bounds__(256) vtrans_kernel()
{
    __shared__ float ts[32][65];
    const int j0 = blockIdx.x * 32;
    const int bh = blockIdx.y;
    const int b = bh >> 4, h = bh & 15;
    const int tid = threadIdx.x;
#pragma unroll
    for (int i = 0; i < 8; i++) {
        int idx = tid + i * 256;           // 2048 = 32 j x 64 d
        int r = idx >> 6, c = idx & 63;
        ts[r][c] = g_V[(size_t)(b * T_SEQ + j0 + r) * D_MODEL + h * 64 + c];
    }
    __syncthreads();
    u32* oh = reinterpret_cast<u32*>(g_vth);
    u32* ol = reinterpret_cast<u32*>(g_vtl);
#pragma unroll
    for (int i = 0; i < 4; i++) {
        int idx = tid + i * 256;           // 1024 = 64 d x 16 j-pairs
        int d = idx >> 4, jj = (idx & 15) * 2;
        u32 h2, l2;
        bsplit2(ts[jj][d], ts[jj + 1][d], h2, l2);
        size_t o = ((size_t)(bh * 64 + d) * T_SEQ + j0 + jj) >> 1;
        oh[o] = h2; ol[o] = l2;
    }
}

// ---------------------------------------------------------------------------
// GEMM: C[m][n] = sum_k A[m][k]*B[n][k] + bias[n], 3xBF16 pre-split operands.
// 128x128x32 tiles, 256 thr, warp tile 64x32. Staged rows: 16 data words + 4 pad.
// ---------------------------------------------------------------------------
#define GKW 20
#define GT  (128 * GKW)

template <bool SPLIT_OUT>
__global__ void __launch_bounds__(256) gemm_bf16(
    const __nv_bfloat16* __restrict__ Ah, const __nv_bfloat16* __restrict__ Al,
    const __nv_bfloat16* __restrict__ Bh, const __nv_bfloat16* __restrict__ Bl,
    const float* __restrict__ bias,
    float* __restrict__ Cf, u32* __restrict__ Ch, u32* __restrict__ Cl,
    int M, int N, int K)
{
    extern __shared__ u32 smw[];   // [2 buf][Ah,Al,Bh,Bl][GT]

    const int tid  = threadIdx.x;
    const int lane = tid & 31;
    const int wid  = tid >> 5;
    const int g    = lane >> 2;
    const int q    = lane & 3;
    const int wm   = wid >> 2;
    const int wn   = wid & 3;
    const int bm   = blockIdx.y * 128;
    const int bn   = blockIdx.x * 128;

    float acc[4][4][4] = {};

    auto issue = [&](int t, int buf) {
        const int k0 = t * 32;
        u32* base = smw + buf * 4 * GT;
#pragma unroll
        for (int i = 0; i < 8; i++) {
            int idx = tid + i * 256;
            int arr = idx >> 9;
            int w   = idx & 511;
            int row = w >> 2, c = w & 3;
            const __nv_bfloat16* gp;
            int rb;
            if      (arr == 0) { gp = Ah; rb = bm; }
            else if (arr == 1) { gp = Al; rb = bm; }
            else if (arr == 2) { gp = Bh; rb = bn; }
            else               { gp = Bl; rb = bn; }
            cpa16(base + arr * GT + row * GKW + c * 4,
                  gp + (size_t)(rb + row) * K + k0 + c * 8);
        }
    };

    const int NT = K / 32;
    issue(0, 0);
    cpa_commit();

    for (int t = 0; t < NT; t++) {
        if (t + 1 < NT) {
            issue(t + 1, (t + 1) & 1);
            cpa_commit();
            cpa_wait<1>();
        } else {
            cpa_wait<0>();
        }
        __syncthreads();

        const u32* ash = smw + (t & 1) * 4 * GT;
        const u32* asl = ash + GT;
        const u32* bsh = ash + 2 * GT;
        const u32* bsl = ash + 3 * GT;

#pragma unroll
        for (int ks = 0; ks < 2; ks++) {
            u32 ah[4][4], al[4][4];
#pragma unroll
            for (int mt = 0; mt < 4; mt++) {
                int bi = (wm * 64 + mt * 16 + g) * GKW + ks * 8 + q;
                ah[mt][0] = ash[bi];               al[mt][0] = asl[bi];
                ah[mt][1] = ash[bi + 8 * GKW];     al[mt][1] = asl[bi + 8 * GKW];
                ah[mt][2] = ash[bi + 4];           al[mt][2] = asl[bi + 4];
                ah[mt][3] = ash[bi + 8 * GKW + 4]; al[mt][3] = asl[bi + 8 * GKW + 4];
            }
            u32 bh[4][2], bl[4][2];
#pragma unroll
            for (int nt = 0; nt < 4; nt++) {
                int bi = (wn * 32 + nt * 8 + g) * GKW + ks * 8 + q;
                bh[nt][0] = bsh[bi]; bh[nt][1] = bsh[bi + 4];
                bl[nt][0] = bsl[bi]; bl[nt][1] = bsl[bi + 4];
            }
#pragma unroll
            for (int mt = 0; mt < 4; mt++)
#pragma unroll
                for (int nt = 0; nt < 4; nt++) {
                    bmma(acc[mt][nt], ah[mt], bh[nt][0], bh[nt][1]);
                    bmma(acc[mt][nt], al[mt], bh[nt][0], bh[nt][1]);
                    bmma(acc[mt][nt], ah[mt], bl[nt][0], bl[nt][1]);
                }
        }
        __syncthreads();
    }

#pragma unroll
    for (int mt = 0; mt < 4; mt++) {
        int row0 = bm + wm * 64 + mt * 16 + g;
#pragma unroll
        for (int nt = 0; nt < 4; nt++) {
            int col = bn + wn * 32 + nt * 8 + 2 * q;
            float b0 = bias[col], b1 = bias[col + 1];
            float v00 = acc[mt][nt][0] + b0, v01 = acc[mt][nt][1] + b1;
            float v10 = acc[mt][nt][2] + b0, v11 = acc[mt][nt][3] + b1;
            if (SPLIT_OUT) {
                u32 h2, l2;
                size_t o0 = ((size_t)row0 * N + col) >> 1;
                size_t o1 = ((size_t)(row0 + 8) * N + col) >> 1;
                bsplit2(v00, v01, h2, l2); Ch[o0] = h2; Cl[o0] = l2;
                bsplit2(v10, v11, h2, l2); Ch[o1] = h2; Cl[o1] = l2;
            } else {
                *(float2*)&Cf[(size_t)row0 * N + col]       = make_float2(v00, v01);
                *(float2*)&Cf[(size_t)(row0 + 8) * N + col] = make_float2(v10, v11);
            }
        }
    }
}

// ---------------------------------------------------------------------------
// Causal flash attention, 3xBF16, pre-split Q/K/Vt, P in registers.
// Grid (T/128, B*H), 256 thr = 8 warps x 16 q-rows.
// ---------------------------------------------------------------------------
#define ASTR 36
#define ATILE (64 * ASTR)       // 2304 words
#define KH_OFF(b) ((b) * ATILE)
#define KL_OFF(b) (2 * ATILE + (b) * ATILE)
#define VH_OFF(b) (4 * ATILE + (b) * ATILE)
#define VL_OFF(b) (6 * ATILE + (b) * ATILE)
#define ATTN_SMEM_W (8 * ATILE) // 18432 words = 73728 B

__global__ void __launch_bounds__(256) attn_causal()
{
    extern __shared__ u32 smw[];

    const int qb = gridDim.x - 1 - blockIdx.x;   // heavy blocks first
    const int bh = blockIdx.y;
    const int b  = bh >> 4;
    const int h  = bh & 15;

    const int tid  = threadIdx.x;
    const int lane = tid & 31;
    const int wq   = tid >> 5;
    const int g    = lane >> 2;
    const int q    = lane & 3;

    const float scale = 0.125f;
    const u32* kh_g = reinterpret_cast<const u32*>(g_pkh);
    const u32* kl_g = reinterpret_cast<const u32*>(g_pkl);
    const u32* vh_g = reinterpret_cast<const u32*>(g_vth);
    const u32* vl_g = reinterpret_cast<const u32*>(g_vtl);

    // ---- stage Q (128 rows x 32 words, hi+lo) into smem, load fragments ----
    {
        const u32* qh_g = reinterpret_cast<const u32*>(g_pqh);
        const u32* ql_g = reinterpret_cast<const u32*>(g_pql);
#pragma unroll
        for (int i = 0; i < 8; i++) {
            int idx = tid + i * 256;         // 2048
            int arr = idx >> 10;
            int w   = idx & 1023;
            int row = w >> 3, c = w & 7;
            const u32* gp = arr ? ql_g : qh_g;
            cpa16(smw + arr * (128 * ASTR) + row * ASTR + c * 4,
                  gp + (((size_t)(b * T_SEQ + qb * 128 + row) * D_MODEL + h * 64) >> 1) + c * 4);
        }
        cpa_commit();
        cpa_wait<0>();
        __syncthreads();
    }
    u32 qh[4][4], ql[4][4];
    {
        const u32* qsh = smw;
        const u32* qsl = smw + 128 * ASTR;
#pragma unroll
        for (int kt = 0; kt < 4; kt++) {
            int bi = (wq * 16 + g) * ASTR + kt * 8 + q;
            qh[kt][0] = qsh[bi];               ql[kt][0] = qsl[bi];
            qh[kt][1] = qsh[bi + 8 * ASTR];    ql[kt][1] = qsl[bi + 8 * ASTR];
            qh[kt][2] = qsh[bi + 4];           ql[kt][2] = qsl[bi + 4];
            qh[kt][3] = qsh[bi + 8 * ASTR + 4];ql[kt][3] = qsl[bi + 8 * ASTR + 4];
        }
    }
    __syncthreads();   // Q region reused by K/V staging

    auto stage_kv = [&](int kb, int buf) {
#pragma unroll
        for (int i = 0; i < 4; i++) {        // K hi/lo: 1024 cpa
            int idx = tid + i * 256;
            int arr = idx >> 9;
            int w   = idx & 511;
            int row = w >> 3, c = w & 7;
            const u32* gp = arr ? kl_g : kh_g;
            cpa16(smw + (arr ? KL_OFF(buf) : KH_OFF(buf)) + row * ASTR + c * 4,
                  gp + (((size_t)(b * T_SEQ + kb * 64 + row) * D_MODEL + h * 64) >> 1) + c * 4);
        }
#pragma unroll
        for (int i = 0; i < 4; i++) {        // Vt hi/lo: 1024 cpa
            int idx = tid + i * 256;
            int arr = idx >> 9;
            int w   = idx & 511;
            int row = w >> 3, c = w & 7;     // row = d
            const u32* gp = arr ? vl_g : vh_g;
            cpa16(smw + (arr ? VL_OFF(buf) : VH_OFF(buf)) + row * ASTR + c * 4,
                  gp + (((size_t)(bh * 64 + row) * T_SEQ + kb * 64) >> 1) + c * 4);
        }
    };

    stage_kv(0, 0);
    cpa_commit();

    float of[8][4] = {};
    float m0 = -INFINITY, m1 = -INFINITY, l0 = 0.f, l1 = 0.f;
    const int R = qb * 128 + wq * 16;        // warp's first q row
    const int kbmax = 2 * qb + 1;

    for (int kb = 0; kb <= kbmax; kb++) {
        if (kb + 1 <= kbmax) {
            stage_kv(kb + 1, (kb + 1) & 1);
            cpa_commit();
            cpa_wait<1>();
        } else {
            cpa_wait<0>();
        }
        __syncthreads();

        const bool active = (kb * 64 <= R + 15);
        if (active) {
            const u32* ksh = smw + KH_OFF(kb & 1);
            const u32* ksl = smw + KL_OFF(kb & 1);
            const u32* vsh = smw + VH_OFF(kb & 1);
            const u32* vsl = smw + VL_OFF(kb & 1);

            // S = Q K^T
            float sf[8][4] = {};
#pragma unroll
            for (int kt = 0; kt < 4; kt++) {
#pragma unroll
                for (int nt = 0; nt < 8; nt++) {
                    int bi = (nt * 8 + g) * ASTR + kt * 8 + q;
                    u32 kb0 = ksh[bi], kb1 = ksh[bi + 4];
                    u32 kl0 = ksl[bi], kl1 = ksl[bi + 4];
                    bmma(sf[nt], qh[kt], kb0, kb1);
                    bmma(sf[nt], ql[kt], kb0, kb1);
                    bmma(sf[nt], qh[kt], kl0, kl1);
                }
            }

            // mask + scale
            if (kb * 64 + 63 > R) {
                int r0 = R + g, r1 = r0 + 8;
#pragma unroll
                for (int nt = 0; nt < 8; nt++) {
                    int c0 = kb * 64 + nt * 8 + 2 * q, c1 = c0 + 1;
                    if (c0 > r0) sf[nt][0] = -INFINITY;
                    if (c1 > r0) sf[nt][1] = -INFINITY;
                    if (c0 > r1) sf[nt][2] = -INFINITY;
                    if (c1 > r1) sf[nt][3] = -INFINITY;
                }
            }
#pragma unroll
            for (int nt = 0; nt < 8; nt++) {
                sf[nt][0] *= scale; sf[nt][1] *= scale;
                sf[nt][2] *= scale; sf[nt][3] *= scale;
            }

            // online softmax; p left in sf
            float mx0 = -INFINITY, mx1 = -INFINITY;
#pragma unroll
            for (int nt = 0; nt < 8; nt++) {
                mx0 = fmaxf(mx0, fmaxf(sf[nt][0], sf[nt][1]));
                mx1 = fmaxf(mx1, fmaxf(sf[nt][2], sf[nt][3]));
            }
            mx0 = fmaxf(mx0, __shfl_xor_sync(0xffffffffu, mx0, 1));
            mx0 = fmaxf(mx0, __shfl_xor_sync(0xffffffffu, mx0, 2));
            mx1 = fmaxf(mx1, __shfl_xor_sync(0xffffffffu, mx1, 1));
            mx1 = fmaxf(mx1, __shfl_xor_sync(0xffffffffu, mx1, 2));

            float mn0 = fmaxf(m0, mx0), mn1 = fmaxf(m1, mx1);
            float c0 = __expf(m0 - mn0), c1 = __expf(m1 - mn1);
            m0 = mn0; m1 = mn1;

            float ls0 = 0.f, ls1 = 0.f;
#pragma unroll
            for (int nt = 0; nt < 8; nt++) {
                sf[nt][0] = __expf(sf[nt][0] - mn0);
                sf[nt][1] = __expf(sf[nt][1] - mn0);
                sf[nt][2] = __expf(sf[nt][2] - mn1);
                sf[nt][3] = __expf(sf[nt][3] - mn1);
                ls0 += sf[nt][0] + sf[nt][1];
                ls1 += sf[nt][2] + sf[nt][3];
                of[nt][0] *= c0; of[nt][1] *= c0;
                of[nt][2] *= c1; of[nt][3] *= c1;
            }
            ls0 += __shfl_xor_sync(0xffffffffu, ls0, 1);
            ls0 += __shfl_xor_sync(0xffffffffu, ls0, 2);
            ls1 += __shfl_xor_sync(0xffffffffu, ls1, 1);
            ls1 += __shfl_xor_sync(0xffffffffu, ls1, 2);
            l0 = l0 * c0 + ls0;
            l1 = l1 * c1 + ls1;

            // O += P V (P packed in registers)
#pragma unroll
            for (int jt = 0; jt < 4; jt++) {
                u32 pah[4], pal[4];
                bsplit2(sf[2 * jt][0],     sf[2 * jt][1],     pah[0], pal[0]);
                bsplit2(sf[2 * jt][2],     sf[2 * jt][3],     pah[1], pal[1]);
                bsplit2(sf[2 * jt + 1][0], sf[2 * jt + 1][1], pah[2], pal[2]);
                bsplit2(sf[2 * jt + 1][2], sf[2 * jt + 1][3], pah[3], pal[3]);
#pragma unroll
                for (int nt = 0; nt < 8; nt++) {
                    int bi = (nt * 8 + g) * ASTR + jt * 8 + q;
                    u32 vb0 = vsh[bi], vb1 = vsh[bi + 4];
                    u32 vl0 = vsl[bi], vl1 = vsl[bi + 4];
                    bmma(of[nt], pah, vb0, vb1);
                    bmma(of[nt], pal, vb0, vb1);
                    bmma(of[nt], pah, vl0, vl1);
                }
            }
        }
        __syncthreads();
    }

    // epilogue: normalize + split-write to aoh/aol (heads merged)
    float inv0 = 1.0f / l0, inv1 = 1.0f / l1;
    u32* oh = reinterpret_cast<u32*>(g_aoh);
    u32* ol = reinterpret_cast<u32*>(g_aol);
    size_t m0i = (size_t)(b * T_SEQ + R + g) * D_MODEL + h * 64;
    size_t m1i = m0i + (size_t)8 * D_MODEL;
#pragma unroll
    for (int nt = 0; nt < 8; nt++) {
        int col = nt * 8 + 2 * q;
        u32 h2, l2;
        bsplit2(of[nt][0] * inv0, of[nt][1] * inv0, h2, l2);
        oh[(m0i + col) >> 1] = h2; ol[(m0i + col) >> 1] = l2;
        bsplit2(of[nt][2] * inv1, of[nt][3] * inv1, h2, l2);
        oh[(m1i + col) >> 1] = h2; ol[(m1i + col) >> 1] = l2;
    }
}

// ---------------------------------------------------------------------------
extern "C" void kernel_launch(void* const* d_in, const int* in_sizes, int n_in,
                              void* d_out, int out_size)
{
    const float* q   = (const float*)d_in[0];
    const float* k   = (const float*)d_in[1];
    const float* v   = (const float*)d_in[2];
    const float* W_q = (const float*)d_in[4];
    const float* b_q = (const float*)d_in[5];
    const float* W_k = (const float*)d_in[6];
    const float* b_k = (const float*)d_in[7];
    const float* W_v = (const float*)d_in[8];
    const float* b_v = (const float*)d_in[9];
    const float* W_o = (const float*)d_in[10];
    const float* b_o = (const float*)d_in[11];
    float* out = (float*)d_out;

    struct Sym { void *iqh,*iql,*ikh,*ikl,*ivh,*ivl,*wqh,*wql,*wkh,*wkl,*wvh,*wvl,
                      *woh,*wol,*pqh,*pql,*pkh,*pkl,*V,*aoh,*aol; };
    static Sym s;
    cudaGetSymbolAddress(&s.iqh, g_iqh); cudaGetSymbolAddress(&s.iql, g_iql);
    cudaGetSymbolAddress(&s.ikh, g_ikh); cudaGetSymbolAddress(&s.ikl, g_ikl);
    cudaGetSymbolAddress(&s.ivh, g_ivh); cudaGetSymbolAddress(&s.ivl, g_ivl);
    cudaGetSymbolAddress(&s.wqh, g_wqh); cudaGetSymbolAddress(&s.wql, g_wql);
    cudaGetSymbolAddress(&s.wkh, g_wkh); cudaGetSymbolAddress(&s.wkl, g_wkl);
    cudaGetSymbolAddress(&s.wvh, g_wvh); cudaGetSymbolAddress(&s.wvl, g_wvl);
    cudaGetSymbolAddress(&s.woh, g_woh); cudaGetSymbolAddress(&s.wol, g_wol);
    cudaGetSymbolAddress(&s.pqh, g_pqh); cudaGetSymbolAddress(&s.pql, g_pql);
    cudaGetSymbolAddress(&s.pkh, g_pkh); cudaGetSymbolAddress(&s.pkl, g_pkl);
    cudaGetSymbolAddress(&s.V,   g_V);
    cudaGetSymbolAddress(&s.aoh, g_aoh); cudaGetSymbolAddress(&s.aol, g_aol);

    const int gemm_smem = 2 * 4 * GT * 4;                 // 81920 B
    const int attn_smem = ATTN_SMEM_W * 4;                // 73728 B
    cudaFuncSetAttribute(gemm_bf16<true>,  cudaFuncAttributeMaxDynamicSharedMemorySize, gemm_smem);
    cudaFuncSetAttribute(gemm_bf16<false>, cudaFuncAttributeMaxDynamicSharedMemorySize, gemm_smem);
    cudaFuncSetAttribute(attn_causal, cudaFuncAttributeMaxDynamicSharedMemorySize, attn_smem);

    // splits
    const int nin4 = M_ROWS * D_MODEL / 4, nw4 = D_MODEL * D_MODEL / 4;
    split_kernel<<<nin4 / 256, 256>>>((const float4*)q, (u32*)s.iqh, (u32*)s.iql, nin4);
    split_kernel<<<nin4 / 256, 256>>>((const float4*)k, (u32*)s.ikh, (u32*)s.ikl, nin4);
    split_kernel<<<nin4 / 256, 256>>>((const float4*)v, (u32*)s.ivh, (u32*)s.ivl, nin4);
    split_kernel<<<nw4 / 256, 256>>>((const float4*)W_q, (u32*)s.wqh, (u32*)s.wql, nw4);
    split_kernel<<<nw4 / 256, 256>>>((const float4*)W_k, (u32*)s.wkh, (u32*)s.wkl, nw4);
    split_kernel<<<nw4 / 256, 256>>>((const float4*)W_v, (u32*)s.wvh, (u32*)s.wvl, nw4);
    split_kernel<<<nw4 / 256, 256>>>((const float4*)W_o, (u32*)s.woh, (u32*)s.wol, nw4);

    dim3 gg(D_MODEL / 128, M_ROWS / 128);
    typedef const __nv_bfloat16* bp;
    gemm_bf16<true><<<gg, 256, gemm_smem>>>(
        (bp)s.iqh, (bp)s.iql, (bp)s.wqh, (bp)s.wql, b_q,
        nullptr, (u32*)s.pqh, (u32*)s.pql, M_ROWS, D_MODEL, D_MODEL);
    gemm_bf16<true><<<gg, 256, gemm_smem>>>(
        (bp)s.ikh, (bp)s.ikl, (bp)s.wkh, (bp)s.wkl, b_k,
        nullptr, (u32*)s.pkh, (u32*)s.pkl, M_ROWS, D_MODEL, D_MODEL);
    gemm_bf16<false><<<gg, 256, gemm_smem>>>(
        (bp)s.ivh, (bp)s.ivl, (bp)s.wvh, (bp)s.wvl, b_v,
        (float*)s.V, nullptr, nullptr, M_ROWS, D_MODEL, D_MODEL);

    dim3 tg(T_SEQ / 32, B_SZ * N_HEADS);
    vtrans_kernel<<<tg, 256>>>();

    dim3 ag(T_SEQ / 128, B_SZ * N_HEADS);
    attn_causal<<<ag, 256, attn_smem>>>();

    gemm_bf16<false><<<gg, 256, gemm_smem>>>(
        (bp)s.aoh, (bp)s.aol, (bp)s.woh, (bp)s.wol, b_o,
        out, nullptr, nullptr, M_ROWS, D_MODEL, D_MODEL);
}

// round 8
// speedup vs baseline: 1.8661x; 1.0970x over previous
#include <cuda_runtime.h>
#include <cuda_bf16.h>
#include <math.h>
#include <stdint.h>

#define D_MODEL 1024
#define N_HEADS 16
#define B_SZ    4
#define T_SEQ   2048
#define M_ROWS  8192

typedef unsigned int u32;

// bf16 hi/lo scratch (allocation-free rule: __device__ globals)
__device__ __nv_bfloat16 g_iqh[M_ROWS * D_MODEL], g_iql[M_ROWS * D_MODEL];
__device__ __nv_bfloat16 g_ikh[M_ROWS * D_MODEL], g_ikl[M_ROWS * D_MODEL];
__device__ __nv_bfloat16 g_ivh[M_ROWS * D_MODEL], g_ivl[M_ROWS * D_MODEL];
__device__ __nv_bfloat16 g_wqh[D_MODEL * D_MODEL], g_wql[D_MODEL * D_MODEL];
__device__ __nv_bfloat16 g_wkh[D_MODEL * D_MODEL], g_wkl[D_MODEL * D_MODEL];
__device__ __nv_bfloat16 g_wvh[D_MODEL * D_MODEL], g_wvl[D_MODEL * D_MODEL];
__device__ __nv_bfloat16 g_woh[D_MODEL * D_MODEL], g_wol[D_MODEL * D_MODEL];
__device__ __nv_bfloat16 g_pqh[M_ROWS * D_MODEL], g_pql[M_ROWS * D_MODEL];
__device__ __nv_bfloat16 g_pkh[M_ROWS * D_MODEL], g_pkl[M_ROWS * D_MODEL];
__device__ float         g_V  [M_ROWS * D_MODEL];
__device__ __nv_bfloat16 g_vth[M_ROWS * D_MODEL], g_vtl[M_ROWS * D_MODEL]; // [bh][64][2048]
__device__ __nv_bfloat16 g_aoh[M_ROWS * D_MODEL], g_aol[M_ROWS * D_MODEL];

// ---------------------------------------------------------------------------
// pack bf16x2 hi/lo split of (x0,x1): lower half = x0 (even index)
__device__ __forceinline__ void bsplit2(float x0, float x1, u32& hi, u32& lo) {
    u32 h;
    asm("cvt.rn.bf16x2.f32 %0, %1, %2;" : "=r"(h) : "f"(x1), "f"(x0));
    float h0 = __uint_as_float(h << 16);
    float h1 = __uint_as_float(h & 0xffff0000u);
    u32 l;
    float r0 = x0 - h0, r1 = x1 - h1;
    asm("cvt.rn.bf16x2.f32 %0, %1, %2;" : "=r"(l) : "f"(r1), "f"(r0));
    hi = h; lo = l;
}

__device__ __forceinline__ void bmma(float d[4], const u32 a[4], u32 b0, u32 b1) {
    asm volatile(
        "mma.sync.aligned.m16n8k16.row.col.f32.bf16.bf16.f32 "
        "{%0,%1,%2,%3}, {%4,%5,%6,%7}, {%8,%9}, {%0,%1,%2,%3};\n"
        : "+f"(d[0]), "+f"(d[1]), "+f"(d[2]), "+f"(d[3])
        : "r"(a[0]), "r"(a[1]), "r"(a[2]), "r"(a[3]), "r"(b0), "r"(b1));
}

__device__ __forceinline__ void ldsm4(u32& r0, u32& r1, u32& r2, u32& r3, u32 addr) {
    asm volatile("ldmatrix.sync.aligned.m8n8.x4.shared.b16 {%0,%1,%2,%3}, [%4];"
                 : "=r"(r0), "=r"(r1), "=r"(r2), "=r"(r3) : "r"(addr));
}

__device__ __forceinline__ void cpa16(void* smem_ptr, const void* gptr) {
    u32 s = (u32)__cvta_generic_to_shared(smem_ptr);
    asm volatile("cp.async.cg.shared.global [%0], [%1], 16;\n" :: "r"(s), "l"(gptr));
}
__device__ __forceinline__ void cpa_commit() { asm volatile("cp.async.commit_group;\n"); }
template <int N>
__device__ __forceinline__ void cpa_wait() { asm volatile("cp.async.wait_group %0;\n" :: "n"(N)); }

__device__ __forceinline__ u32 smem_u32(const void* p) {
    return (u32)__cvta_generic_to_shared(p);
}

// ---------------------------------------------------------------------------
__global__ void __launch_bounds__(256) split_kernel(
    const float4* __restrict__ src, u32* __restrict__ dh, u32* __restrict__ dl, int n4)
{
    int i = blockIdx.x * 256 + threadIdx.x;
    if (i >= n4) return;
    float4 v = src[i];
    u32 h0, l0, h1, l1;
    bsplit2(v.x, v.y, h0, l0);
    bsplit2(v.z, v.w, h1, l1);
    dh[2 * i] = h0; dh[2 * i + 1] = h1;
    dl[2 * i] = l0; dl[2 * i + 1] = l1;
}

// transpose + split V per head: g_V[b][t][h*64+d] -> vth/vtl[bh][d][t]
__global__ void __launch_bounds__(256) vtrans_kernel()
{
    __shared__ float ts[32][65];
    const int j0 = blockIdx.x * 32;
    const int bh = blockIdx.y;
    const int b = bh >> 4, h = bh & 15;
    const int tid = threadIdx.x;
#pragma unroll
    for (int i = 0; i < 8; i++) {
        int idx = tid + i * 256;
        int r = idx >> 6, c = idx & 63;
        ts[r][c] = g_V[(size_t)(b * T_SEQ + j0 + r) * D_MODEL + h * 64 + c];
    }
    __syncthreads();
    u32* oh = reinterpret_cast<u32*>(g_vth);
    u32* ol = reinterpret_cast<u32*>(g_vtl);
#pragma unroll
    for (int i = 0; i < 4; i++) {
        int idx = tid + i * 256;
        int d = idx >> 4, jj = (idx & 15) * 2;
        u32 h2, l2;
        bsplit2(ts[jj][d], ts[jj + 1][d], h2, l2);
        size_t o = ((size_t)(bh * 64 + d) * T_SEQ + j0 + jj) >> 1;
        oh[o] = h2; ol[o] = l2;
    }
}

// ---------------------------------------------------------------------------
// GEMM body: C[m][n] = sum_k A[m][k]*B[n][k] + bias[n], 3xBF16, ldmatrix frags,
// 3-stage cp.async pipeline. 128x128x32 tiles, 256 thr, warp tile 64x32.
// ---------------------------------------------------------------------------
#define GKW 20
#define GT  (128 * GKW)
#define GEMM_SMEM (3 * 4 * GT * 4)   // 122880 B

__device__ __forceinline__ void gemm_body(
    char* smb,
    const __nv_bfloat16* __restrict__ Ah, const __nv_bfloat16* __restrict__ Al,
    const __nv_bfloat16* __restrict__ Bh, const __nv_bfloat16* __restrict__ Bl,
    const float* __restrict__ bias,
    float* __restrict__ Cf, u32* __restrict__ Ch, u32* __restrict__ Cl,
    bool split_out)
{
    const u32 sb = smem_u32(smb);
    const int tid  = threadIdx.x;
    const int lane = tid & 31;
    const int wid  = tid >> 5;
    const int g    = lane >> 2;
    const int q    = lane & 3;
    const int wm   = wid >> 2;
    const int wn   = wid & 3;
    const int bm   = blockIdx.y * 128;
    const int bn   = blockIdx.x * 128;
    const int K = D_MODEL, N = D_MODEL;

    float acc[4][4][4] = {};

    u32* smw = reinterpret_cast<u32*>(smb);
    auto issue = [&](int t, int buf) {
        const int k0 = t * 32;
        u32* base = smw + buf * 4 * GT;
#pragma unroll
        for (int i = 0; i < 8; i++) {
            int idx = tid + i * 256;
            int arr = idx >> 9;
            int w   = idx & 511;
            int row = w >> 2, c = w & 3;
            const __nv_bfloat16* gp;
            int rb;
            if      (arr == 0) { gp = Ah; rb = bm; }
            else if (arr == 1) { gp = Al; rb = bm; }
            else if (arr == 2) { gp = Bh; rb = bn; }
            else               { gp = Bl; rb = bn; }
            cpa16(base + arr * GT + row * GKW + c * 4,
                  gp + (size_t)(rb + row) * K + k0 + c * 8);
        }
    };

    const int NT = K / 32;   // 32
    issue(0, 0); cpa_commit();
    issue(1, 1); cpa_commit();

    // ldmatrix lane offsets
    const int aRow = (lane & 7) + ((lane >> 3) & 1) * 8;
    const int aK4  = ((lane >> 4) & 1) * 4;
    const int bRow = (lane & 7) + ((lane >> 4) & 1) * 8;
    const int bK4  = ((lane >> 3) & 1) * 4;

    for (int s = 0; s < NT; s++) {
        const int buf = s % 3;
        if (s + 2 < NT)      { issue(s + 2, (s + 2) % 3); cpa_commit(); cpa_wait<2>(); }
        else if (s + 1 < NT) { cpa_wait<1>(); }
        else                 { cpa_wait<0>(); }
        __syncthreads();

        const u32 abh = sb + (u32)(buf * 4 * GT) * 4;
        const u32 abl = abh + GT * 4;
        const u32 bbh = abh + 2 * GT * 4;
        const u32 bbl = abh + 3 * GT * 4;

#pragma unroll
        for (int ks = 0; ks < 2; ks++) {
            u32 ah[4][4], al[4][4];
#pragma unroll
            for (int mt = 0; mt < 4; mt++) {
                u32 off = ((wm * 64 + mt * 16 + aRow) * GKW + ks * 8 + aK4) * 4;
                ldsm4(ah[mt][0], ah[mt][1], ah[mt][2], ah[mt][3], abh + off);
                ldsm4(al[mt][0], al[mt][1], al[mt][2], al[mt][3], abl + off);
            }
#pragma unroll
            for (int ntp = 0; ntp < 2; ntp++) {
                u32 bh0, bh1, bh2, bh3, bl0, bl1, bl2, bl3;
                u32 off = ((wn * 32 + ntp * 16 + bRow) * GKW + ks * 8 + bK4) * 4;
                ldsm4(bh0, bh1, bh2, bh3, bbh + off);
                ldsm4(bl0, bl1, bl2, bl3, bbl + off);
#pragma unroll
                for (int mt = 0; mt < 4; mt++) {
                    bmma(acc[mt][2 * ntp],     ah[mt], bh0, bh1);
                    bmma(acc[mt][2 * ntp],     al[mt], bh0, bh1);
                    bmma(acc[mt][2 * ntp],     ah[mt], bl0, bl1);
                    bmma(acc[mt][2 * ntp + 1], ah[mt], bh2, bh3);
                    bmma(acc[mt][2 * ntp + 1], al[mt], bh2, bh3);
                    bmma(acc[mt][2 * ntp + 1], ah[mt], bl2, bl3);
                }
            }
        }
        __syncthreads();
    }

#pragma unroll
    for (int mt = 0; mt < 4; mt++) {
        int row0 = bm + wm * 64 + mt * 16 + g;
#pragma unroll
        for (int nt = 0; nt < 4; nt++) {
            int col = bn + wn * 32 + nt * 8 + 2 * q;
            float b0 = bias[col], b1 = bias[col + 1];
            float v00 = acc[mt][nt][0] + b0, v01 = acc[mt][nt][1] + b1;
            float v10 = acc[mt][nt][2] + b0, v11 = acc[mt][nt][3] + b1;
            if (split_out) {
                u32 h2, l2;
                size_t o0 = ((size_t)row0 * N + col) >> 1;
                size_t o1 = ((size_t)(row0 + 8) * N + col) >> 1;
                bsplit2(v00, v01, h2, l2); Ch[o0] = h2; Cl[o0] = l2;
                bsplit2(v10, v11, h2, l2); Ch[o1] = h2; Cl[o1] = l2;
            } else {
                *(float2*)&Cf[(size_t)row0 * N + col]       = make_float2(v00, v01);
                *(float2*)&Cf[(size_t)(row0 + 8) * N + col] = make_float2(v10, v11);
            }
        }
    }
}

// fused Q/K/V projection: grid.z picks the matmul
__global__ void __launch_bounds__(256) gemm_qkv(
    const float* __restrict__ b_q, const float* __restrict__ b_k,
    const float* __restrict__ b_v)
{
    extern __shared__ char smb[];
    const int z = blockIdx.z;
    if (z == 0)
        gemm_body(smb, g_iqh, g_iql, g_wqh, g_wql, b_q,
                  nullptr, (u32*)g_pqh, (u32*)g_pql, true);
    else if (z == 1)
        gemm_body(smb, g_ikh, g_ikl, g_wkh, g_wkl, b_k,
                  nullptr, (u32*)g_pkh, (u32*)g_pkl, true);
    else
        gemm_body(smb, g_ivh, g_ivl, g_wvh, g_wvl, b_v,
                  g_V, nullptr, nullptr, false);
}

__global__ void __launch_bounds__(256) gemm_o(
    const float* __restrict__ b_o, float* __restrict__ out)
{
    extern __shared__ char smb[];
    gemm_body(smb, g_aoh, g_aol, g_woh, g_wol, b_o, out, nullptr, nullptr, false);
}

// ---------------------------------------------------------------------------
// Causal flash attention, 3xBF16, pre-split Q/K/Vt, P in registers, ldmatrix.
// Grid (T/128, B*H), 256 thr = 8 warps x 16 q-rows.
// ---------------------------------------------------------------------------
#define ASTR 36
#define ATILE (64 * ASTR)
#define KH_OFF(b) ((b) * ATILE)
#define KL_OFF(b) (2 * ATILE + (b) * ATILE)
#define VH_OFF(b) (4 * ATILE + (b) * ATILE)
#define VL_OFF(b) (6 * ATILE + (b) * ATILE)
#define ATTN_SMEM_W (8 * ATILE)

__global__ void __launch_bounds__(256) attn_causal()
{
    extern __shared__ u32 smw[];
    const u32 sb = smem_u32(smw);

    const int qb = gridDim.x - 1 - blockIdx.x;
    const int bh = blockIdx.y;
    const int b  = bh >> 4;
    const int h  = bh & 15;

    const int tid  = threadIdx.x;
    const int lane = tid & 31;
    const int wq   = tid >> 5;
    const int g    = lane >> 2;
    const int q    = lane & 3;

    const float scale = 0.125f;
    const u32* kh_g = reinterpret_cast<const u32*>(g_pkh);
    const u32* kl_g = reinterpret_cast<const u32*>(g_pkl);
    const u32* vh_g = reinterpret_cast<const u32*>(g_vth);
    const u32* vl_g = reinterpret_cast<const u32*>(g_vtl);

    const int aRow = (lane & 7) + ((lane >> 3) & 1) * 8;
    const int aK4  = ((lane >> 4) & 1) * 4;
    const int bRow = (lane & 7) + ((lane >> 4) & 1) * 8;
    const int bK4  = ((lane >> 3) & 1) * 4;

    // ---- stage Q (128 rows x 32 words, hi+lo), load fragments via ldsm ----
    {
        const u32* qh_g = reinterpret_cast<const u32*>(g_pqh);
        const u32* ql_g = reinterpret_cast<const u32*>(g_pql);
#pragma unroll
        for (int i = 0; i < 8; i++) {
            int idx = tid + i * 256;
            int arr = idx >> 10;
            int w   = idx & 1023;
            int row = w >> 3, c = w & 7;
            const u32* gp = arr ? ql_g : qh_g;
            cpa16(smw + arr * (128 * ASTR) + row * ASTR + c * 4,
                  gp + (((size_t)(b * T_SEQ + qb * 128 + row) * D_MODEL + h * 64) >> 1) + c * 4);
        }
        cpa_commit();
        cpa_wait<0>();
        __syncthreads();
    }
    u32 qh[4][4], ql[4][4];
#pragma unroll
    for (int kt = 0; kt < 4; kt++) {
        u32 off = ((wq * 16 + aRow) * ASTR + kt * 8 + aK4) * 4;
        ldsm4(qh[kt][0], qh[kt][1], qh[kt][2], qh[kt][3], sb + off);
        ldsm4(ql[kt][0], ql[kt][1], ql[kt][2], ql[kt][3], sb + (u32)(128 * ASTR) * 4 + off);
    }
    __syncthreads();   // Q region reused by K/V staging

    auto stage_kv = [&](int kb, int buf) {
#pragma unroll
        for (int i = 0; i < 4; i++) {
            int idx = tid + i * 256;
            int arr = idx >> 9;
            int w   = idx & 511;
            int row = w >> 3, c = w & 7;
            const u32* gp = arr ? kl_g : kh_g;
            cpa16(smw + (arr ? KL_OFF(buf) : KH_OFF(buf)) + row * ASTR + c * 4,
                  gp + (((size_t)(b * T_SEQ + kb * 64 + row) * D_MODEL + h * 64) >> 1) + c * 4);
        }
#pragma unroll
        for (int i = 0; i < 4; i++) {
            int idx = tid + i * 256;
            int arr = idx >> 9;
            int w   = idx & 511;
            int row = w >> 3, c = w & 7;
            const u32* gp = arr ? vl_g : vh_g;
            cpa16(smw + (arr ? VL_OFF(buf) : VH_OFF(buf)) + row * ASTR + c * 4,
                  gp + (((size_t)(bh * 64 + row) * T_SEQ + kb * 64) >> 1) + c * 4);
        }
    };

    stage_kv(0, 0);
    cpa_commit();

    float of[8][4] = {};
    float m0 = -INFINITY, m1 = -INFINITY, l0 = 0.f, l1 = 0.f;
    const int R = qb * 128 + wq * 16;
    const int kbmax = 2 * qb + 1;

    for (int kb = 0; kb <= kbmax; kb++) {
        if (kb + 1 <= kbmax) {
            stage_kv(kb + 1, (kb + 1) & 1);
            cpa_commit();
            cpa_wait<1>();
        } else {
            cpa_wait<0>();
        }
        __syncthreads();

        const bool active = (kb * 64 <= R + 15);
        if (active) {
            const u32 kshb = sb + (u32)KH_OFF(kb & 1) * 4;
            const u32 kslb = sb + (u32)KL_OFF(kb & 1) * 4;
            const u32 vshb = sb + (u32)VH_OFF(kb & 1) * 4;
            const u32 vslb = sb + (u32)VL_OFF(kb & 1) * 4;

            // S = Q K^T
            float sf[8][4] = {};
#pragma unroll
            for (int kt = 0; kt < 4; kt++) {
#pragma unroll
                for (int ntp = 0; ntp < 4; ntp++) {
                    u32 h0, h1, h2, h3, l0r, l1r, l2r, l3r;
                    u32 off = ((ntp * 16 + bRow) * ASTR + kt * 8 + bK4) * 4;
                    ldsm4(h0, h1, h2, h3, kshb + off);
                    ldsm4(l0r, l1r, l2r, l3r, kslb + off);
                    bmma(sf[2 * ntp],     qh[kt], h0, h1);
                    bmma(sf[2 * ntp],     ql[kt], h0, h1);
                    bmma(sf[2 * ntp],     qh[kt], l0r, l1r);
                    bmma(sf[2 * ntp + 1], qh[kt], h2, h3);
                    bmma(sf[2 * ntp + 1], ql[kt], h2, h3);
                    bmma(sf[2 * ntp + 1], qh[kt], l2r, l3r);
                }
            }

            if (kb * 64 + 63 > R) {
                int r0 = R + g, r1 = r0 + 8;
#pragma unroll
                for (int nt = 0; nt < 8; nt++) {
                    int c0 = kb * 64 + nt * 8 + 2 * q, c1 = c0 + 1;
                    if (c0 > r0) sf[nt][0] = -INFINITY;
                    if (c1 > r0) sf[nt][1] = -INFINITY;
                    if (c0 > r1) sf[nt][2] = -INFINITY;
                    if (c1 > r1) sf[nt][3] = -INFINITY;
                }
            }
#pragma unroll
            for (int nt = 0; nt < 8; nt++) {
                sf[nt][0] *= scale; sf[nt][1] *= scale;
                sf[nt][2] *= scale; sf[nt][3] *= scale;
            }

            float mx0 = -INFINITY, mx1 = -INFINITY;
#pragma unroll
            for (int nt = 0; nt < 8; nt++) {
                mx0 = fmaxf(mx0, fmaxf(sf[nt][0], sf[nt][1]));
                mx1 = fmaxf(mx1, fmaxf(sf[nt][2], sf[nt][3]));
            }
            mx0 = fmaxf(mx0, __shfl_xor_sync(0xffffffffu, mx0, 1));
            mx0 = fmaxf(mx0, __shfl_xor_sync(0xffffffffu, mx0, 2));
            mx1 = fmaxf(mx1, __shfl_xor_sync(0xffffffffu, mx1, 1));
            mx1 = fmaxf(mx1, __shfl_xor_sync(0xffffffffu, mx1, 2));

            float mn0 = fmaxf(m0, mx0), mn1 = fmaxf(m1, mx1);
            float c0 = __expf(m0 - mn0), c1 = __expf(m1 - mn1);
            m0 = mn0; m1 = mn1;

            float ls0 = 0.f, ls1 = 0.f;
#pragma unroll
            for (int nt = 0; nt < 8; nt++) {
                sf[nt][0] = __expf(sf[nt][0] - mn0);
                sf[nt][1] = __expf(sf[nt][1] - mn0);
                sf[nt][2] = __expf(sf[nt][2] - mn1);
                sf[nt][3] = __expf(sf[nt][3] - mn1);
                ls0 += sf[nt][0] + sf[nt][1];
                ls1 += sf[nt][2] + sf[nt][3];
                of[nt][0] *= c0; of[nt][1] *= c0;
                of[nt][2] *= c1; of[nt][3] *= c1;
            }
            ls0 += __shfl_xor_sync(0xffffffffu, ls0, 1);
            ls0 += __shfl_xor_sync(0xffffffffu, ls0, 2);
            ls1 += __shfl_xor_sync(0xffffffffu, ls1, 1);
            ls1 += __shfl_xor_sync(0xffffffffu, ls1, 2);
            l0 = l0 * c0 + ls0;
            l1 = l1 * c1 + ls1;

            // O += P V (P packed in registers)
#pragma unroll
            for (int jt = 0; jt < 4; jt++) {
                u32 pah[4], pal[4];
                bsplit2(sf[2 * jt][0],     sf[2 * jt][1],     pah[0], pal[0]);
                bsplit2(sf[2 * jt][2],     sf[2 * jt][3],     pah[1], pal[1]);
                bsplit2(sf[2 * jt + 1][0], sf[2 * jt + 1][1], pah[2], pal[2]);
                bsplit2(sf[2 * jt + 1][2], sf[2 * jt + 1][3], pah[3], pal[3]);
#pragma unroll
                for (int ntp = 0; ntp < 4; ntp++) {
                    u32 h0, h1, h2, h3, l0r, l1r, l2r, l3r;
                    u32 off = ((ntp * 16 + bRow) * ASTR + jt * 8 + bK4) * 4;
                    ldsm4(h0, h1, h2, h3, vshb + off);
                    ldsm4(l0r, l1r, l2r, l3r, vslb + off);
                    bmma(of[2 * ntp],     pah, h0, h1);
                    bmma(of[2 * ntp],     pal, h0, h1);
                    bmma(of[2 * ntp],     pah, l0r, l1r);
                    bmma(of[2 * ntp + 1], pah, h2, h3);
                    bmma(of[2 * ntp + 1], pal, h2, h3);
                    bmma(of[2 * ntp + 1], pah, l2r, l3r);
                }
            }
        }
        __syncthreads();
    }

    float inv0 = 1.0f / l0, inv1 = 1.0f / l1;
    u32* oh = reinterpret_cast<u32*>(g_aoh);
    u32* ol = reinterpret_cast<u32*>(g_aol);
    size_t m0i = (size_t)(b * T_SEQ + R + g) * D_MODEL + h * 64;
    size_t m1i = m0i + (size_t)8 * D_MODEL;
#pragma unroll
    for (int nt = 0; nt < 8; nt++) {
        int col = nt * 8 + 2 * q;
        u32 h2, l2;
        bsplit2(of[nt][0] * inv0, of[nt][1] * inv0, h2, l2);
        oh[(m0i + col) >> 1] = h2; ol[(m0i + col) >> 1] = l2;
        bsplit2(of[nt][2] * inv1, of[nt][3] * inv1, h2, l2);
        oh[(m1i + col) >> 1] = h2; ol[(m1i + col) >> 1] = l2;
    }
}

// ---------------------------------------------------------------------------
extern "C" void kernel_launch(void* const* d_in, const int* in_sizes, int n_in,
                              void* d_out, int out_size)
{
    const float* q   = (const float*)d_in[0];
    const float* k   = (const float*)d_in[1];
    const float* v   = (const float*)d_in[2];
    const float* W_q = (const float*)d_in[4];
    const float* b_q = (const float*)d_in[5];
    const float* W_k = (const float*)d_in[6];
    const float* b_k = (const float*)d_in[7];
    const float* W_v = (const float*)d_in[8];
    const float* b_v = (const float*)d_in[9];
    const float* W_o = (const float*)d_in[10];
    const float* b_o = (const float*)d_in[11];
    float* out = (float*)d_out;

    struct Sym { void *iqh,*iql,*ikh,*ikl,*ivh,*ivl,*wqh,*wql,*wkh,*wkl,*wvh,*wvl,
                      *woh,*wol; };
    static Sym s;
    cudaGetSymbolAddress(&s.iqh, g_iqh); cudaGetSymbolAddress(&s.iql, g_iql);
    cudaGetSymbolAddress(&s.ikh, g_ikh); cudaGetSymbolAddress(&s.ikl, g_ikl);
    cudaGetSymbolAddress(&s.ivh, g_ivh); cudaGetSymbolAddress(&s.ivl, g_ivl);
    cudaGetSymbolAddress(&s.wqh, g_wqh); cudaGetSymbolAddress(&s.wql, g_wql);
    cudaGetSymbolAddress(&s.wkh, g_wkh); cudaGetSymbolAddress(&s.wkl, g_wkl);
    cudaGetSymbolAddress(&s.wvh, g_wvh); cudaGetSymbolAddress(&s.wvl, g_wvl);
    cudaGetSymbolAddress(&s.woh, g_woh); cudaGetSymbolAddress(&s.wol, g_wol);

    const int attn_smem = ATTN_SMEM_W * 4;
    cudaFuncSetAttribute(gemm_qkv, cudaFuncAttributeMaxDynamicSharedMemorySize, GEMM_SMEM);
    cudaFuncSetAttribute(gemm_o,   cudaFuncAttributeMaxDynamicSharedMemorySize, GEMM_SMEM);
    cudaFuncSetAttribute(attn_causal, cudaFuncAttributeMaxDynamicSharedMemorySize, attn_smem);

    const int nin4 = M_ROWS * D_MODEL / 4, nw4 = D_MODEL * D_MODEL / 4;
    split_kernel<<<nin4 / 256, 256>>>((const float4*)q, (u32*)s.iqh, (u32*)s.iql, nin4);
    split_kernel<<<nin4 / 256, 256>>>((const float4*)k, (u32*)s.ikh, (u32*)s.ikl, nin4);
    split_kernel<<<nin4 / 256, 256>>>((const float4*)v, (u32*)s.ivh, (u32*)s.ivl, nin4);
    split_kernel<<<nw4 / 256, 256>>>((const float4*)W_q, (u32*)s.wqh, (u32*)s.wql, nw4);
    split_kernel<<<nw4 / 256, 256>>>((const float4*)W_k, (u32*)s.wkh, (u32*)s.wkl, nw4);
    split_kernel<<<nw4 / 256, 256>>>((const float4*)W_v, (u32*)s.wvh, (u32*)s.wvl, nw4);
    split_kernel<<<nw4 / 256, 256>>>((const float4*)W_o, (u32*)s.woh, (u32*)s.wol, nw4);

    dim3 gg(D_MODEL / 128, M_ROWS / 128, 3);   // (8, 64, 3)
    gemm_qkv<<<gg, 256, GEMM_SMEM>>>(b_q, b_k, b_v);

    dim3 tg(T_SEQ / 32, B_SZ * N_HEADS);
    vtrans_kernel<<<tg, 256>>>();

    dim3 ag(T_SEQ / 128, B_SZ * N_HEADS);
    attn_causal<<<ag, 256, attn_smem>>>();

    dim3 go(D_MODEL / 128, M_ROWS / 128);
    gemm_o<<<go, 256, GEMM_SMEM>>>(b_o, out);
}

// round 9
// speedup vs baseline: 1.9078x; 1.0224x over previous
#include <cuda_runtime.h>
#include <cuda_bf16.h>
#include <math.h>
#include <stdint.h>

#define D_MODEL 1024
#define N_HEADS 16
#define B_SZ    4
#define T_SEQ   2048
#define M_ROWS  8192

typedef unsigned int u32;

// bf16 hi/lo scratch (allocation-free rule: __device__ globals)
__device__ __nv_bfloat16 g_iqh[M_ROWS * D_MODEL], g_iql[M_ROWS * D_MODEL];
__device__ __nv_bfloat16 g_ikh[M_ROWS * D_MODEL], g_ikl[M_ROWS * D_MODEL];
__device__ __nv_bfloat16 g_ivh[M_ROWS * D_MODEL], g_ivl[M_ROWS * D_MODEL];
__device__ __nv_bfloat16 g_wqh[D_MODEL * D_MODEL], g_wql[D_MODEL * D_MODEL];
__device__ __nv_bfloat16 g_wkh[D_MODEL * D_MODEL], g_wkl[D_MODEL * D_MODEL];
__device__ __nv_bfloat16 g_wvh[D_MODEL * D_MODEL], g_wvl[D_MODEL * D_MODEL];
__device__ __nv_bfloat16 g_woh[D_MODEL * D_MODEL], g_wol[D_MODEL * D_MODEL];
__device__ __nv_bfloat16 g_pqh[M_ROWS * D_MODEL], g_pql[M_ROWS * D_MODEL];
__device__ __nv_bfloat16 g_pkh[M_ROWS * D_MODEL], g_pkl[M_ROWS * D_MODEL];
__device__ float         g_V  [M_ROWS * D_MODEL];
__device__ __nv_bfloat16 g_vth[M_ROWS * D_MODEL], g_vtl[M_ROWS * D_MODEL]; // [bh][64][2048]
__device__ __nv_bfloat16 g_aoh[M_ROWS * D_MODEL], g_aol[M_ROWS * D_MODEL];

// ---------------------------------------------------------------------------
// pack bf16x2 hi/lo split of (x0,x1): lower half = x0 (even index)
__device__ __forceinline__ void bsplit2(float x0, float x1, u32& hi, u32& lo) {
    u32 h;
    asm("cvt.rn.bf16x2.f32 %0, %1, %2;" : "=r"(h) : "f"(x1), "f"(x0));
    float h0 = __uint_as_float(h << 16);
    float h1 = __uint_as_float(h & 0xffff0000u);
    u32 l;
    float r0 = x0 - h0, r1 = x1 - h1;
    asm("cvt.rn.bf16x2.f32 %0, %1, %2;" : "=r"(l) : "f"(r1), "f"(r0));
    hi = h; lo = l;
}

__device__ __forceinline__ void bmma(float d[4], const u32 a[4], u32 b0, u32 b1) {
    asm volatile(
        "mma.sync.aligned.m16n8k16.row.col.f32.bf16.bf16.f32 "
        "{%0,%1,%2,%3}, {%4,%5,%6,%7}, {%8,%9}, {%0,%1,%2,%3};\n"
        : "+f"(d[0]), "+f"(d[1]), "+f"(d[2]), "+f"(d[3])
        : "r"(a[0]), "r"(a[1]), "r"(a[2]), "r"(a[3]), "r"(b0), "r"(b1));
}

__device__ __forceinline__ void ldsm4(u32& r0, u32& r1, u32& r2, u32& r3, u32 addr) {
    asm volatile("ldmatrix.sync.aligned.m8n8.x4.shared.b16 {%0,%1,%2,%3}, [%4];"
                 : "=r"(r0), "=r"(r1), "=r"(r2), "=r"(r3) : "r"(addr));
}

__device__ __forceinline__ void cpa16(void* smem_ptr, const void* gptr) {
    u32 s = (u32)__cvta_generic_to_shared(smem_ptr);
    asm volatile("cp.async.cg.shared.global [%0], [%1], 16;\n" :: "r"(s), "l"(gptr));
}
__device__ __forceinline__ void cpa_commit() { asm volatile("cp.async.commit_group;\n"); }
template <int N>
__device__ __forceinline__ void cpa_wait() { asm volatile("cp.async.wait_group %0;\n" :: "n"(N)); }

__device__ __forceinline__ u32 smem_u32(const void* p) {
    return (u32)__cvta_generic_to_shared(p);
}

// ---------------------------------------------------------------------------
// fused split: grid (8192, 7); dsts are device globals
__global__ void __launch_bounds__(256) split7_kernel(
    const float4* __restrict__ q, const float4* __restrict__ k,
    const float4* __restrict__ v,
    const float4* __restrict__ wq, const float4* __restrict__ wk,
    const float4* __restrict__ wv, const float4* __restrict__ wo)
{
    const int seg = blockIdx.y;
    const int i = blockIdx.x * 256 + threadIdx.x;
    const float4* src; u32* dh; u32* dl; int n4;
    const int NI = M_ROWS * D_MODEL / 4, NW = D_MODEL * D_MODEL / 4;
    switch (seg) {
        case 0: src = q;  dh = (u32*)g_iqh; dl = (u32*)g_iql; n4 = NI; break;
        case 1: src = k;  dh = (u32*)g_ikh; dl = (u32*)g_ikl; n4 = NI; break;
        case 2: src = v;  dh = (u32*)g_ivh; dl = (u32*)g_ivl; n4 = NI; break;
        case 3: src = wq; dh = (u32*)g_wqh; dl = (u32*)g_wql; n4 = NW; break;
        case 4: src = wk; dh = (u32*)g_wkh; dl = (u32*)g_wkl; n4 = NW; break;
        case 5: src = wv; dh = (u32*)g_wvh; dl = (u32*)g_wvl; n4 = NW; break;
        default: src = wo; dh = (u32*)g_woh; dl = (u32*)g_wol; n4 = NW; break;
    }
    if (i >= n4) return;
    float4 val = src[i];
    u32 h0, l0, h1, l1;
    bsplit2(val.x, val.y, h0, l0);
    bsplit2(val.z, val.w, h1, l1);
    dh[2 * i] = h0; dh[2 * i + 1] = h1;
    dl[2 * i] = l0; dl[2 * i + 1] = l1;
}

// transpose + split V per head: g_V[b][t][h*64+d] -> vth/vtl[bh][d][t]
__global__ void __launch_bounds__(256) vtrans_kernel()
{
    __shared__ float ts[32][65];
    const int j0 = blockIdx.x * 32;
    const int bh = blockIdx.y;
    const int b = bh >> 4, h = bh & 15;
    const int tid = threadIdx.x;
#pragma unroll
    for (int i = 0; i < 8; i++) {
        int idx = tid + i * 256;
        int r = idx >> 6, c = idx & 63;
        ts[r][c] = g_V[(size_t)(b * T_SEQ + j0 + r) * D_MODEL + h * 64 + c];
    }
    __syncthreads();
    u32* oh = reinterpret_cast<u32*>(g_vth);
    u32* ol = reinterpret_cast<u32*>(g_vtl);
#pragma unroll
    for (int i = 0; i < 4; i++) {
        int idx = tid + i * 256;
        int d = idx >> 4, jj = (idx & 15) * 2;
        u32 h2, l2;
        bsplit2(ts[jj][d], ts[jj + 1][d], h2, l2);
        size_t o = ((size_t)(bh * 64 + d) * T_SEQ + j0 + jj) >> 1;
        oh[o] = h2; ol[o] = l2;
    }
}

// ---------------------------------------------------------------------------
// GEMM body: 3xBF16, ldmatrix, 3-stage pipeline, ONE sync per iteration.
// ---------------------------------------------------------------------------
#define GKW 20
#define GT  (128 * GKW)
#define GEMM_SMEM (3 * 4 * GT * 4)   // 122880 B

__device__ __forceinline__ void gemm_body(
    char* smb,
    const __nv_bfloat16* __restrict__ Ah, const __nv_bfloat16* __restrict__ Al,
    const __nv_bfloat16* __restrict__ Bh, const __nv_bfloat16* __restrict__ Bl,
    const float* __restrict__ bias,
    float* __restrict__ Cf, u32* __restrict__ Ch, u32* __restrict__ Cl,
    bool split_out)
{
    const u32 sb = smem_u32(smb);
    const int tid  = threadIdx.x;
    const int lane = tid & 31;
    const int wid  = tid >> 5;
    const int g    = lane >> 2;
    const int q    = lane & 3;
    const int wm   = wid >> 2;
    const int wn   = wid & 3;
    const int bm   = blockIdx.y * 128;
    const int bn   = blockIdx.x * 128;
    const int K = D_MODEL, N = D_MODEL;

    float acc[4][4][4] = {};

    u32* smw = reinterpret_cast<u32*>(smb);
    auto issue = [&](int t, int buf) {
        const int k0 = t * 32;
        u32* base = smw + buf * 4 * GT;
#pragma unroll
        for (int i = 0; i < 8; i++) {
            int idx = tid + i * 256;
            int arr = idx >> 9;
            int w   = idx & 511;
            int row = w >> 2, c = w & 3;
            const __nv_bfloat16* gp;
            int rb;
            if      (arr == 0) { gp = Ah; rb = bm; }
            else if (arr == 1) { gp = Al; rb = bm; }
            else if (arr == 2) { gp = Bh; rb = bn; }
            else               { gp = Bl; rb = bn; }
            cpa16(base + arr * GT + row * GKW + c * 4,
                  gp + (size_t)(rb + row) * K + k0 + c * 8);
        }
    };

    const int NT = K / 32;   // 32
    issue(0, 0); cpa_commit();
    issue(1, 1); cpa_commit();

    const int aRow = (lane & 7) + ((lane >> 3) & 1) * 8;
    const int aK4  = ((lane >> 4) & 1) * 4;
    const int bRow = (lane & 7) + ((lane >> 4) & 1) * 8;
    const int bK4  = ((lane >> 3) & 1) * 4;

    for (int s = 0; s < NT; s++) {
        const int buf = s % 3;
        if (s + 1 < NT) cpa_wait<1>(); else cpa_wait<0>();
        __syncthreads();
        if (s + 2 < NT) { issue(s + 2, (s + 2) % 3); cpa_commit(); }

        const u32 abh = sb + (u32)(buf * 4 * GT) * 4;
        const u32 abl = abh + GT * 4;
        const u32 bbh = abh + 2 * GT * 4;
        const u32 bbl = abh + 3 * GT * 4;

#pragma unroll
        for (int ks = 0; ks < 2; ks++) {
            u32 ah[4][4], al[4][4];
#pragma unroll
            for (int mt = 0; mt < 4; mt++) {
                u32 off = ((wm * 64 + mt * 16 + aRow) * GKW + ks * 8 + aK4) * 4;
                ldsm4(ah[mt][0], ah[mt][1], ah[mt][2], ah[mt][3], abh + off);
                ldsm4(al[mt][0], al[mt][1], al[mt][2], al[mt][3], abl + off);
            }
#pragma unroll
            for (int ntp = 0; ntp < 2; ntp++) {
                u32 bh0, bh1, bh2, bh3, bl0, bl1, bl2, bl3;
                u32 off = ((wn * 32 + ntp * 16 + bRow) * GKW + ks * 8 + bK4) * 4;
                ldsm4(bh0, bh1, bh2, bh3, bbh + off);
                ldsm4(bl0, bl1, bl2, bl3, bbl + off);
#pragma unroll
                for (int mt = 0; mt < 4; mt++) {
                    bmma(acc[mt][2 * ntp],     ah[mt], bh0, bh1);
                    bmma(acc[mt][2 * ntp],     al[mt], bh0, bh1);
                    bmma(acc[mt][2 * ntp],     ah[mt], bl0, bl1);
                    bmma(acc[mt][2 * ntp + 1], ah[mt], bh2, bh3);
                    bmma(acc[mt][2 * ntp + 1], al[mt], bh2, bh3);
                    bmma(acc[mt][2 * ntp + 1], ah[mt], bl2, bl3);
                }
            }
        }
    }

#pragma unroll
    for (int mt = 0; mt < 4; mt++) {
        int row0 = bm + wm * 64 + mt * 16 + g;
#pragma unroll
        for (int nt = 0; nt < 4; nt++) {
            int col = bn + wn * 32 + nt * 8 + 2 * q;
            float b0 = bias[col], b1 = bias[col + 1];
            float v00 = acc[mt][nt][0] + b0, v01 = acc[mt][nt][1] + b1;
            float v10 = acc[mt][nt][2] + b0, v11 = acc[mt][nt][3] + b1;
            if (split_out) {
                u32 h2, l2;
                size_t o0 = ((size_t)row0 * N + col) >> 1;
                size_t o1 = ((size_t)(row0 + 8) * N + col) >> 1;
                bsplit2(v00, v01, h2, l2); Ch[o0] = h2; Cl[o0] = l2;
                bsplit2(v10, v11, h2, l2); Ch[o1] = h2; Cl[o1] = l2;
            } else {
                *(float2*)&Cf[(size_t)row0 * N + col]       = make_float2(v00, v01);
                *(float2*)&Cf[(size_t)(row0 + 8) * N + col] = make_float2(v10, v11);
            }
        }
    }
}

__global__ void __launch_bounds__(256) gemm_qkv(
    const float* __restrict__ b_q, const float* __restrict__ b_k,
    const float* __restrict__ b_v)
{
    extern __shared__ char smb[];
    const int z = blockIdx.z;
    if (z == 0)
        gemm_body(smb, g_iqh, g_iql, g_wqh, g_wql, b_q,
                  nullptr, (u32*)g_pqh, (u32*)g_pql, true);
    else if (z == 1)
        gemm_body(smb, g_ikh, g_ikl, g_wkh, g_wkl, b_k,
                  nullptr, (u32*)g_pkh, (u32*)g_pkl, true);
    else
        gemm_body(smb, g_ivh, g_ivl, g_wvh, g_wvl, b_v,
                  g_V, nullptr, nullptr, false);
}

__global__ void __launch_bounds__(256) gemm_o(
    const float* __restrict__ b_o, float* __restrict__ out)
{
    extern __shared__ char smb[];
    gemm_body(smb, g_aoh, g_aol, g_woh, g_wol, b_o, out, nullptr, nullptr, false);
}

// ---------------------------------------------------------------------------
// Causal flash attention, 3xBF16, 128-wide kv tiles, one sync per tile.
// Grid (T/128, B*H), 256 thr = 8 warps x 16 q-rows.
// ---------------------------------------------------------------------------
#define KSTR 36
#define VSTR 68
#define KT_W (128 * KSTR)   // 4608 words
#define VT_W (64 * VSTR)    // 4352 words
#define KH_OFF(b) ((b) * KT_W)
#define KL_OFF(b) (2 * KT_W + (b) * KT_W)
#define VH_OFF(b) (4 * KT_W + (b) * VT_W)
#define VL_OFF(b) (4 * KT_W + 2 * VT_W + (b) * VT_W)
#define ATTN_SMEM_W (4 * KT_W + 4 * VT_W)   // 35840 words = 143360 B

__global__ void __launch_bounds__(256) attn_causal()
{
    extern __shared__ u32 smw[];
    const u32 sb = smem_u32(smw);

    const int qb = gridDim.x - 1 - blockIdx.x;   // heavy blocks first
    const int bh = blockIdx.y;
    const int b  = bh >> 4;
    const int h  = bh & 15;

    const int tid  = threadIdx.x;
    const int lane = tid & 31;
    const int wq   = tid >> 5;
    const int g    = lane >> 2;
    const int q    = lane & 3;

    const float scale = 0.125f;
    const u32* kh_g = reinterpret_cast<const u32*>(g_pkh);
    const u32* kl_g = reinterpret_cast<const u32*>(g_pkl);
    const u32* vh_g = reinterpret_cast<const u32*>(g_vth);
    const u32* vl_g = reinterpret_cast<const u32*>(g_vtl);

    const int aRow = (lane & 7) + ((lane >> 3) & 1) * 8;
    const int aK4  = ((lane >> 4) & 1) * 4;
    const int bRow = (lane & 7) + ((lane >> 4) & 1) * 8;
    const int bK4  = ((lane >> 3) & 1) * 4;

    // ---- stage Q (reuses K region), load fragments ----
    {
        const u32* qh_g = reinterpret_cast<const u32*>(g_pqh);
        const u32* ql_g = reinterpret_cast<const u32*>(g_pql);
#pragma unroll
        for (int i = 0; i < 8; i++) {
            int idx = tid + i * 256;
            int arr = idx >> 10;
            int w   = idx & 1023;
            int row = w >> 3, c = w & 7;
            const u32* gp = arr ? ql_g : qh_g;
            cpa16(smw + arr * KT_W + row * KSTR + c * 4,
                  gp + (((size_t)(b * T_SEQ + qb * 128 + row) * D_MODEL + h * 64) >> 1) + c * 4);
        }
        cpa_commit();
        cpa_wait<0>();
        __syncthreads();
    }
    u32 qh[4][4], ql[4][4];
#pragma unroll
    for (int kt = 0; kt < 4; kt++) {
        u32 off = ((wq * 16 + aRow) * KSTR + kt * 8 + aK4) * 4;
        ldsm4(qh[kt][0], qh[kt][1], qh[kt][2], qh[kt][3], sb + off);
        ldsm4(ql[kt][0], ql[kt][1], ql[kt][2], ql[kt][3], sb + (u32)KT_W * 4 + off);
    }
    __syncthreads();   // Q region reused by K staging

    auto stage_kv = [&](int kb, int buf) {
        // K: 128 rows x 32 words, hi+lo
#pragma unroll
        for (int i = 0; i < 8; i++) {
            int idx = tid + i * 256;
            int arr = idx >> 10;
            int w   = idx & 1023;
            int row = w >> 3, c = w & 7;
            const u32* gp = arr ? kl_g : kh_g;
            cpa16(smw + (arr ? KL_OFF(buf) : KH_OFF(buf)) + row * KSTR + c * 4,
                  gp + (((size_t)(b * T_SEQ + kb * 128 + row) * D_MODEL + h * 64) >> 1) + c * 4);
        }
        // Vt: 64 d-rows x 64 words (128 t), hi+lo
#pragma unroll
        for (int i = 0; i < 8; i++) {
            int idx = tid + i * 256;
            int arr = idx >> 10;
            int w   = idx & 1023;
            int row = w >> 4, c = w & 15;
            const u32* gp = arr ? vl_g : vh_g;
            cpa16(smw + (arr ? VL_OFF(buf) : VH_OFF(buf)) + row * VSTR + c * 4,
                  gp + (size_t)(bh * 64 + row) * (T_SEQ / 2) + kb * 64 + c * 4);
        }
    };

    stage_kv(0, 0);
    cpa_commit();

    float of[8][4] = {};
    float m0 = -INFINITY, m1 = -INFINITY, l0 = 0.f, l1 = 0.f;
    const int R = qb * 128 + wq * 16;

    for (int kb = 0; kb <= qb; kb++) {
        cpa_wait<0>();
        __syncthreads();
        if (kb + 1 <= qb) { stage_kv(kb + 1, (kb + 1) & 1); cpa_commit(); }

        const bool active = (kb * 128 <= R + 15);
        if (active) {
            const u32 kshb = sb + (u32)KH_OFF(kb & 1) * 4;
            const u32 kslb = sb + (u32)KL_OFF(kb & 1) * 4;
            const u32 vshb = sb + (u32)VH_OFF(kb & 1) * 4;
            const u32 vslb = sb + (u32)VL_OFF(kb & 1) * 4;

            // S = Q K^T  (16 x 128 per warp)
            float sf[16][4] = {};
#pragma unroll
            for (int kt = 0; kt < 4; kt++) {
#pragma unroll
                for (int ntp = 0; ntp < 8; ntp++) {
                    u32 h0, h1, h2, h3, l0r, l1r, l2r, l3r;
                    u32 off = ((ntp * 16 + bRow) * KSTR + kt * 8 + bK4) * 4;
                    ldsm4(h0, h1, h2, h3, kshb + off);
                    ldsm4(l0r, l1r, l2r, l3r, kslb + off);
                    bmma(sf[2 * ntp],     qh[kt], h0, h1);
                    bmma(sf[2 * ntp],     ql[kt], h0, h1);
                    bmma(sf[2 * ntp],     qh[kt], l0r, l1r);
                    bmma(sf[2 * ntp + 1], qh[kt], h2, h3);
                    bmma(sf[2 * ntp + 1], ql[kt], h2, h3);
                    bmma(sf[2 * ntp + 1], qh[kt], l2r, l3r);
                }
            }

            // mask (diagonal 128-tile only) + scale
            if (kb * 128 + 127 > R) {
                int r0 = R + g, r1 = r0 + 8;
#pragma unroll
                for (int nt = 0; nt < 16; nt++) {
                    int c0 = kb * 128 + nt * 8 + 2 * q, c1 = c0 + 1;
                    if (c0 > r0) sf[nt][0] = -INFINITY;
                    if (c1 > r0) sf[nt][1] = -INFINITY;
                    if (c0 > r1) sf[nt][2] = -INFINITY;
                    if (c1 > r1) sf[nt][3] = -INFINITY;
                }
            }
#pragma unroll
            for (int nt = 0; nt < 16; nt++) {
                sf[nt][0] *= scale; sf[nt][1] *= scale;
                sf[nt][2] *= scale; sf[nt][3] *= scale;
            }

            // online softmax
            float mx0 = -INFINITY, mx1 = -INFINITY;
#pragma unroll
            for (int nt = 0; nt < 16; nt++) {
                mx0 = fmaxf(mx0, fmaxf(sf[nt][0], sf[nt][1]));
                mx1 = fmaxf(mx1, fmaxf(sf[nt][2], sf[nt][3]));
            }
            mx0 = fmaxf(mx0, __shfl_xor_sync(0xffffffffu, mx0, 1));
            mx0 = fmaxf(mx0, __shfl_xor_sync(0xffffffffu, mx0, 2));
            mx1 = fmaxf(mx1, __shfl_xor_sync(0xffffffffu, mx1, 1));
            mx1 = fmaxf(mx1, __shfl_xor_sync(0xffffffffu, mx1, 2));

            float mn0 = fmaxf(m0, mx0), mn1 = fmaxf(m1, mx1);
            float c0 = __expf(m0 - mn0), c1 = __expf(m1 - mn1);
            m0 = mn0; m1 = mn1;

            float ls0 = 0.f, ls1 = 0.f;
#pragma unroll
            for (int nt = 0; nt < 16; nt++) {
                sf[nt][0] = __expf(sf[nt][0] - mn0);
                sf[nt][1] = __expf(sf[nt][1] - mn0);
                sf[nt][2] = __expf(sf[nt][2] - mn1);
                sf[nt][3] = __expf(sf[nt][3] - mn1);
                ls0 += sf[nt][0] + sf[nt][1];
                ls1 += sf[nt][2] + sf[nt][3];
            }
#pragma unroll
            for (int nt = 0; nt < 8; nt++) {
                of[nt][0] *= c0; of[nt][1] *= c0;
                of[nt][2] *= c1; of[nt][3] *= c1;
            }
            ls0 += __shfl_xor_sync(0xffffffffu, ls0, 1);
            ls0 += __shfl_xor_sync(0xffffffffu, ls0, 2);
            ls1 += __shfl_xor_sync(0xffffffffu, ls1, 1);
            ls1 += __shfl_xor_sync(0xffffffffu, ls1, 2);
            l0 = l0 * c0 + ls0;
            l1 = l1 * c1 + ls1;

            // O += P V (P packed in registers; jt over 8 k-groups of 16 j)
#pragma unroll
            for (int jt = 0; jt < 8; jt++) {
                u32 pah[4], pal[4];
                bsplit2(sf[2 * jt][0],     sf[2 * jt][1],     pah[0], pal[0]);
                bsplit2(sf[2 * jt][2],     sf[2 * jt][3],     pah[1], pal[1]);
                bsplit2(sf[2 * jt + 1][0], sf[2 * jt + 1][1], pah[2], pal[2]);
                bsplit2(sf[2 * jt + 1][2], sf[2 * jt + 1][3], pah[3], pal[3]);
#pragma unroll
                for (int ntp = 0; ntp < 4; ntp++) {
                    u32 h0, h1, h2, h3, l0r, l1r, l2r, l3r;
                    u32 off = ((ntp * 16 + bRow) * VSTR + jt * 8 + bK4) * 4;
                    ldsm4(h0, h1, h2, h3, vshb + off);
                    ldsm4(l0r, l1r, l2r, l3r, vslb + off);
                    bmma(of[2 * ntp],     pah, h0, h1);
                    bmma(of[2 * ntp],     pal, h0, h1);
                    bmma(of[2 * ntp],     pah, l0r, l1r);
                    bmma(of[2 * ntp + 1], pah, h2, h3);
                    bmma(of[2 * ntp + 1], pal, h2, h3);
                    bmma(of[2 * ntp + 1], pah, l2r, l3r);
                }
            }
        }
    }

    // epilogue: normalize + split-write (heads merged)
    float inv0 = 1.0f / l0, inv1 = 1.0f / l1;
    u32* oh = reinterpret_cast<u32*>(g_aoh);
    u32* ol = reinterpret_cast<u32*>(g_aol);
    size_t m0i = (size_t)(b * T_SEQ + R + g) * D_MODEL + h * 64;
    size_t m1i = m0i + (size_t)8 * D_MODEL;
#pragma unroll
    for (int nt = 0; nt < 8; nt++) {
        int col = nt * 8 + 2 * q;
        u32 h2, l2;
        bsplit2(of[nt][0] * inv0, of[nt][1] * inv0, h2, l2);
        oh[(m0i + col) >> 1] = h2; ol[(m0i + col) >> 1] = l2;
        bsplit2(of[nt][2] * inv1, of[nt][3] * inv1, h2, l2);
        oh[(m1i + col) >> 1] = h2; ol[(m1i + col) >> 1] = l2;
    }
}

// ---------------------------------------------------------------------------
extern "C" void kernel_launch(void* const* d_in, const int* in_sizes, int n_in,
                              void* d_out, int out_size)
{
    const float* q   = (const float*)d_in[0];
    const float* k   = (const float*)d_in[1];
    const float* v   = (const float*)d_in[2];
    const float* W_q = (const float*)d_in[4];
    const float* b_q = (const float*)d_in[5];
    const float* W_k = (const float*)d_in[6];
    const float* b_k = (const float*)d_in[7];
    const float* W_v = (const float*)d_in[8];
    const float* b_v = (const float*)d_in[9];
    const float* W_o = (const float*)d_in[10];
    const float* b_o = (const float*)d_in[11];
    float* out = (float*)d_out;

    const int attn_smem = ATTN_SMEM_W * 4;   // 143360
    cudaFuncSetAttribute(gemm_qkv, cudaFuncAttributeMaxDynamicSharedMemorySize, GEMM_SMEM);
    cudaFuncSetAttribute(gemm_o,   cudaFuncAttributeMaxDynamicSharedMemorySize, GEMM_SMEM);
    cudaFuncSetAttribute(attn_causal, cudaFuncAttributeMaxDynamicSharedMemorySize, attn_smem);

    dim3 sg(M_ROWS * D_MODEL / 4 / 256, 7);   // (8192, 7)
    split7_kernel<<<sg, 256>>>((const float4*)q, (const float4*)k, (const float4*)v,
                               (const float4*)W_q, (const float4*)W_k,
                               (const float4*)W_v, (const float4*)W_o);

    dim3 gg(D_MODEL / 128, M_ROWS / 128, 3);   // (8, 64, 3)
    gemm_qkv<<<gg, 256, GEMM_SMEM>>>(b_q, b_k, b_v);

    dim3 tg(T_SEQ / 32, B_SZ * N_HEADS);
    vtrans_kernel<<<tg, 256>>>();

    dim3 ag(T_SEQ / 128, B_SZ * N_HEADS);      // (16, 64)
    attn_causal<<<ag, 256, attn_smem>>>();

    dim3 go(D_MODEL / 128, M_ROWS / 128);
    gemm_o<<<go, 256, GEMM_SMEM>>>(b_o, out);
}

// round 10
// speedup vs baseline: 2.1110x; 1.1065x over previous
#include <cuda_runtime.h>
#include <cuda_bf16.h>
#include <math.h>
#include <stdint.h>

#define D_MODEL 1024
#define N_HEADS 16
#define B_SZ    4
#define T_SEQ   2048
#define M_ROWS  8192

typedef unsigned int u32;

// bf16 hi/lo scratch (allocation-free rule: __device__ globals)
__device__ __nv_bfloat16 g_iqh[M_ROWS * D_MODEL], g_iql[M_ROWS * D_MODEL];
__device__ __nv_bfloat16 g_ikh[M_ROWS * D_MODEL], g_ikl[M_ROWS * D_MODEL];
__device__ __nv_bfloat16 g_ivh[M_ROWS * D_MODEL], g_ivl[M_ROWS * D_MODEL];
__device__ __nv_bfloat16 g_wqh[D_MODEL * D_MODEL], g_wql[D_MODEL * D_MODEL];
__device__ __nv_bfloat16 g_wkh[D_MODEL * D_MODEL], g_wkl[D_MODEL * D_MODEL];
__device__ __nv_bfloat16 g_wvh[D_MODEL * D_MODEL], g_wvl[D_MODEL * D_MODEL];
__device__ __nv_bfloat16 g_woh[D_MODEL * D_MODEL], g_wol[D_MODEL * D_MODEL];
__device__ __nv_bfloat16 g_pqh[M_ROWS * D_MODEL], g_pql[M_ROWS * D_MODEL];
__device__ __nv_bfloat16 g_pkh[M_ROWS * D_MODEL], g_pkl[M_ROWS * D_MODEL];
__device__ float         g_V  [M_ROWS * D_MODEL];
__device__ __nv_bfloat16 g_vth[M_ROWS * D_MODEL], g_vtl[M_ROWS * D_MODEL]; // [bh][64][2048]
__device__ __nv_bfloat16 g_aoh[M_ROWS * D_MODEL], g_aol[M_ROWS * D_MODEL];

// ---------------------------------------------------------------------------
// pack bf16x2 hi/lo split of (x0,x1): lower half = x0 (even index)
__device__ __forceinline__ void bsplit2(float x0, float x1, u32& hi, u32& lo) {
    u32 h;
    asm("cvt.rn.bf16x2.f32 %0, %1, %2;" : "=r"(h) : "f"(x1), "f"(x0));
    float h0 = __uint_as_float(h << 16);
    float h1 = __uint_as_float(h & 0xffff0000u);
    u32 l;
    float r0 = x0 - h0, r1 = x1 - h1;
    asm("cvt.rn.bf16x2.f32 %0, %1, %2;" : "=r"(l) : "f"(r1), "f"(r0));
    hi = h; lo = l;
}

__device__ __forceinline__ void bmma(float d[4], const u32 a[4], u32 b0, u32 b1) {
    asm volatile(
        "mma.sync.aligned.m16n8k16.row.col.f32.bf16.bf16.f32 "
        "{%0,%1,%2,%3}, {%4,%5,%6,%7}, {%8,%9}, {%0,%1,%2,%3};\n"
        : "+f"(d[0]), "+f"(d[1]), "+f"(d[2]), "+f"(d[3])
        : "r"(a[0]), "r"(a[1]), "r"(a[2]), "r"(a[3]), "r"(b0), "r"(b1));
}

__device__ __forceinline__ void ldsm4(u32& r0, u32& r1, u32& r2, u32& r3, u32 addr) {
    asm volatile("ldmatrix.sync.aligned.m8n8.x4.shared.b16 {%0,%1,%2,%3}, [%4];"
                 : "=r"(r0), "=r"(r1), "=r"(r2), "=r"(r3) : "r"(addr));
}

__device__ __forceinline__ void cpa16(void* smem_ptr, const void* gptr) {
    u32 s = (u32)__cvta_generic_to_shared(smem_ptr);
    asm volatile("cp.async.cg.shared.global [%0], [%1], 16;\n" :: "r"(s), "l"(gptr));
}
__device__ __forceinline__ void cpa_commit() { asm volatile("cp.async.commit_group;\n"); }
template <int N>
__device__ __forceinline__ void cpa_wait() { asm volatile("cp.async.wait_group %0;\n" :: "n"(N)); }

__device__ __forceinline__ u32 smem_u32(const void* p) {
    return (u32)__cvta_generic_to_shared(p);
}

// ---------------------------------------------------------------------------
// fused split: grid (8192, 7); dsts are device globals
__global__ void __launch_bounds__(256) split7_kernel(
    const float4* __restrict__ q, const float4* __restrict__ k,
    const float4* __restrict__ v,
    const float4* __restrict__ wq, const float4* __restrict__ wk,
    const float4* __restrict__ wv, const float4* __restrict__ wo)
{
    const int seg = blockIdx.y;
    const int i = blockIdx.x * 256 + threadIdx.x;
    const float4* src; u32* dh; u32* dl; int n4;
    const int NI = M_ROWS * D_MODEL / 4, NW = D_MODEL * D_MODEL / 4;
    switch (seg) {
        case 0: src = q;  dh = (u32*)g_iqh; dl = (u32*)g_iql; n4 = NI; break;
        case 1: src = k;  dh = (u32*)g_ikh; dl = (u32*)g_ikl; n4 = NI; break;
        case 2: src = v;  dh = (u32*)g_ivh; dl = (u32*)g_ivl; n4 = NI; break;
        case 3: src = wq; dh = (u32*)g_wqh; dl = (u32*)g_wql; n4 = NW; break;
        case 4: src = wk; dh = (u32*)g_wkh; dl = (u32*)g_wkl; n4 = NW; break;
        case 5: src = wv; dh = (u32*)g_wvh; dl = (u32*)g_wvl; n4 = NW; break;
        default: src = wo; dh = (u32*)g_woh; dl = (u32*)g_wol; n4 = NW; break;
    }
    if (i >= n4) return;
    float4 val = src[i];
    u32 h0, l0, h1, l1;
    bsplit2(val.x, val.y, h0, l0);
    bsplit2(val.z, val.w, h1, l1);
    dh[2 * i] = h0; dh[2 * i + 1] = h1;
    dl[2 * i] = l0; dl[2 * i + 1] = l1;
}

// transpose + split V per head: g_V[b][t][h*64+d] -> vth/vtl[bh][d][t]
__global__ void __launch_bounds__(256) vtrans_kernel()
{
    __shared__ float ts[32][65];
    const int j0 = blockIdx.x * 32;
    const int bh = blockIdx.y;
    const int b = bh >> 4, h = bh & 15;
    const int tid = threadIdx.x;
#pragma unroll
    for (int i = 0; i < 8; i++) {
        int idx = tid + i * 256;
        int r = idx >> 6, c = idx & 63;
        ts[r][c] = g_V[(size_t)(b * T_SEQ + j0 + r) * D_MODEL + h * 64 + c];
    }
    __syncthreads();
    u32* oh = reinterpret_cast<u32*>(g_vth);
    u32* ol = reinterpret_cast<u32*>(g_vtl);
#pragma unroll
    for (int i = 0; i < 4; i++) {
        int idx = tid + i * 256;
        int d = idx >> 4, jj = (idx & 15) * 2;
        u32 h2, l2;
        bsplit2(ts[jj][d], ts[jj + 1][d], h2, l2);
        size_t o = ((size_t)(bh * 64 + d) * T_SEQ + j0 + jj) >> 1;
        oh[o] = h2; ol[o] = l2;
    }
}

// ---------------------------------------------------------------------------
// GEMM body: 3xBF16, ldmatrix, 2-stage pipeline, 2 CTAs/SM.
// ---------------------------------------------------------------------------
#define GKW 20
#define GT  (128 * GKW)
#define GEMM_SMEM (2 * 4 * GT * 4)   // 81920 B

__device__ __forceinline__ void gemm_body(
    char* smb,
    const __nv_bfloat16* __restrict__ Ah, const __nv_bfloat16* __restrict__ Al,
    const __nv_bfloat16* __restrict__ Bh, const __nv_bfloat16* __restrict__ Bl,
    const float* __restrict__ bias,
    float* __restrict__ Cf, u32* __restrict__ Ch, u32* __restrict__ Cl,
    bool split_out)
{
    const u32 sb = smem_u32(smb);
    const int tid  = threadIdx.x;
    const int lane = tid & 31;
    const int wid  = tid >> 5;
    const int g    = lane >> 2;
    const int q    = lane & 3;
    const int wm   = wid >> 2;
    const int wn   = wid & 3;
    const int bm   = blockIdx.y * 128;
    const int bn   = blockIdx.x * 128;
    const int K = D_MODEL, N = D_MODEL;

    float acc[4][4][4] = {};

    u32* smw = reinterpret_cast<u32*>(smb);
    auto issue = [&](int t, int buf) {
        const int k0 = t * 32;
        u32* base = smw + buf * 4 * GT;
#pragma unroll
        for (int i = 0; i < 8; i++) {
            int idx = tid + i * 256;
            int arr = idx >> 9;
            int w   = idx & 511;
            int row = w >> 2, c = w & 3;
            const __nv_bfloat16* gp;
            int rb;
            if      (arr == 0) { gp = Ah; rb = bm; }
            else if (arr == 1) { gp = Al; rb = bm; }
            else if (arr == 2) { gp = Bh; rb = bn; }
            else               { gp = Bl; rb = bn; }
            cpa16(base + arr * GT + row * GKW + c * 4,
                  gp + (size_t)(rb + row) * K + k0 + c * 8);
        }
    };

    const int NT = K / 32;   // 32
    issue(0, 0); cpa_commit();
    issue(1, 1); cpa_commit();

    const int aRow = (lane & 7) + ((lane >> 3) & 1) * 8;
    const int aK4  = ((lane >> 4) & 1) * 4;
    const int bRow = (lane & 7) + ((lane >> 4) & 1) * 8;
    const int bK4  = ((lane >> 3) & 1) * 4;

    for (int s = 0; s < NT; s++) {
        const int buf = s & 1;
        if (s + 1 < NT) cpa_wait<1>(); else cpa_wait<0>();
        __syncthreads();

        const u32 abh = sb + (u32)(buf * 4 * GT) * 4;
        const u32 abl = abh + GT * 4;
        const u32 bbh = abh + 2 * GT * 4;
        const u32 bbl = abh + 3 * GT * 4;

#pragma unroll
        for (int ks = 0; ks < 2; ks++) {
            u32 ah[4][4], al[4][4];
#pragma unroll
            for (int mt = 0; mt < 4; mt++) {
                u32 off = ((wm * 64 + mt * 16 + aRow) * GKW + ks * 8 + aK4) * 4;
                ldsm4(ah[mt][0], ah[mt][1], ah[mt][2], ah[mt][3], abh + off);
                ldsm4(al[mt][0], al[mt][1], al[mt][2], al[mt][3], abl + off);
            }
#pragma unroll
            for (int ntp = 0; ntp < 2; ntp++) {
                u32 bh0, bh1, bh2, bh3, bl0, bl1, bl2, bl3;
                u32 off = ((wn * 32 + ntp * 16 + bRow) * GKW + ks * 8 + bK4) * 4;
                ldsm4(bh0, bh1, bh2, bh3, bbh + off);
                ldsm4(bl0, bl1, bl2, bl3, bbl + off);
#pragma unroll
                for (int mt = 0; mt < 4; mt++) {
                    bmma(acc[mt][2 * ntp],     ah[mt], bh0, bh1);
                    bmma(acc[mt][2 * ntp],     al[mt], bh0, bh1);
                    bmma(acc[mt][2 * ntp],     ah[mt], bl0, bl1);
                    bmma(acc[mt][2 * ntp + 1], ah[mt], bh2, bh3);
                    bmma(acc[mt][2 * ntp + 1], al[mt], bh2, bh3);
                    bmma(acc[mt][2 * ntp + 1], ah[mt], bl2, bl3);
                }
            }
        }

        __syncthreads();
        if (s + 2 < NT) { issue(s + 2, buf); cpa_commit(); }
    }

#pragma unroll
    for (int mt = 0; mt < 4; mt++) {
        int row0 = bm + wm * 64 + mt * 16 + g;
#pragma unroll
        for (int nt = 0; nt < 4; nt++) {
            int col = bn + wn * 32 + nt * 8 + 2 * q;
            float b0 = bias[col], b1 = bias[col + 1];
            float v00 = acc[mt][nt][0] + b0, v01 = acc[mt][nt][1] + b1;
            float v10 = acc[mt][nt][2] + b0, v11 = acc[mt][nt][3] + b1;
            if (split_out) {
                u32 h2, l2;
                size_t o0 = ((size_t)row0 * N + col) >> 1;
                size_t o1 = ((size_t)(row0 + 8) * N + col) >> 1;
                bsplit2(v00, v01, h2, l2); Ch[o0] = h2; Cl[o0] = l2;
                bsplit2(v10, v11, h2, l2); Ch[o1] = h2; Cl[o1] = l2;
            } else {
                *(float2*)&Cf[(size_t)row0 * N + col]       = make_float2(v00, v01);
                *(float2*)&Cf[(size_t)(row0 + 8) * N + col] = make_float2(v10, v11);
            }
        }
    }
}

__global__ void __launch_bounds__(256, 2) gemm_qkv(
    const float* __restrict__ b_q, const float* __restrict__ b_k,
    const float* __restrict__ b_v)
{
    extern __shared__ char smb[];
    const int z = blockIdx.z;
    if (z == 0)
        gemm_body(smb, g_iqh, g_iql, g_wqh, g_wql, b_q,
                  nullptr, (u32*)g_pqh, (u32*)g_pql, true);
    else if (z == 1)
        gemm_body(smb, g_ikh, g_ikl, g_wkh, g_wkl, b_k,
                  nullptr, (u32*)g_pkh, (u32*)g_pkl, true);
    else
        gemm_body(smb, g_ivh, g_ivl, g_wvh, g_wvl, b_v,
                  g_V, nullptr, nullptr, false);
}

__global__ void __launch_bounds__(256, 2) gemm_o(
    const float* __restrict__ b_o, float* __restrict__ out)
{
    extern __shared__ char smb[];
    gemm_body(smb, g_aoh, g_aol, g_woh, g_wol, b_o, out, nullptr, nullptr, false);
}

// ---------------------------------------------------------------------------
// Causal flash attention, 3xBF16, 128-wide kv tiles, one sync per tile.
// Grid (T/128, B*H), 256 thr = 8 warps x 16 q-rows.
// ---------------------------------------------------------------------------
#define KSTR 36
#define VSTR 68
#define KT_W (128 * KSTR)   // 4608 words
#define VT_W (64 * VSTR)    // 4352 words
#define KH_OFF(b) ((b) * KT_W)
#define KL_OFF(b) (2 * KT_W + (b) * KT_W)
#define VH_OFF(b) (4 * KT_W + (b) * VT_W)
#define VL_OFF(b) (4 * KT_W + 2 * VT_W + (b) * VT_W)
#define ATTN_SMEM_W (4 * KT_W + 4 * VT_W)   // 35840 words = 143360 B

__global__ void __launch_bounds__(256) attn_causal()
{
    extern __shared__ u32 smw[];
    const u32 sb = smem_u32(smw);

    const int qb = gridDim.x - 1 - blockIdx.x;   // heavy blocks first
    const int bh = blockIdx.y;
    const int b  = bh >> 4;
    const int h  = bh & 15;

    const int tid  = threadIdx.x;
    const int lane = tid & 31;
    const int wq   = tid >> 5;
    const int g    = lane >> 2;
    const int q    = lane & 3;

    const float scale = 0.125f;
    const u32* kh_g = reinterpret_cast<const u32*>(g_pkh);
    const u32* kl_g = reinterpret_cast<const u32*>(g_pkl);
    const u32* vh_g = reinterpret_cast<const u32*>(g_vth);
    const u32* vl_g = reinterpret_cast<const u32*>(g_vtl);

    const int aRow = (lane & 7) + ((lane >> 3) & 1) * 8;
    const int aK4  = ((lane >> 4) & 1) * 4;
    const int bRow = (lane & 7) + ((lane >> 4) & 1) * 8;
    const int bK4  = ((lane >> 3) & 1) * 4;

    // ---- stage Q (reuses K region), load fragments ----
    {
        const u32* qh_g = reinterpret_cast<const u32*>(g_pqh);
        const u32* ql_g = reinterpret_cast<const u32*>(g_pql);
#pragma unroll
        for (int i = 0; i < 8; i++) {
            int idx = tid + i * 256;
            int arr = idx >> 10;
            int w   = idx & 1023;
            int row = w >> 3, c = w & 7;
            const u32* gp = arr ? ql_g : qh_g;
            cpa16(smw + arr * KT_W + row * KSTR + c * 4,
                  gp + (((size_t)(b * T_SEQ + qb * 128 + row) * D_MODEL + h * 64) >> 1) + c * 4);
        }
        cpa_commit();
        cpa_wait<0>();
        __syncthreads();
    }
    u32 qh[4][4], ql[4][4];
#pragma unroll
    for (int kt = 0; kt < 4; kt++) {
        u32 off = ((wq * 16 + aRow) * KSTR + kt * 8 + aK4) * 4;
        ldsm4(qh[kt][0], qh[kt][1], qh[kt][2], qh[kt][3], sb + off);
        ldsm4(ql[kt][0], ql[kt][1], ql[kt][2], ql[kt][3], sb + (u32)KT_W * 4 + off);
    }
    __syncthreads();   // Q region reused by K staging

    auto stage_kv = [&](int kb, int buf) {
#pragma unroll
        for (int i = 0; i < 8; i++) {
            int idx = tid + i * 256;
            int arr = idx >> 10;
            int w   = idx & 1023;
            int row = w >> 3, c = w & 7;
            const u32* gp = arr ? kl_g : kh_g;
            cpa16(smw + (arr ? KL_OFF(buf) : KH_OFF(buf)) + row * KSTR + c * 4,
                  gp + (((size_t)(b * T_SEQ + kb * 128 + row) * D_MODEL + h * 64) >> 1) + c * 4);
        }
#pragma unroll
        for (int i = 0; i < 8; i++) {
            int idx = tid + i * 256;
            int arr = idx >> 10;
            int w   = idx & 1023;
            int row = w >> 4, c = w & 15;
            const u32* gp = arr ? vl_g : vh_g;
            cpa16(smw + (arr ? VL_OFF(buf) : VH_OFF(buf)) + row * VSTR + c * 4,
                  gp + (size_t)(bh * 64 + row) * (T_SEQ / 2) + kb * 64 + c * 4);
        }
    };

    stage_kv(0, 0);
    cpa_commit();

    float of[8][4] = {};
    float m0 = -INFINITY, m1 = -INFINITY, l0 = 0.f, l1 = 0.f;
    const int R = qb * 128 + wq * 16;

    for (int kb = 0; kb <= qb; kb++) {
        cpa_wait<0>();
        __syncthreads();
        if (kb + 1 <= qb) { stage_kv(kb + 1, (kb + 1) & 1); cpa_commit(); }

        const bool active = (kb * 128 <= R + 15);
        if (active) {
            const u32 kshb = sb + (u32)KH_OFF(kb & 1) * 4;
            const u32 kslb = sb + (u32)KL_OFF(kb & 1) * 4;
            const u32 vshb = sb + (u32)VH_OFF(kb & 1) * 4;
            const u32 vslb = sb + (u32)VL_OFF(kb & 1) * 4;

            // S = Q K^T  (16 x 128 per warp)
            float sf[16][4] = {};
#pragma unroll
            for (int kt = 0; kt < 4; kt++) {
#pragma unroll
                for (int ntp = 0; ntp < 8; ntp++) {
                    u32 h0, h1, h2, h3, l0r, l1r, l2r, l3r;
                    u32 off = ((ntp * 16 + bRow) * KSTR + kt * 8 + bK4) * 4;
                    ldsm4(h0, h1, h2, h3, kshb + off);
                    ldsm4(l0r, l1r, l2r, l3r, kslb + off);
                    bmma(sf[2 * ntp],     qh[kt], h0, h1);
                    bmma(sf[2 * ntp],     ql[kt], h0, h1);
                    bmma(sf[2 * ntp],     qh[kt], l0r, l1r);
                    bmma(sf[2 * ntp + 1], qh[kt], h2, h3);
                    bmma(sf[2 * ntp + 1], ql[kt], h2, h3);
                    bmma(sf[2 * ntp + 1], qh[kt], l2r, l3r);
                }
            }

            // mask (diagonal 128-tile only) + scale
            if (kb * 128 + 127 > R) {
                int r0 = R + g, r1 = r0 + 8;
#pragma unroll
                for (int nt = 0; nt < 16; nt++) {
                    int c0 = kb * 128 + nt * 8 + 2 * q, c1 = c0 + 1;
                    if (c0 > r0) sf[nt][0] = -INFINITY;
                    if (c1 > r0) sf[nt][1] = -INFINITY;
                    if (c0 > r1) sf[nt][2] = -INFINITY;
                    if (c1 > r1) sf[nt][3] = -INFINITY;
                }
            }
#pragma unroll
            for (int nt = 0; nt < 16; nt++) {
                sf[nt][0] *= scale; sf[nt][1] *= scale;
                sf[nt][2] *= scale; sf[nt][3] *= scale;
            }

            // online softmax
            float mx0 = -INFINITY, mx1 = -INFINITY;
#pragma unroll
            for (int nt = 0; nt < 16; nt++) {
                mx0 = fmaxf(mx0, fmaxf(sf[nt][0], sf[nt][1]));
                mx1 = fmaxf(mx1, fmaxf(sf[nt][2], sf[nt][3]));
            }
            mx0 = fmaxf(mx0, __shfl_xor_sync(0xffffffffu, mx0, 1));
            mx0 = fmaxf(mx0, __shfl_xor_sync(0xffffffffu, mx0, 2));
            mx1 = fmaxf(mx1, __shfl_xor_sync(0xffffffffu, mx1, 1));
            mx1 = fmaxf(mx1, __shfl_xor_sync(0xffffffffu, mx1, 2));

            float mn0 = fmaxf(m0, mx0), mn1 = fmaxf(m1, mx1);
            float c0 = __expf(m0 - mn0), c1 = __expf(m1 - mn1);
            m0 = mn0; m1 = mn1;

            float ls0 = 0.f, ls1 = 0.f;
#pragma unroll
            for (int nt = 0; nt < 16; nt++) {
                sf[nt][0] = __expf(sf[nt][0] - mn0);
                sf[nt][1] = __expf(sf[nt][1] - mn0);
                sf[nt][2] = __expf(sf[nt][2] - mn1);
                sf[nt][3] = __expf(sf[nt][3] - mn1);
                ls0 += sf[nt][0] + sf[nt][1];
                ls1 += sf[nt][2] + sf[nt][3];
            }
#pragma unroll
            for (int nt = 0; nt < 8; nt++) {
                of[nt][0] *= c0; of[nt][1] *= c0;
                of[nt][2] *= c1; of[nt][3] *= c1;
            }
            ls0 += __shfl_xor_sync(0xffffffffu, ls0, 1);
            ls0 += __shfl_xor_sync(0xffffffffu, ls0, 2);
            ls1 += __shfl_xor_sync(0xffffffffu, ls1, 1);
            ls1 += __shfl_xor_sync(0xffffffffu, ls1, 2);
            l0 = l0 * c0 + ls0;
            l1 = l1 * c1 + ls1;

            // O += P V (P packed in registers; jt over 8 k-groups of 16 j)
#pragma unroll
            for (int jt = 0; jt < 8; jt++) {
                u32 pah[4], pal[4];
                bsplit2(sf[2 * jt][0],     sf[2 * jt][1],     pah[0], pal[0]);
                bsplit2(sf[2 * jt][2],     sf[2 * jt][3],     pah[1], pal[1]);
                bsplit2(sf[2 * jt + 1][0], sf[2 * jt + 1][1], pah[2], pal[2]);
                bsplit2(sf[2 * jt + 1][2], sf[2 * jt + 1][3], pah[3], pal[3]);
#pragma unroll
                for (int ntp = 0; ntp < 4; ntp++) {
                    u32 h0, h1, h2, h3, l0r, l1r, l2r, l3r;
                    u32 off = ((ntp * 16 + bRow) * VSTR + jt * 8 + bK4) * 4;
                    ldsm4(h0, h1, h2, h3, vshb + off);
                    ldsm4(l0r, l1r, l2r, l3r, vslb + off);
                    bmma(of[2 * ntp],     pah, h0, h1);
                    bmma(of[2 * ntp],     pal, h0, h1);
                    bmma(of[2 * ntp],     pah, l0r, l1r);
                    bmma(of[2 * ntp + 1], pah, h2, h3);
                    bmma(of[2 * ntp + 1], pal, h2, h3);
                    bmma(of[2 * ntp + 1], pah, l2r, l3r);
                }
            }
        }
    }

    // epilogue: normalize + split-write (heads merged)
    float inv0 = 1.0f / l0, inv1 = 1.0f / l1;
    u32* oh = reinterpret_cast<u32*>(g_aoh);
    u32* ol = reinterpret_cast<u32*>(g_aol);
    size_t m0i = (size_t)(b * T_SEQ + R + g) * D_MODEL + h * 64;
    size_t m1i = m0i + (size_t)8 * D_MODEL;
#pragma unroll
    for (int nt = 0; nt < 8; nt++) {
        int col = nt * 8 + 2 * q;
        u32 h2, l2;
        bsplit2(of[nt][0] * inv0, of[nt][1] * inv0, h2, l2);
        oh[(m0i + col) >> 1] = h2; ol[(m0i + col) >> 1] = l2;
        bsplit2(of[nt][2] * inv1, of[nt][3] * inv1, h2, l2);
        oh[(m1i + col) >> 1] = h2; ol[(m1i + col) >> 1] = l2;
    }
}

// ---------------------------------------------------------------------------
extern "C" void kernel_launch(void* const* d_in, const int* in_sizes, int n_in,
                              void* d_out, int out_size)
{
    const float* q   = (const float*)d_in[0];
    const float* k   = (const float*)d_in[1];
    const float* v   = (const float*)d_in[2];
    const float* W_q = (const float*)d_in[4];
    const float* b_q = (const float*)d_in[5];
    const float* W_k = (const float*)d_in[6];
    const float* b_k = (const float*)d_in[7];
    const float* W_v = (const float*)d_in[8];
    const float* b_v = (const float*)d_in[9];
    const float* W_o = (const float*)d_in[10];
    const float* b_o = (const float*)d_in[11];
    float* out = (float*)d_out;

    const int attn_smem = ATTN_SMEM_W * 4;   // 143360
    cudaFuncSetAttribute(gemm_qkv, cudaFuncAttributeMaxDynamicSharedMemorySize, GEMM_SMEM);
    cudaFuncSetAttribute(gemm_o,   cudaFuncAttributeMaxDynamicSharedMemorySize, GEMM_SMEM);
    cudaFuncSetAttribute(attn_causal, cudaFuncAttributeMaxDynamicSharedMemorySize, attn_smem);

    dim3 sg(M_ROWS * D_MODEL / 4 / 256, 7);   // (8192, 7)
    split7_kernel<<<sg, 256>>>((const float4*)q, (const float4*)k, (const float4*)v,
                               (const float4*)W_q, (const float4*)W_k,
                               (const float4*)W_v, (const float4*)W_o);

    dim3 gg(D_MODEL / 128, M_ROWS / 128, 3);   // (8, 64, 3)
    gemm_qkv<<<gg, 256, GEMM_SMEM>>>(b_q, b_k, b_v);

    dim3 tg(T_SEQ / 32, B_SZ * N_HEADS);
    vtrans_kernel<<<tg, 256>>>();

    dim3 ag(T_SEQ / 128, B_SZ * N_HEADS);      // (16, 64)
    attn_causal<<<ag, 256, attn_smem>>>();

    dim3 go(D_MODEL / 128, M_ROWS / 128);
    gemm_o<<<go, 256, GEMM_SMEM>>>(b_o, out);
}

// round 11
// speedup vs baseline: 2.1168x; 1.0027x over previous
#include <cuda_runtime.h>
#include <cuda_bf16.h>
#include <math.h>
#include <stdint.h>

#define D_MODEL 1024
#define N_HEADS 16
#define B_SZ    4
#define T_SEQ   2048
#define M_ROWS  8192

typedef unsigned int u32;

// bf16 hi/lo scratch (allocation-free rule: __device__ globals)
__device__ __nv_bfloat16 g_iqh[M_ROWS * D_MODEL], g_iql[M_ROWS * D_MODEL];
__device__ __nv_bfloat16 g_ikh[M_ROWS * D_MODEL], g_ikl[M_ROWS * D_MODEL];
__device__ __nv_bfloat16 g_ivh[M_ROWS * D_MODEL], g_ivl[M_ROWS * D_MODEL];
__device__ __nv_bfloat16 g_wqh[D_MODEL * D_MODEL], g_wql[D_MODEL * D_MODEL];
__device__ __nv_bfloat16 g_wkh[D_MODEL * D_MODEL], g_wkl[D_MODEL * D_MODEL];
__device__ __nv_bfloat16 g_wvh[D_MODEL * D_MODEL], g_wvl[D_MODEL * D_MODEL];
__device__ __nv_bfloat16 g_woh[D_MODEL * D_MODEL], g_wol[D_MODEL * D_MODEL];
__device__ __nv_bfloat16 g_pqh[M_ROWS * D_MODEL], g_pql[M_ROWS * D_MODEL];
__device__ __nv_bfloat16 g_pkh[M_ROWS * D_MODEL], g_pkl[M_ROWS * D_MODEL];
__device__ float         g_V  [M_ROWS * D_MODEL];
__device__ __nv_bfloat16 g_vth[M_ROWS * D_MODEL], g_vtl[M_ROWS * D_MODEL]; // [bh][64][2048]
__device__ __nv_bfloat16 g_aoh[M_ROWS * D_MODEL], g_aol[M_ROWS * D_MODEL];

// ---------------------------------------------------------------------------
// pack bf16x2 hi/lo split of (x0,x1): lower half = x0 (even index)
__device__ __forceinline__ void bsplit2(float x0, float x1, u32& hi, u32& lo) {
    u32 h;
    asm("cvt.rn.bf16x2.f32 %0, %1, %2;" : "=r"(h) : "f"(x1), "f"(x0));
    float h0 = __uint_as_float(h << 16);
    float h1 = __uint_as_float(h & 0xffff0000u);
    u32 l;
    float r0 = x0 - h0, r1 = x1 - h1;
    asm("cvt.rn.bf16x2.f32 %0, %1, %2;" : "=r"(l) : "f"(r1), "f"(r0));
    hi = h; lo = l;
}

__device__ __forceinline__ void bmma(float d[4], const u32 a[4], u32 b0, u32 b1) {
    asm volatile(
        "mma.sync.aligned.m16n8k16.row.col.f32.bf16.bf16.f32 "
        "{%0,%1,%2,%3}, {%4,%5,%6,%7}, {%8,%9}, {%0,%1,%2,%3};\n"
        : "+f"(d[0]), "+f"(d[1]), "+f"(d[2]), "+f"(d[3])
        : "r"(a[0]), "r"(a[1]), "r"(a[2]), "r"(a[3]), "r"(b0), "r"(b1));
}

__device__ __forceinline__ void ldsm4(u32& r0, u32& r1, u32& r2, u32& r3, u32 addr) {
    asm volatile("ldmatrix.sync.aligned.m8n8.x4.shared.b16 {%0,%1,%2,%3}, [%4];"
                 : "=r"(r0), "=r"(r1), "=r"(r2), "=r"(r3) : "r"(addr));
}

__device__ __forceinline__ void cpa16(void* smem_ptr, const void* gptr) {
    u32 s = (u32)__cvta_generic_to_shared(smem_ptr);
    asm volatile("cp.async.cg.shared.global [%0], [%1], 16;\n" :: "r"(s), "l"(gptr));
}
__device__ __forceinline__ void cpa_commit() { asm volatile("cp.async.commit_group;\n"); }
template <int N>
__device__ __forceinline__ void cpa_wait() { asm volatile("cp.async.wait_group %0;\n" :: "n"(N)); }

__device__ __forceinline__ u32 smem_u32(const void* p) {
    return (u32)__cvta_generic_to_shared(p);
}

// ---------------------------------------------------------------------------
// fused split: grid (8192, 7); dsts are device globals
__global__ void __launch_bounds__(256) split7_kernel(
    const float4* __restrict__ q, const float4* __restrict__ k,
    const float4* __restrict__ v,
    const float4* __restrict__ wq, const float4* __restrict__ wk,
    const float4* __restrict__ wv, const float4* __restrict__ wo)
{
    const int seg = blockIdx.y;
    const int i = blockIdx.x * 256 + threadIdx.x;
    const float4* src; u32* dh; u32* dl; int n4;
    const int NI = M_ROWS * D_MODEL / 4, NW = D_MODEL * D_MODEL / 4;
    switch (seg) {
        case 0: src = q;  dh = (u32*)g_iqh; dl = (u32*)g_iql; n4 = NI; break;
        case 1: src = k;  dh = (u32*)g_ikh; dl = (u32*)g_ikl; n4 = NI; break;
        case 2: src = v;  dh = (u32*)g_ivh; dl = (u32*)g_ivl; n4 = NI; break;
        case 3: src = wq; dh = (u32*)g_wqh; dl = (u32*)g_wql; n4 = NW; break;
        case 4: src = wk; dh = (u32*)g_wkh; dl = (u32*)g_wkl; n4 = NW; break;
        case 5: src = wv; dh = (u32*)g_wvh; dl = (u32*)g_wvl; n4 = NW; break;
        default: src = wo; dh = (u32*)g_woh; dl = (u32*)g_wol; n4 = NW; break;
    }
    if (i >= n4) return;
    float4 val = src[i];
    u32 h0, l0, h1, l1;
    bsplit2(val.x, val.y, h0, l0);
    bsplit2(val.z, val.w, h1, l1);
    dh[2 * i] = h0; dh[2 * i + 1] = h1;
    dl[2 * i] = l0; dl[2 * i + 1] = l1;
}

// transpose + split V per head: g_V[b][t][h*64+d] -> vth/vtl[bh][d][t]
__global__ void __launch_bounds__(256) vtrans_kernel()
{
    __shared__ float ts[32][65];
    const int j0 = blockIdx.x * 32;
    const int bh = blockIdx.y;
    const int b = bh >> 4, h = bh & 15;
    const int tid = threadIdx.x;
#pragma unroll
    for (int i = 0; i < 8; i++) {
        int idx = tid + i * 256;
        int r = idx >> 6, c = idx & 63;
        ts[r][c] = g_V[(size_t)(b * T_SEQ + j0 + r) * D_MODEL + h * 64 + c];
    }
    __syncthreads();
    u32* oh = reinterpret_cast<u32*>(g_vth);
    u32* ol = reinterpret_cast<u32*>(g_vtl);
#pragma unroll
    for (int i = 0; i < 4; i++) {
        int idx = tid + i * 256;
        int d = idx >> 4, jj = (idx & 15) * 2;
        u32 h2, l2;
        bsplit2(ts[jj][d], ts[jj + 1][d], h2, l2);
        size_t o = ((size_t)(bh * 64 + d) * T_SEQ + j0 + jj) >> 1;
        oh[o] = h2; ol[o] = l2;
    }
}

// ---------------------------------------------------------------------------
// GEMM body: 3xBF16, ldmatrix, 2-stage pipeline, 2 CTAs/SM. (unchanged)
// ---------------------------------------------------------------------------
#define GKW 20
#define GT  (128 * GKW)
#define GEMM_SMEM (2 * 4 * GT * 4)   // 81920 B

__device__ __forceinline__ void gemm_body(
    char* smb,
    const __nv_bfloat16* __restrict__ Ah, const __nv_bfloat16* __restrict__ Al,
    const __nv_bfloat16* __restrict__ Bh, const __nv_bfloat16* __restrict__ Bl,
    const float* __restrict__ bias,
    float* __restrict__ Cf, u32* __restrict__ Ch, u32* __restrict__ Cl,
    bool split_out)
{
    const u32 sb = smem_u32(smb);
    const int tid  = threadIdx.x;
    const int lane = tid & 31;
    const int wid  = tid >> 5;
    const int g    = lane >> 2;
    const int q    = lane & 3;
    const int wm   = wid >> 2;
    const int wn   = wid & 3;
    const int bm   = blockIdx.y * 128;
    const int bn   = blockIdx.x * 128;
    const int K = D_MODEL, N = D_MODEL;

    float acc[4][4][4] = {};

    u32* smw = reinterpret_cast<u32*>(smb);
    auto issue = [&](int t, int buf) {
        const int k0 = t * 32;
        u32* base = smw + buf * 4 * GT;
#pragma unroll
        for (int i = 0; i < 8; i++) {
            int idx = tid + i * 256;
            int arr = idx >> 9;
            int w   = idx & 511;
            int row = w >> 2, c = w & 3;
            const __nv_bfloat16* gp;
            int rb;
            if      (arr == 0) { gp = Ah; rb = bm; }
            else if (arr == 1) { gp = Al; rb = bm; }
            else if (arr == 2) { gp = Bh; rb = bn; }
            else               { gp = Bl; rb = bn; }
            cpa16(base + arr * GT + row * GKW + c * 4,
                  gp + (size_t)(rb + row) * K + k0 + c * 8);
        }
    };

    const int NT = K / 32;   // 32
    issue(0, 0); cpa_commit();
    issue(1, 1); cpa_commit();

    const int aRow = (lane & 7) + ((lane >> 3) & 1) * 8;
    const int aK4  = ((lane >> 4) & 1) * 4;
    const int bRow = (lane & 7) + ((lane >> 4) & 1) * 8;
    const int bK4  = ((lane >> 3) & 1) * 4;

    for (int s = 0; s < NT; s++) {
        const int buf = s & 1;
        if (s + 1 < NT) cpa_wait<1>(); else cpa_wait<0>();
        __syncthreads();

        const u32 abh = sb + (u32)(buf * 4 * GT) * 4;
        const u32 abl = abh + GT * 4;
        const u32 bbh = abh + 2 * GT * 4;
        const u32 bbl = abh + 3 * GT * 4;

#pragma unroll
        for (int ks = 0; ks < 2; ks++) {
            u32 ah[4][4], al[4][4];
#pragma unroll
            for (int mt = 0; mt < 4; mt++) {
                u32 off = ((wm * 64 + mt * 16 + aRow) * GKW + ks * 8 + aK4) * 4;
                ldsm4(ah[mt][0], ah[mt][1], ah[mt][2], ah[mt][3], abh + off);
                ldsm4(al[mt][0], al[mt][1], al[mt][2], al[mt][3], abl + off);
            }
#pragma unroll
            for (int ntp = 0; ntp < 2; ntp++) {
                u32 bh0, bh1, bh2, bh3, bl0, bl1, bl2, bl3;
                u32 off = ((wn * 32 + ntp * 16 + bRow) * GKW + ks * 8 + bK4) * 4;
                ldsm4(bh0, bh1, bh2, bh3, bbh + off);
                ldsm4(bl0, bl1, bl2, bl3, bbl + off);
#pragma unroll
                for (int mt = 0; mt < 4; mt++) {
                    bmma(acc[mt][2 * ntp],     ah[mt], bh0, bh1);
                    bmma(acc[mt][2 * ntp],     al[mt], bh0, bh1);
                    bmma(acc[mt][2 * ntp],     ah[mt], bl0, bl1);
                    bmma(acc[mt][2 * ntp + 1], ah[mt], bh2, bh3);
                    bmma(acc[mt][2 * ntp + 1], al[mt], bh2, bh3);
                    bmma(acc[mt][2 * ntp + 1], ah[mt], bl2, bl3);
                }
            }
        }

        __syncthreads();
        if (s + 2 < NT) { issue(s + 2, buf); cpa_commit(); }
    }

#pragma unroll
    for (int mt = 0; mt < 4; mt++) {
        int row0 = bm + wm * 64 + mt * 16 + g;
#pragma unroll
        for (int nt = 0; nt < 4; nt++) {
            int col = bn + wn * 32 + nt * 8 + 2 * q;
            float b0 = bias[col], b1 = bias[col + 1];
            float v00 = acc[mt][nt][0] + b0, v01 = acc[mt][nt][1] + b1;
            float v10 = acc[mt][nt][2] + b0, v11 = acc[mt][nt][3] + b1;
            if (split_out) {
                u32 h2, l2;
                size_t o0 = ((size_t)row0 * N + col) >> 1;
                size_t o1 = ((size_t)(row0 + 8) * N + col) >> 1;
                bsplit2(v00, v01, h2, l2); Ch[o0] = h2; Cl[o0] = l2;
                bsplit2(v10, v11, h2, l2); Ch[o1] = h2; Cl[o1] = l2;
            } else {
                *(float2*)&Cf[(size_t)row0 * N + col]       = make_float2(v00, v01);
                *(float2*)&Cf[(size_t)(row0 + 8) * N + col] = make_float2(v10, v11);
            }
        }
    }
}

__global__ void __launch_bounds__(256, 2) gemm_qkv(
    const float* __restrict__ b_q, const float* __restrict__ b_k,
    const float* __restrict__ b_v)
{
    extern __shared__ char smb[];
    const int z = blockIdx.z;
    if (z == 0)
        gemm_body(smb, g_iqh, g_iql, g_wqh, g_wql, b_q,
                  nullptr, (u32*)g_pqh, (u32*)g_pql, true);
    else if (z == 1)
        gemm_body(smb, g_ikh, g_ikl, g_wkh, g_wkl, b_k,
                  nullptr, (u32*)g_pkh, (u32*)g_pkl, true);
    else
        gemm_body(smb, g_ivh, g_ivl, g_wvh, g_wvl, b_v,
                  g_V, nullptr, nullptr, false);
}

__global__ void __launch_bounds__(256, 2) gemm_o(
    const float* __restrict__ b_o, float* __restrict__ out)
{
    extern __shared__ char smb[];
    gemm_body(smb, g_aoh, g_aol, g_woh, g_wol, b_o, out, nullptr, nullptr, false);
}

// ---------------------------------------------------------------------------
// Causal flash attention, 3xBF16, 64-wide kv tiles, 2 CTAs/SM (16 warps).
// Grid (T/128, B*H), 256 thr = 8 warps x 16 q-rows.
// ---------------------------------------------------------------------------
#define KSTR 36
#define ATW  (64 * KSTR)                   // 2304 words per tile copy
#define KH_OFF(b) ((b) * ATW)
#define KL_OFF(b) (2 * ATW + (b) * ATW)
#define VH_OFF(b) (4 * ATW + (b) * ATW)
#define VL_OFF(b) (6 * ATW + (b) * ATW)
#define ATTN_SMEM_W (8 * ATW)              // 18432 words = 73728 B

__global__ void __launch_bounds__(256, 2) attn_causal()
{
    extern __shared__ u32 smw[];
    const u32 sb = smem_u32(smw);

    const int qb = gridDim.x - 1 - blockIdx.x;   // heavy blocks first
    const int bh = blockIdx.y;
    const int b  = bh >> 4;
    const int h  = bh & 15;

    const int tid  = threadIdx.x;
    const int lane = tid & 31;
    const int wq   = tid >> 5;
    const int g    = lane >> 2;
    const int q    = lane & 3;

    const float scale = 0.125f;
    const u32* kh_g = reinterpret_cast<const u32*>(g_pkh);
    const u32* kl_g = reinterpret_cast<const u32*>(g_pkl);
    const u32* vh_g = reinterpret_cast<const u32*>(g_vth);
    const u32* vl_g = reinterpret_cast<const u32*>(g_vtl);

    const int aRow = (lane & 7) + ((lane >> 3) & 1) * 8;
    const int aK4  = ((lane >> 4) & 1) * 4;
    const int bRow = (lane & 7) + ((lane >> 4) & 1) * 8;
    const int bK4  = ((lane >> 3) & 1) * 4;

    // ---- stage Q (128 rows x 32 words, hi+lo; reuses K/V region) ----
    {
        const u32* qh_g = reinterpret_cast<const u32*>(g_pqh);
        const u32* ql_g = reinterpret_cast<const u32*>(g_pql);
#pragma unroll
        for (int i = 0; i < 8; i++) {
            int idx = tid + i * 256;         // 2048 chunks
            int arr = idx >> 10;
            int w   = idx & 1023;
            int row = w >> 3, c = w & 7;
            const u32* gp = arr ? ql_g : qh_g;
            cpa16(smw + arr * (128 * KSTR) + row * KSTR + c * 4,
                  gp + (((size_t)(b * T_SEQ + qb * 128 + row) * D_MODEL + h * 64) >> 1) + c * 4);
        }
        cpa_commit();
        cpa_wait<0>();
        __syncthreads();
    }
    u32 qh[4][4], ql[4][4];
#pragma unroll
    for (int kt = 0; kt < 4; kt++) {
        u32 off = ((wq * 16 + aRow) * KSTR + kt * 8 + aK4) * 4;
        ldsm4(qh[kt][0], qh[kt][1], qh[kt][2], qh[kt][3], sb + off);
        ldsm4(ql[kt][0], ql[kt][1], ql[kt][2], ql[kt][3], sb + (u32)(128 * KSTR) * 4 + off);
    }
    __syncthreads();   // Q region reused by K/V staging

    auto stage_kv = [&](int kb, int buf) {
        // K: 64 rows x 32 words, hi+lo = 1024 chunks
#pragma unroll
        for (int i = 0; i < 4; i++) {
            int idx = tid + i * 256;
            int arr = idx >> 9;
            int w   = idx & 511;
            int row = w >> 3, c = w & 7;
            const u32* gp = arr ? kl_g : kh_g;
            cpa16(smw + (arr ? KL_OFF(buf) : KH_OFF(buf)) + row * KSTR + c * 4,
                  gp + (((size_t)(b * T_SEQ + kb * 64 + row) * D_MODEL + h * 64) >> 1) + c * 4);
        }
        // Vt: 64 d-rows x 32 words (64 t), hi+lo = 1024 chunks
#pragma unroll
        for (int i = 0; i < 4; i++) {
            int idx = tid + i * 256;
            int arr = idx >> 9;
            int w   = idx & 511;
            int row = w >> 3, c = w & 7;
            const u32* gp = arr ? vl_g : vh_g;
            cpa16(smw + (arr ? VL_OFF(buf) : VH_OFF(buf)) + row * KSTR + c * 4,
                  gp + (size_t)(bh * 64 + row) * (T_SEQ / 2) + kb * 32 + c * 4);
        }
    };

    stage_kv(0, 0);
    cpa_commit();

    float of[8][4] = {};
    float m0 = -INFINITY, m1 = -INFINITY, l0 = 0.f, l1 = 0.f;
    const int R = qb * 128 + wq * 16;
    const int kbmax = 2 * qb + 1;

    for (int kb = 0; kb <= kbmax; kb++) {
        cpa_wait<0>();
        __syncthreads();
        if (kb + 1 <= kbmax) { stage_kv(kb + 1, (kb + 1) & 1); cpa_commit(); }

        const bool active = (kb * 64 <= R + 15);
        if (active) {
            const u32 kshb = sb + (u32)KH_OFF(kb & 1) * 4;
            const u32 kslb = sb + (u32)KL_OFF(kb & 1) * 4;
            const u32 vshb = sb + (u32)VH_OFF(kb & 1) * 4;
            const u32 vslb = sb + (u32)VL_OFF(kb & 1) * 4;

            // S = Q K^T  (16 x 64 per warp)
            float sf[8][4] = {};
#pragma unroll
            for (int kt = 0; kt < 4; kt++) {
#pragma unroll
                for (int ntp = 0; ntp < 4; ntp++) {
                    u32 h0, h1, h2, h3, l0r, l1r, l2r, l3r;
                    u32 off = ((ntp * 16 + bRow) * KSTR + kt * 8 + bK4) * 4;
                    ldsm4(h0, h1, h2, h3, kshb + off);
                    ldsm4(l0r, l1r, l2r, l3r, kslb + off);
                    bmma(sf[2 * ntp],     qh[kt], h0, h1);
                    bmma(sf[2 * ntp],     ql[kt], h0, h1);
                    bmma(sf[2 * ntp],     qh[kt], l0r, l1r);
                    bmma(sf[2 * ntp + 1], qh[kt], h2, h3);
                    bmma(sf[2 * ntp + 1], ql[kt], h2, h3);
                    bmma(sf[2 * ntp + 1], qh[kt], l2r, l3r);
                }
            }

            // mask (boundary tiles only) + scale
            if (kb * 64 + 63 > R) {
                int r0 = R + g, r1 = r0 + 8;
#pragma unroll
                for (int nt = 0; nt < 8; nt++) {
                    int c0 = kb * 64 + nt * 8 + 2 * q, c1 = c0 + 1;
                    if (c0 > r0) sf[nt][0] = -INFINITY;
                    if (c1 > r0) sf[nt][1] = -INFINITY;
                    if (c0 > r1) sf[nt][2] = -INFINITY;
                    if (c1 > r1) sf[nt][3] = -INFINITY;
                }
            }
#pragma unroll
            for (int nt = 0; nt < 8; nt++) {
                sf[nt][0] *= scale; sf[nt][1] *= scale;
                sf[nt][2] *= scale; sf[nt][3] *= scale;
            }

            // online softmax
            float mx0 = -INFINITY, mx1 = -INFINITY;
#pragma unroll
            for (int nt = 0; nt < 8; nt++) {
                mx0 = fmaxf(mx0, fmaxf(sf[nt][0], sf[nt][1]));
                mx1 = fmaxf(mx1, fmaxf(sf[nt][2], sf[nt][3]));
            }
            mx0 = fmaxf(mx0, __shfl_xor_sync(0xffffffffu, mx0, 1));
            mx0 = fmaxf(mx0, __shfl_xor_sync(0xffffffffu, mx0, 2));
            mx1 = fmaxf(mx1, __shfl_xor_sync(0xffffffffu, mx1, 1));
            mx1 = fmaxf(mx1, __shfl_xor_sync(0xffffffffu, mx1, 2));

            float mn0 = fmaxf(m0, mx0), mn1 = fmaxf(m1, mx1);
            float c0 = __expf(m0 - mn0), c1 = __expf(m1 - mn1);
            m0 = mn0; m1 = mn1;

            float ls0 = 0.f, ls1 = 0.f;
#pragma unroll
            for (int nt = 0; nt < 8; nt++) {
                sf[nt][0] = __expf(sf[nt][0] - mn0);
                sf[nt][1] = __expf(sf[nt][1] - mn0);
                sf[nt][2] = __expf(sf[nt][2] - mn1);
                sf[nt][3] = __expf(sf[nt][3] - mn1);
                ls0 += sf[nt][0] + sf[nt][1];
                ls1 += sf[nt][2] + sf[nt][3];
            }
#pragma unroll
            for (int nt = 0; nt < 8; nt++) {
                of[nt][0] *= c0; of[nt][1] *= c0;
                of[nt][2] *= c1; of[nt][3] *= c1;
            }
            ls0 += __shfl_xor_sync(0xffffffffu, ls0, 1);
            ls0 += __shfl_xor_sync(0xffffffffu, ls0, 2);
            ls1 += __shfl_xor_sync(0xffffffffu, ls1, 1);
            ls1 += __shfl_xor_sync(0xffffffffu, ls1, 2);
            l0 = l0 * c0 + ls0;
            l1 = l1 * c1 + ls1;

            // O += P V (P packed in registers; jt over 4 k-groups of 16 j)
#pragma unroll
            for (int jt = 0; jt < 4; jt++) {
                u32 pah[4], pal[4];
                bsplit2(sf[2 * jt][0],     sf[2 * jt][1],     pah[0], pal[0]);
                bsplit2(sf[2 * jt][2],     sf[2 * jt][3],     pah[1], pal[1]);
                bsplit2(sf[2 * jt + 1][0], sf[2 * jt + 1][1], pah[2], pal[2]);
                bsplit2(sf[2 * jt + 1][2], sf[2 * jt + 1][3], pah[3], pal[3]);
#pragma unroll
                for (int ntp = 0; ntp < 4; ntp++) {
                    u32 h0, h1, h2, h3, l0r, l1r, l2r, l3r;
                    u32 off = ((ntp * 16 + bRow) * KSTR + jt * 8 + bK4) * 4;
                    ldsm4(h0, h1, h2, h3, vshb + off);
                    ldsm4(l0r, l1r, l2r, l3r, vslb + off);
                    bmma(of[2 * ntp],     pah, h0, h1);
                    bmma(of[2 * ntp],     pal, h0, h1);
                    bmma(of[2 * ntp],     pah, l0r, l1r);
                    bmma(of[2 * ntp + 1], pah, h2, h3);
                    bmma(of[2 * ntp + 1], pal, h2, h3);
                    bmma(of[2 * ntp + 1], pah, l2r, l3r);
                }
            }
        }
    }

    // epilogue: normalize + split-write (heads merged)
    float inv0 = 1.0f / l0, inv1 = 1.0f / l1;
    u32* oh = reinterpret_cast<u32*>(g_aoh);
    u32* ol = reinterpret_cast<u32*>(g_aol);
    size_t m0i = (size_t)(b * T_SEQ + R + g) * D_MODEL + h * 64;
    size_t m1i = m0i + (size_t)8 * D_MODEL;
#pragma unroll
    for (int nt = 0; nt < 8; nt++) {
        int col = nt * 8 + 2 * q;
        u32 h2, l2;
        bsplit2(of[nt][0] * inv0, of[nt][1] * inv0, h2, l2);
        oh[(m0i + col) >> 1] = h2; ol[(m0i + col) >> 1] = l2;
        bsplit2(of[nt][2] * inv1, of[nt][3] * inv1, h2, l2);
        oh[(m1i + col) >> 1] = h2; ol[(m1i + col) >> 1] = l2;
    }
}

// ---------------------------------------------------------------------------
extern "C" void kernel_launch(void* const* d_in, const int* in_sizes, int n_in,
                              void* d_out, int out_size)
{
    const float* q   = (const float*)d_in[0];
    const float* k   = (const float*)d_in[1];
    const float* v   = (const float*)d_in[2];
    const float* W_q = (const float*)d_in[4];
    const float* b_q = (const float*)d_in[5];
    const float* W_k = (const float*)d_in[6];
    const float* b_k = (const float*)d_in[7];
    const float* W_v = (const float*)d_in[8];
    const float* b_v = (const float*)d_in[9];
    const float* W_o = (const float*)d_in[10];
    const float* b_o = (const float*)d_in[11];
    float* out = (float*)d_out;

    const int attn_smem = ATTN_SMEM_W * 4;   // 73728
    cudaFuncSetAttribute(gemm_qkv, cudaFuncAttributeMaxDynamicSharedMemorySize, GEMM_SMEM);
    cudaFuncSetAttribute(gemm_o,   cudaFuncAttributeMaxDynamicSharedMemorySize, GEMM_SMEM);
    cudaFuncSetAttribute(attn_causal, cudaFuncAttributeMaxDynamicSharedMemorySize, attn_smem);

    dim3 sg(M_ROWS * D_MODEL / 4 / 256, 7);   // (8192, 7)
    split7_kernel<<<sg, 256>>>((const float4*)q, (const float4*)k, (const float4*)v,
                               (const float4*)W_q, (const float4*)W_k,
                               (const float4*)W_v, (const float4*)W_o);

    dim3 gg(D_MODEL / 128, M_ROWS / 128, 3);   // (8, 64, 3)
    gemm_qkv<<<gg, 256, GEMM_SMEM>>>(b_q, b_k, b_v);

    dim3 tg(T_SEQ / 32, B_SZ * N_HEADS);
    vtrans_kernel<<<tg, 256>>>();

    dim3 ag(T_SEQ / 128, B_SZ * N_HEADS);      // (16, 64)
    attn_causal<<<ag, 256, attn_smem>>>();

    dim3 go(D_MODEL / 128, M_ROWS / 128);
    gemm_o<<<go, 256, GEMM_SMEM>>>(b_o, out);
}

// round 12
// speedup vs baseline: 2.6682x; 1.2605x over previous
#include <cuda_runtime.h>
#include <cuda_bf16.h>
#include <cuda_fp16.h>
#include <math.h>
#include <stdint.h>

#define D_MODEL 1024
#define N_HEADS 16
#define B_SZ    4
#define T_SEQ   2048
#define M_ROWS  8192

typedef unsigned int u32;

// scratch (allocation-free rule: __device__ globals)
__device__ __nv_bfloat16 g_iqh[M_ROWS * D_MODEL], g_iql[M_ROWS * D_MODEL];
__device__ __nv_bfloat16 g_ikh[M_ROWS * D_MODEL], g_ikl[M_ROWS * D_MODEL];
__device__ __nv_bfloat16 g_ivh[M_ROWS * D_MODEL], g_ivl[M_ROWS * D_MODEL];
__device__ __nv_bfloat16 g_wqh[D_MODEL * D_MODEL], g_wql[D_MODEL * D_MODEL];
__device__ __nv_bfloat16 g_wkh[D_MODEL * D_MODEL], g_wkl[D_MODEL * D_MODEL];
__device__ __nv_bfloat16 g_wvh[D_MODEL * D_MODEL], g_wvl[D_MODEL * D_MODEL];
__device__ __nv_bfloat16 g_woh[D_MODEL * D_MODEL], g_wol[D_MODEL * D_MODEL];
__device__ __half        g_pq [M_ROWS * D_MODEL];              // fp16 Q proj
__device__ __half        g_pk [M_ROWS * D_MODEL];              // fp16 K proj
__device__ float         g_V  [M_ROWS * D_MODEL];
__device__ __half        g_vt [M_ROWS * D_MODEL];              // fp16 V^T [bh][64][2048]
__device__ __nv_bfloat16 g_aoh[M_ROWS * D_MODEL], g_aol[M_ROWS * D_MODEL];

// ---------------------------------------------------------------------------
__device__ __forceinline__ void bsplit2(float x0, float x1, u32& hi, u32& lo) {
    u32 h;
    asm("cvt.rn.bf16x2.f32 %0, %1, %2;" : "=r"(h) : "f"(x1), "f"(x0));
    float h0 = __uint_as_float(h << 16);
    float h1 = __uint_as_float(h & 0xffff0000u);
    u32 l;
    float r0 = x0 - h0, r1 = x1 - h1;
    asm("cvt.rn.bf16x2.f32 %0, %1, %2;" : "=r"(l) : "f"(r1), "f"(r0));
    hi = h; lo = l;
}

__device__ __forceinline__ u32 packf16(float x0, float x1) {
    u32 r;
    asm("cvt.rn.f16x2.f32 %0, %1, %2;" : "=r"(r) : "f"(x1), "f"(x0));
    return r;
}

// bf16 mma (projection GEMMs)
__device__ __forceinline__ void bmma(float d[4], const u32 a[4], u32 b0, u32 b1) {
    asm volatile(
        "mma.sync.aligned.m16n8k16.row.col.f32.bf16.bf16.f32 "
        "{%0,%1,%2,%3}, {%4,%5,%6,%7}, {%8,%9}, {%0,%1,%2,%3};\n"
        : "+f"(d[0]), "+f"(d[1]), "+f"(d[2]), "+f"(d[3])
        : "r"(a[0]), "r"(a[1]), "r"(a[2]), "r"(a[3]), "r"(b0), "r"(b1));
}
// fp16 mma (attention)
__device__ __forceinline__ void fmma(float d[4], const u32 a[4], u32 b0, u32 b1) {
    asm volatile(
        "mma.sync.aligned.m16n8k16.row.col.f32.f16.f16.f32 "
        "{%0,%1,%2,%3}, {%4,%5,%6,%7}, {%8,%9}, {%0,%1,%2,%3};\n"
        : "+f"(d[0]), "+f"(d[1]), "+f"(d[2]), "+f"(d[3])
        : "r"(a[0]), "r"(a[1]), "r"(a[2]), "r"(a[3]), "r"(b0), "r"(b1));
}

__device__ __forceinline__ void ldsm4(u32& r0, u32& r1, u32& r2, u32& r3, u32 addr) {
    asm volatile("ldmatrix.sync.aligned.m8n8.x4.shared.b16 {%0,%1,%2,%3}, [%4];"
                 : "=r"(r0), "=r"(r1), "=r"(r2), "=r"(r3) : "r"(addr));
}

__device__ __forceinline__ void cpa16(void* smem_ptr, const void* gptr) {
    u32 s = (u32)__cvta_generic_to_shared(smem_ptr);
    asm volatile("cp.async.cg.shared.global [%0], [%1], 16;\n" :: "r"(s), "l"(gptr));
}
__device__ __forceinline__ void cpa_commit() { asm volatile("cp.async.commit_group;\n"); }
template <int N>
__device__ __forceinline__ void cpa_wait() { asm volatile("cp.async.wait_group %0;\n" :: "n"(N)); }

__device__ __forceinline__ u32 smem_u32(const void* p) {
    return (u32)__cvta_generic_to_shared(p);
}

// ---------------------------------------------------------------------------
// fused split: grid (8192, 7)
__global__ void __launch_bounds__(256) split7_kernel(
    const float4* __restrict__ q, const float4* __restrict__ k,
    const float4* __restrict__ v,
    const float4* __restrict__ wq, const float4* __restrict__ wk,
    const float4* __restrict__ wv, const float4* __restrict__ wo)
{
    const int seg = blockIdx.y;
    const int i = blockIdx.x * 256 + threadIdx.x;
    const float4* src; u32* dh; u32* dl; int n4;
    const int NI = M_ROWS * D_MODEL / 4, NW = D_MODEL * D_MODEL / 4;
    switch (seg) {
        case 0: src = q;  dh = (u32*)g_iqh; dl = (u32*)g_iql; n4 = NI; break;
        case 1: src = k;  dh = (u32*)g_ikh; dl = (u32*)g_ikl; n4 = NI; break;
        case 2: src = v;  dh = (u32*)g_ivh; dl = (u32*)g_ivl; n4 = NI; break;
        case 3: src = wq; dh = (u32*)g_wqh; dl = (u32*)g_wql; n4 = NW; break;
        case 4: src = wk; dh = (u32*)g_wkh; dl = (u32*)g_wkl; n4 = NW; break;
        case 5: src = wv; dh = (u32*)g_wvh; dl = (u32*)g_wvl; n4 = NW; break;
        default: src = wo; dh = (u32*)g_woh; dl = (u32*)g_wol; n4 = NW; break;
    }
    if (i >= n4) return;
    float4 val = src[i];
    u32 h0, l0, h1, l1;
    bsplit2(val.x, val.y, h0, l0);
    bsplit2(val.z, val.w, h1, l1);
    dh[2 * i] = h0; dh[2 * i + 1] = h1;
    dl[2 * i] = l0; dl[2 * i + 1] = l1;
}

// transpose V per head to fp16: g_V[b][t][h*64+d] -> g_vt[bh][d][t]
__global__ void __launch_bounds__(256) vtrans_kernel()
{
    __shared__ float ts[32][65];
    const int j0 = blockIdx.x * 32;
    const int bh = blockIdx.y;
    const int b = bh >> 4, h = bh & 15;
    const int tid = threadIdx.x;
#pragma unroll
    for (int i = 0; i < 8; i++) {
        int idx = tid + i * 256;
        int r = idx >> 6, c = idx & 63;
        ts[r][c] = g_V[(size_t)(b * T_SEQ + j0 + r) * D_MODEL + h * 64 + c];
    }
    __syncthreads();
    u32* ov = reinterpret_cast<u32*>(g_vt);
#pragma unroll
    for (int i = 0; i < 4; i++) {
        int idx = tid + i * 256;
        int d = idx >> 4, jj = (idx & 15) * 2;
        size_t o = ((size_t)(bh * 64 + d) * T_SEQ + j0 + jj) >> 1;
        ov[o] = packf16(ts[jj][d], ts[jj + 1][d]);
    }
}

// ---------------------------------------------------------------------------
// GEMM body: 3xBF16, ldmatrix, 2-stage pipeline, 2 CTAs/SM.
// outmode: 0 = float, 1 = bf16 hi/lo split, 2 = fp16 packed
// ---------------------------------------------------------------------------
#define GKW 20
#define GT  (128 * GKW)
#define GEMM_SMEM (2 * 4 * GT * 4)   // 81920 B

__device__ __forceinline__ void gemm_body(
    char* smb,
    const __nv_bfloat16* __restrict__ Ah, const __nv_bfloat16* __restrict__ Al,
    const __nv_bfloat16* __restrict__ Bh, const __nv_bfloat16* __restrict__ Bl,
    const float* __restrict__ bias,
    float* __restrict__ Cf, u32* __restrict__ Ch, u32* __restrict__ Cl,
    int outmode)
{
    const u32 sb = smem_u32(smb);
    const int tid  = threadIdx.x;
    const int lane = tid & 31;
    const int wid  = tid >> 5;
    const int g    = lane >> 2;
    const int q    = lane & 3;
    const int wm   = wid >> 2;
    const int wn   = wid & 3;
    const int bm   = blockIdx.y * 128;
    const int bn   = blockIdx.x * 128;
    const int K = D_MODEL, N = D_MODEL;

    float acc[4][4][4] = {};

    u32* smw = reinterpret_cast<u32*>(smb);
    auto issue = [&](int t, int buf) {
        const int k0 = t * 32;
        u32* base = smw + buf * 4 * GT;
#pragma unroll
        for (int i = 0; i < 8; i++) {
            int idx = tid + i * 256;
            int arr = idx >> 9;
            int w   = idx & 511;
            int row = w >> 2, c = w & 3;
            const __nv_bfloat16* gp;
            int rb;
            if      (arr == 0) { gp = Ah; rb = bm; }
            else if (arr == 1) { gp = Al; rb = bm; }
            else if (arr == 2) { gp = Bh; rb = bn; }
            else               { gp = Bl; rb = bn; }
            cpa16(base + arr * GT + row * GKW + c * 4,
                  gp + (size_t)(rb + row) * K + k0 + c * 8);
        }
    };

    const int NT = K / 32;   // 32
    issue(0, 0); cpa_commit();
    issue(1, 1); cpa_commit();

    const int aRow = (lane & 7) + ((lane >> 3) & 1) * 8;
    const int aK4  = ((lane >> 4) & 1) * 4;
    const int bRow = (lane & 7) + ((lane >> 4) & 1) * 8;
    const int bK4  = ((lane >> 3) & 1) * 4;

    for (int s = 0; s < NT; s++) {
        const int buf = s & 1;
        if (s + 1 < NT) cpa_wait<1>(); else cpa_wait<0>();
        __syncthreads();

        const u32 abh = sb + (u32)(buf * 4 * GT) * 4;
        const u32 abl = abh + GT * 4;
        const u32 bbh = abh + 2 * GT * 4;
        const u32 bbl = abh + 3 * GT * 4;

#pragma unroll
        for (int ks = 0; ks < 2; ks++) {
            u32 ah[4][4], al[4][4];
#pragma unroll
            for (int mt = 0; mt < 4; mt++) {
                u32 off = ((wm * 64 + mt * 16 + aRow) * GKW + ks * 8 + aK4) * 4;
                ldsm4(ah[mt][0], ah[mt][1], ah[mt][2], ah[mt][3], abh + off);
                ldsm4(al[mt][0], al[mt][1], al[mt][2], al[mt][3], abl + off);
            }
#pragma unroll
            for (int ntp = 0; ntp < 2; ntp++) {
                u32 bh0, bh1, bh2, bh3, bl0, bl1, bl2, bl3;
                u32 off = ((wn * 32 + ntp * 16 + bRow) * GKW + ks * 8 + bK4) * 4;
                ldsm4(bh0, bh1, bh2, bh3, bbh + off);
                ldsm4(bl0, bl1, bl2, bl3, bbl + off);
#pragma unroll
                for (int mt = 0; mt < 4; mt++) {
                    bmma(acc[mt][2 * ntp],     ah[mt], bh0, bh1);
                    bmma(acc[mt][2 * ntp],     al[mt], bh0, bh1);
                    bmma(acc[mt][2 * ntp],     ah[mt], bl0, bl1);
                    bmma(acc[mt][2 * ntp + 1], ah[mt], bh2, bh3);
                    bmma(acc[mt][2 * ntp + 1], al[mt], bh2, bh3);
                    bmma(acc[mt][2 * ntp + 1], ah[mt], bl2, bl3);
                }
            }
        }

        __syncthreads();
        if (s + 2 < NT) { issue(s + 2, buf); cpa_commit(); }
    }

#pragma unroll
    for (int mt = 0; mt < 4; mt++) {
        int row0 = bm + wm * 64 + mt * 16 + g;
#pragma unroll
        for (int nt = 0; nt < 4; nt++) {
            int col = bn + wn * 32 + nt * 8 + 2 * q;
            float b0 = bias[col], b1 = bias[col + 1];
            float v00 = acc[mt][nt][0] + b0, v01 = acc[mt][nt][1] + b1;
            float v10 = acc[mt][nt][2] + b0, v11 = acc[mt][nt][3] + b1;
            size_t o0 = ((size_t)row0 * N + col) >> 1;
            size_t o1 = ((size_t)(row0 + 8) * N + col) >> 1;
            if (outmode == 1) {
                u32 h2, l2;
                bsplit2(v00, v01, h2, l2); Ch[o0] = h2; Cl[o0] = l2;
                bsplit2(v10, v11, h2, l2); Ch[o1] = h2; Cl[o1] = l2;
            } else if (outmode == 2) {
                Ch[o0] = packf16(v00, v01);
                Ch[o1] = packf16(v10, v11);
            } else {
                *(float2*)&Cf[(size_t)row0 * N + col]       = make_float2(v00, v01);
                *(float2*)&Cf[(size_t)(row0 + 8) * N + col] = make_float2(v10, v11);
            }
        }
    }
}

__global__ void __launch_bounds__(256, 2) gemm_qkv(
    const float* __restrict__ b_q, const float* __restrict__ b_k,
    const float* __restrict__ b_v)
{
    extern __shared__ char smb[];
    const int z = blockIdx.z;
    if (z == 0)
        gemm_body(smb, g_iqh, g_iql, g_wqh, g_wql, b_q,
                  nullptr, (u32*)g_pq, nullptr, 2);
    else if (z == 1)
        gemm_body(smb, g_ikh, g_ikl, g_wkh, g_wkl, b_k,
                  nullptr, (u32*)g_pk, nullptr, 2);
    else
        gemm_body(smb, g_ivh, g_ivl, g_wvh, g_wvl, b_v,
                  g_V, nullptr, nullptr, 0);
}

__global__ void __launch_bounds__(256, 2) gemm_o(
    const float* __restrict__ b_o, float* __restrict__ out)
{
    extern __shared__ char smb[];
    gemm_body(smb, g_aoh, g_aol, g_woh, g_wol, b_o, out, nullptr, nullptr, 0);
}

// ---------------------------------------------------------------------------
// Causal flash attention, single-term FP16, 64-wide kv tiles, 2 CTAs/SM.
// Grid (T/128, B*H), 256 thr = 8 warps x 16 q-rows.
// ---------------------------------------------------------------------------
#define KSTR 36
#define ATW  (64 * KSTR)                   // 2304 words per tile
#define KH_OFF(b) ((b) * ATW)
#define VH_OFF(b) (2 * ATW + (b) * ATW)
#define ATTN_SMEM_W (4 * ATW)              // 9216 words = 36864 B

__global__ void __launch_bounds__(256, 2) attn_causal()
{
    extern __shared__ u32 smw[];
    const u32 sb = smem_u32(smw);

    const int qb = gridDim.x - 1 - blockIdx.x;   // heavy blocks first
    const int bh = blockIdx.y;
    const int b  = bh >> 4;
    const int h  = bh & 15;

    const int tid  = threadIdx.x;
    const int lane = tid & 31;
    const int wq   = tid >> 5;
    const int g    = lane >> 2;
    const int q    = lane & 3;

    const float scale = 0.125f;
    const u32* kg = reinterpret_cast<const u32*>(g_pk);
    const u32* vg = reinterpret_cast<const u32*>(g_vt);

    const int aRow = (lane & 7) + ((lane >> 3) & 1) * 8;
    const int aK4  = ((lane >> 4) & 1) * 4;
    const int bRow = (lane & 7) + ((lane >> 4) & 1) * 8;
    const int bK4  = ((lane >> 3) & 1) * 4;

    // ---- stage Q (128 rows x 32 words; overlaps K region) ----
    {
        const u32* qg = reinterpret_cast<const u32*>(g_pq);
#pragma unroll
        for (int i = 0; i < 4; i++) {
            int idx = tid + i * 256;         // 1024 chunks
            int row = idx >> 3, c = idx & 7;
            cpa16(smw + row * KSTR + c * 4,
                  qg + (((size_t)(b * T_SEQ + qb * 128 + row) * D_MODEL + h * 64) >> 1) + c * 4);
        }
        cpa_commit();
        cpa_wait<0>();
        __syncthreads();
    }
    u32 qf[4][4];
#pragma unroll
    for (int kt = 0; kt < 4; kt++) {
        u32 off = ((wq * 16 + aRow) * KSTR + kt * 8 + aK4) * 4;
        ldsm4(qf[kt][0], qf[kt][1], qf[kt][2], qf[kt][3], sb + off);
    }
    __syncthreads();   // Q region reused by K staging

    auto stage_kv = [&](int kb, int buf) {
        // K: 64 rows x 32 words = 512 chunks
#pragma unroll
        for (int i = 0; i < 2; i++) {
            int idx = tid + i * 256;
            int row = idx >> 3, c = idx & 7;
            cpa16(smw + KH_OFF(buf) + row * KSTR + c * 4,
                  kg + (((size_t)(b * T_SEQ + kb * 64 + row) * D_MODEL + h * 64) >> 1) + c * 4);
        }
        // Vt: 64 d-rows x 32 words (64 t) = 512 chunks
#pragma unroll
        for (int i = 0; i < 2; i++) {
            int idx = tid + i * 256;
            int row = idx >> 3, c = idx & 7;
            cpa16(smw + VH_OFF(buf) + row * KSTR + c * 4,
                  vg + (((size_t)(bh * 64 + row) * T_SEQ) >> 1) + kb * 32 + c * 4);
        }
    };

    stage_kv(0, 0);
    cpa_commit();

    float of[8][4] = {};
    float m0 = -INFINITY, m1 = -INFINITY, l0 = 0.f, l1 = 0.f;
    const int R = qb * 128 + wq * 16;
    const int kbmax = 2 * qb + 1;

    for (int kb = 0; kb <= kbmax; kb++) {
        cpa_wait<0>();
        __syncthreads();
        if (kb + 1 <= kbmax) { stage_kv(kb + 1, (kb + 1) & 1); cpa_commit(); }

        const bool active = (kb * 64 <= R + 15);
        if (active) {
            const u32 kshb = sb + (u32)KH_OFF(kb & 1) * 4;
            const u32 vshb = sb + (u32)VH_OFF(kb & 1) * 4;

            // S = Q K^T  (16 x 64 per warp), single-term fp16
            float sf[8][4] = {};
#pragma unroll
            for (int kt = 0; kt < 4; kt++) {
#pragma unroll
                for (int ntp = 0; ntp < 4; ntp++) {
                    u32 h0, h1, h2, h3;
                    u32 off = ((ntp * 16 + bRow) * KSTR + kt * 8 + bK4) * 4;
                    ldsm4(h0, h1, h2, h3, kshb + off);
                    fmma(sf[2 * ntp],     qf[kt], h0, h1);
                    fmma(sf[2 * ntp + 1], qf[kt], h2, h3);
                }
            }

            // mask (boundary tiles only) + scale
            if (kb * 64 + 63 > R) {
                int r0 = R + g, r1 = r0 + 8;
#pragma unroll
                for (int nt = 0; nt < 8; nt++) {
                    int c0 = kb * 64 + nt * 8 + 2 * q, c1 = c0 + 1;
                    if (c0 > r0) sf[nt][0] = -INFINITY;
                    if (c1 > r0) sf[nt][1] = -INFINITY;
                    if (c0 > r1) sf[nt][2] = -INFINITY;
                    if (c1 > r1) sf[nt][3] = -INFINITY;
                }
            }
#pragma unroll
            for (int nt = 0; nt < 8; nt++) {
                sf[nt][0] *= scale; sf[nt][1] *= scale;
                sf[nt][2] *= scale; sf[nt][3] *= scale;
            }

            // online softmax
            float mx0 = -INFINITY, mx1 = -INFINITY;
#pragma unroll
            for (int nt = 0; nt < 8; nt++) {
                mx0 = fmaxf(mx0, fmaxf(sf[nt][0], sf[nt][1]));
                mx1 = fmaxf(mx1, fmaxf(sf[nt][2], sf[nt][3]));
            }
            mx0 = fmaxf(mx0, __shfl_xor_sync(0xffffffffu, mx0, 1));
            mx0 = fmaxf(mx0, __shfl_xor_sync(0xffffffffu, mx0, 2));
            mx1 = fmaxf(mx1, __shfl_xor_sync(0xffffffffu, mx1, 1));
            mx1 = fmaxf(mx1, __shfl_xor_sync(0xffffffffu, mx1, 2));

            float mn0 = fmaxf(m0, mx0), mn1 = fmaxf(m1, mx1);
            float c0 = __expf(m0 - mn0), c1 = __expf(m1 - mn1);
            m0 = mn0; m1 = mn1;

            float ls0 = 0.f, ls1 = 0.f;
#pragma unroll
            for (int nt = 0; nt < 8; nt++) {
                sf[nt][0] = __expf(sf[nt][0] - mn0);
                sf[nt][1] = __expf(sf[nt][1] - mn0);
                sf[nt][2] = __expf(sf[nt][2] - mn1);
                sf[nt][3] = __expf(sf[nt][3] - mn1);
                ls0 += sf[nt][0] + sf[nt][1];
                ls1 += sf[nt][2] + sf[nt][3];
            }
#pragma unroll
            for (int nt = 0; nt < 8; nt++) {
                of[nt][0] *= c0; of[nt][1] *= c0;
                of[nt][2] *= c1; of[nt][3] *= c1;
            }
            ls0 += __shfl_xor_sync(0xffffffffu, ls0, 1);
            ls0 += __shfl_xor_sync(0xffffffffu, ls0, 2);
            ls1 += __shfl_xor_sync(0xffffffffu, ls1, 1);
            ls1 += __shfl_xor_sync(0xffffffffu, ls1, 2);
            l0 = l0 * c0 + ls0;
            l1 = l1 * c1 + ls1;

            // O += P V (P packed fp16 in registers)
#pragma unroll
            for (int jt = 0; jt < 4; jt++) {
                u32 pa[4];
                pa[0] = packf16(sf[2 * jt][0],     sf[2 * jt][1]);
                pa[1] = packf16(sf[2 * jt][2],     sf[2 * jt][3]);
                pa[2] = packf16(sf[2 * jt + 1][0], sf[2 * jt + 1][1]);
                pa[3] = packf16(sf[2 * jt + 1][2], sf[2 * jt + 1][3]);
#pragma unroll
                for (int ntp = 0; ntp < 4; ntp++) {
                    u32 h0, h1, h2, h3;
                    u32 off = ((ntp * 16 + bRow) * KSTR + jt * 8 + bK4) * 4;
                    ldsm4(h0, h1, h2, h3, vshb + off);
                    fmma(of[2 * ntp],     pa, h0, h1);
                    fmma(of[2 * ntp + 1], pa, h2, h3);
                }
            }
        }
    }

    // epilogue: normalize + bf16 hi/lo split write (input to 3xBF16 O-proj)
    float inv0 = 1.0f / l0, inv1 = 1.0f / l1;
    u32* oh = reinterpret_cast<u32*>(g_aoh);
    u32* ol = reinterpret_cast<u32*>(g_aol);
    size_t m0i = (size_t)(b * T_SEQ + R + g) * D_MODEL + h * 64;
    size_t m1i = m0i + (size_t)8 * D_MODEL;
#pragma unroll
    for (int nt = 0; nt < 8; nt++) {
        int col = nt * 8 + 2 * q;
        u32 h2, l2;
        bsplit2(of[nt][0] * inv0, of[nt][1] * inv0, h2, l2);
        oh[(m0i + col) >> 1] = h2; ol[(m0i + col) >> 1] = l2;
        bsplit2(of[nt][2] * inv1, of[nt][3] * inv1, h2, l2);
        oh[(m1i + col) >> 1] = h2; ol[(m1i + col) >> 1] = l2;
    }
}

// ---------------------------------------------------------------------------
extern "C" void kernel_launch(void* const* d_in, const int* in_sizes, int n_in,
                              void* d_out, int out_size)
{
    const float* q   = (const float*)d_in[0];
    const float* k   = (const float*)d_in[1];
    const float* v   = (const float*)d_in[2];
    const float* W_q = (const float*)d_in[4];
    const float* b_q = (const float*)d_in[5];
    const float* W_k = (const float*)d_in[6];
    const float* b_k = (const float*)d_in[7];
    const float* W_v = (const float*)d_in[8];
    const float* b_v = (const float*)d_in[9];
    const float* W_o = (const float*)d_in[10];
    const float* b_o = (const float*)d_in[11];
    float* out = (float*)d_out;

    const int attn_smem = ATTN_SMEM_W * 4;   // 36864
    cudaFuncSetAttribute(gemm_qkv, cudaFuncAttributeMaxDynamicSharedMemorySize, GEMM_SMEM);
    cudaFuncSetAttribute(gemm_o,   cudaFuncAttributeMaxDynamicSharedMemorySize, GEMM_SMEM);
    cudaFuncSetAttribute(attn_causal, cudaFuncAttributeMaxDynamicSharedMemorySize, attn_smem);

    dim3 sg(M_ROWS * D_MODEL / 4 / 256, 7);   // (8192, 7)
    split7_kernel<<<sg, 256>>>((const float4*)q, (const float4*)k, (const float4*)v,
                               (const float4*)W_q, (const float4*)W_k,
                               (const float4*)W_v, (const float4*)W_o);

    dim3 gg(D_MODEL / 128, M_ROWS / 128, 3);   // (8, 64, 3)
    gemm_qkv<<<gg, 256, GEMM_SMEM>>>(b_q, b_k, b_v);

    dim3 tg(T_SEQ / 32, B_SZ * N_HEADS);
    vtrans_kernel<<<tg, 256>>>();

    dim3 ag(T_SEQ / 128, B_SZ * N_HEADS);      // (16, 64)
    attn_causal<<<ag, 256, attn_smem>>>();

    dim3 go(D_MODEL / 128, M_ROWS / 128);
    gemm_o<<<go, 256, GEMM_SMEM>>>(b_o, out);
}

// round 13
// speedup vs baseline: 3.4682x; 1.2998x over previous
#include <cuda_runtime.h>
#include <cuda_bf16.h>
#include <cuda_fp16.h>
#include <math.h>
#include <stdint.h>

#define D_MODEL 1024
#define N_HEADS 16
#define B_SZ    4
#define T_SEQ   2048
#define M_ROWS  8192

typedef unsigned int u32;

// scratch (allocation-free rule: __device__ globals)
__device__ __half g_iq [M_ROWS * D_MODEL];                     // fp16 inputs
__device__ __half g_ik [M_ROWS * D_MODEL];
__device__ __half g_iv [M_ROWS * D_MODEL];
__device__ __half g_wqh[D_MODEL * D_MODEL], g_wql[D_MODEL * D_MODEL];  // fp16 hi/lo weights
__device__ __half g_wkh[D_MODEL * D_MODEL], g_wkl[D_MODEL * D_MODEL];
__device__ __half g_wvh[D_MODEL * D_MODEL], g_wvl[D_MODEL * D_MODEL];
__device__ __half g_woh[D_MODEL * D_MODEL], g_wol[D_MODEL * D_MODEL];
__device__ __half g_pq [M_ROWS * D_MODEL];                     // fp16 Q proj
__device__ __half g_pk [M_ROWS * D_MODEL];                     // fp16 K proj
__device__ float  g_V  [M_ROWS * D_MODEL];
__device__ __half g_vt [M_ROWS * D_MODEL];                     // fp16 V^T [bh][64][2048]
__device__ __half g_ao [M_ROWS * D_MODEL];                     // fp16 attention out

// ---------------------------------------------------------------------------
__device__ __forceinline__ u32 packf16(float x0, float x1) {
    u32 r;
    asm("cvt.rn.f16x2.f32 %0, %1, %2;" : "=r"(r) : "f"(x1), "f"(x0));
    return r;
}

// fp16 hi/lo split of (x0,x1) packed
__device__ __forceinline__ void fsplit2(float x0, float x1, u32& hi, u32& lo) {
    __half h0 = __float2half_rn(x0), h1 = __float2half_rn(x1);
    hi = (u32)__half_as_ushort(h0) | ((u32)__half_as_ushort(h1) << 16);
    float r0 = x0 - __half2float(h0), r1 = x1 - __half2float(h1);
    lo = packf16(r0, r1);
}

// fp16 mma
__device__ __forceinline__ void fmma(float d[4], const u32 a[4], u32 b0, u32 b1) {
    asm volatile(
        "mma.sync.aligned.m16n8k16.row.col.f32.f16.f16.f32 "
        "{%0,%1,%2,%3}, {%4,%5,%6,%7}, {%8,%9}, {%0,%1,%2,%3};\n"
        : "+f"(d[0]), "+f"(d[1]), "+f"(d[2]), "+f"(d[3])
        : "r"(a[0]), "r"(a[1]), "r"(a[2]), "r"(a[3]), "r"(b0), "r"(b1));
}

__device__ __forceinline__ void ldsm4(u32& r0, u32& r1, u32& r2, u32& r3, u32 addr) {
    asm volatile("ldmatrix.sync.aligned.m8n8.x4.shared.b16 {%0,%1,%2,%3}, [%4];"
                 : "=r"(r0), "=r"(r1), "=r"(r2), "=r"(r3) : "r"(addr));
}

__device__ __forceinline__ void cpa16(void* smem_ptr, const void* gptr) {
    u32 s = (u32)__cvta_generic_to_shared(smem_ptr);
    asm volatile("cp.async.cg.shared.global [%0], [%1], 16;\n" :: "r"(s), "l"(gptr));
}
__device__ __forceinline__ void cpa_commit() { asm volatile("cp.async.commit_group;\n"); }
template <int N>
__device__ __forceinline__ void cpa_wait() { asm volatile("cp.async.wait_group %0;\n" :: "n"(N)); }

__device__ __forceinline__ u32 smem_u32(const void* p) {
    return (u32)__cvta_generic_to_shared(p);
}

// ---------------------------------------------------------------------------
// fused prep: grid (8192, 7). seg 0-2: inputs -> single fp16.
// seg 3-6: weights -> fp16 hi/lo.
__global__ void __launch_bounds__(256) split7_kernel(
    const float4* __restrict__ q, const float4* __restrict__ k,
    const float4* __restrict__ v,
    const float4* __restrict__ wq, const float4* __restrict__ wk,
    const float4* __restrict__ wv, const float4* __restrict__ wo)
{
    const int seg = blockIdx.y;
    const int i = blockIdx.x * 256 + threadIdx.x;
    const int NI = M_ROWS * D_MODEL / 4, NW = D_MODEL * D_MODEL / 4;

    if (seg < 3) {
        if (i >= NI) return;
        const float4* src = (seg == 0) ? q : (seg == 1) ? k : v;
        u32* d = (seg == 0) ? (u32*)g_iq : (seg == 1) ? (u32*)g_ik : (u32*)g_iv;
        float4 val = src[i];
        d[2 * i]     = packf16(val.x, val.y);
        d[2 * i + 1] = packf16(val.z, val.w);
    } else {
        if (i >= NW) return;
        const float4* src; u32* dh; u32* dl;
        switch (seg) {
            case 3:  src = wq; dh = (u32*)g_wqh; dl = (u32*)g_wql; break;
            case 4:  src = wk; dh = (u32*)g_wkh; dl = (u32*)g_wkl; break;
            case 5:  src = wv; dh = (u32*)g_wvh; dl = (u32*)g_wvl; break;
            default: src = wo; dh = (u32*)g_woh; dl = (u32*)g_wol; break;
        }
        float4 val = src[i];
        u32 h0, l0, h1, l1;
        fsplit2(val.x, val.y, h0, l0);
        fsplit2(val.z, val.w, h1, l1);
        dh[2 * i] = h0; dh[2 * i + 1] = h1;
        dl[2 * i] = l0; dl[2 * i + 1] = l1;
    }
}

// transpose V per head to fp16: g_V[b][t][h*64+d] -> g_vt[bh][d][t]
__global__ void __launch_bounds__(256) vtrans_kernel()
{
    __shared__ float ts[32][65];
    const int j0 = blockIdx.x * 32;
    const int bh = blockIdx.y;
    const int b = bh >> 4, h = bh & 15;
    const int tid = threadIdx.x;
#pragma unroll
    for (int i = 0; i < 8; i++) {
        int idx = tid + i * 256;
        int r = idx >> 6, c = idx & 63;
        ts[r][c] = g_V[(size_t)(b * T_SEQ + j0 + r) * D_MODEL + h * 64 + c];
    }
    __syncthreads();
    u32* ov = reinterpret_cast<u32*>(g_vt);
#pragma unroll
    for (int i = 0; i < 4; i++) {
        int idx = tid + i * 256;
        int d = idx >> 4, jj = (idx & 15) * 2;
        size_t o = ((size_t)(bh * 64 + d) * T_SEQ + j0 + jj) >> 1;
        ov[o] = packf16(ts[jj][d], ts[jj + 1][d]);
    }
}

// ---------------------------------------------------------------------------
// GEMM body: 2-term FP16 (A single, W hi/lo), ldmatrix, 2-stage, 2 CTAs/SM.
// outmode: 0 = float, 2 = fp16 packed
// ---------------------------------------------------------------------------
#define GKW 20
#define GT  (128 * GKW)
#define GEMM_SMEM (2 * 3 * GT * 4)   // 61440 B

__device__ __forceinline__ void gemm_body(
    char* smb,
    const __half* __restrict__ A,
    const __half* __restrict__ Bh, const __half* __restrict__ Bl,
    const float* __restrict__ bias,
    float* __restrict__ Cf, u32* __restrict__ Ch, int outmode)
{
    const u32 sb = smem_u32(smb);
    const int tid  = threadIdx.x;
    const int lane = tid & 31;
    const int wid  = tid >> 5;
    const int g    = lane >> 2;
    const int q    = lane & 3;
    const int wm   = wid >> 2;
    const int wn   = wid & 3;
    const int bm   = blockIdx.y * 128;
    const int bn   = blockIdx.x * 128;
    const int K = D_MODEL, N = D_MODEL;

    float acc[4][4][4] = {};

    u32* smw = reinterpret_cast<u32*>(smb);
    auto issue = [&](int t, int buf) {
        const int k0 = t * 32;
        u32* base = smw + buf * 3 * GT;
#pragma unroll
        for (int i = 0; i < 6; i++) {
            int idx = tid + i * 256;       // 1536 chunks of 16B
            int arr = idx >> 9;            // 0:A 1:Bh 2:Bl
            int w   = idx & 511;
            int row = w >> 2, c = w & 3;
            const __half* gp;
            int rb;
            if      (arr == 0) { gp = A;  rb = bm; }
            else if (arr == 1) { gp = Bh; rb = bn; }
            else               { gp = Bl; rb = bn; }
            cpa16(base + arr * GT + row * GKW + c * 4,
                  gp + (size_t)(rb + row) * K + k0 + c * 8);
        }
    };

    const int NT = K / 32;   // 32
    issue(0, 0); cpa_commit();
    issue(1, 1); cpa_commit();

    const int aRow = (lane & 7) + ((lane >> 3) & 1) * 8;
    const int aK4  = ((lane >> 4) & 1) * 4;
    const int bRow = (lane & 7) + ((lane >> 4) & 1) * 8;
    const int bK4  = ((lane >> 3) & 1) * 4;

    for (int s = 0; s < NT; s++) {
        const int buf = s & 1;
        if (s + 1 < NT) cpa_wait<1>(); else cpa_wait<0>();
        __syncthreads();

        const u32 ab  = sb + (u32)(buf * 3 * GT) * 4;
        const u32 bbh = ab + GT * 4;
        const u32 bbl = ab + 2 * GT * 4;

#pragma unroll
        for (int ks = 0; ks < 2; ks++) {
            u32 af[4][4];
#pragma unroll
            for (int mt = 0; mt < 4; mt++) {
                u32 off = ((wm * 64 + mt * 16 + aRow) * GKW + ks * 8 + aK4) * 4;
                ldsm4(af[mt][0], af[mt][1], af[mt][2], af[mt][3], ab + off);
            }
#pragma unroll
            for (int ntp = 0; ntp < 2; ntp++) {
                u32 bh0, bh1, bh2, bh3, bl0, bl1, bl2, bl3;
                u32 off = ((wn * 32 + ntp * 16 + bRow) * GKW + ks * 8 + bK4) * 4;
                ldsm4(bh0, bh1, bh2, bh3, bbh + off);
                ldsm4(bl0, bl1, bl2, bl3, bbl + off);
#pragma unroll
                for (int mt = 0; mt < 4; mt++) {
                    fmma(acc[mt][2 * ntp],     af[mt], bh0, bh1);
                    fmma(acc[mt][2 * ntp],     af[mt], bl0, bl1);
                    fmma(acc[mt][2 * ntp + 1], af[mt], bh2, bh3);
                    fmma(acc[mt][2 * ntp + 1], af[mt], bl2, bl3);
                }
            }
        }

        __syncthreads();
        if (s + 2 < NT) { issue(s + 2, buf); cpa_commit(); }
    }

#pragma unroll
    for (int mt = 0; mt < 4; mt++) {
        int row0 = bm + wm * 64 + mt * 16 + g;
#pragma unroll
        for (int nt = 0; nt < 4; nt++) {
            int col = bn + wn * 32 + nt * 8 + 2 * q;
            float b0 = bias[col], b1 = bias[col + 1];
            float v00 = acc[mt][nt][0] + b0, v01 = acc[mt][nt][1] + b1;
            float v10 = acc[mt][nt][2] + b0, v11 = acc[mt][nt][3] + b1;
            if (outmode == 2) {
                size_t o0 = ((size_t)row0 * N + col) >> 1;
                size_t o1 = ((size_t)(row0 + 8) * N + col) >> 1;
                Ch[o0] = packf16(v00, v01);
                Ch[o1] = packf16(v10, v11);
            } else {
                *(float2*)&Cf[(size_t)row0 * N + col]       = make_float2(v00, v01);
                *(float2*)&Cf[(size_t)(row0 + 8) * N + col] = make_float2(v10, v11);
            }
        }
    }
}

__global__ void __launch_bounds__(256, 2) gemm_qkv(
    const float* __restrict__ b_q, const float* __restrict__ b_k,
    const float* __restrict__ b_v)
{
    extern __shared__ char smb[];
    const int z = blockIdx.z;
    if (z == 0)
        gemm_body(smb, g_iq, g_wqh, g_wql, b_q, nullptr, (u32*)g_pq, 2);
    else if (z == 1)
        gemm_body(smb, g_ik, g_wkh, g_wkl, b_k, nullptr, (u32*)g_pk, 2);
    else
        gemm_body(smb, g_iv, g_wvh, g_wvl, b_v, g_V, nullptr, 0);
}

__global__ void __launch_bounds__(256, 2) gemm_o(
    const float* __restrict__ b_o, float* __restrict__ out)
{
    extern __shared__ char smb[];
    gemm_body(smb, g_ao, g_woh, g_wol, b_o, out, nullptr, 0);
}

// ---------------------------------------------------------------------------
// Causal flash attention, single-term FP16, 64-wide kv tiles, 2 CTAs/SM.
// Grid (T/128, B*H), 256 thr = 8 warps x 16 q-rows.
// ---------------------------------------------------------------------------
#define KSTR 36
#define ATW  (64 * KSTR)                   // 2304 words per tile
#define KH_OFF(b) ((b) * ATW)
#define VH_OFF(b) (2 * ATW + (b) * ATW)
#define ATTN_SMEM_W (4 * ATW)              // 9216 words = 36864 B

__global__ void __launch_bounds__(256, 2) attn_causal()
{
    extern __shared__ u32 smw[];
    const u32 sb = smem_u32(smw);

    const int qb = gridDim.x - 1 - blockIdx.x;   // heavy blocks first
    const int bh = blockIdx.y;
    const int b  = bh >> 4;
    const int h  = bh & 15;

    const int tid  = threadIdx.x;
    const int lane = tid & 31;
    const int wq   = tid >> 5;
    const int g    = lane >> 2;
    const int q    = lane & 3;

    const float scale = 0.125f;
    const u32* kg = reinterpret_cast<const u32*>(g_pk);
    const u32* vg = reinterpret_cast<const u32*>(g_vt);

    const int aRow = (lane & 7) + ((lane >> 3) & 1) * 8;
    const int aK4  = ((lane >> 4) & 1) * 4;
    const int bRow = (lane & 7) + ((lane >> 4) & 1) * 8;
    const int bK4  = ((lane >> 3) & 1) * 4;

    // ---- stage Q (128 rows x 32 words; overlaps K region) ----
    {
        const u32* qg = reinterpret_cast<const u32*>(g_pq);
#pragma unroll
        for (int i = 0; i < 4; i++) {
            int idx = tid + i * 256;         // 1024 chunks
            int row = idx >> 3, c = idx & 7;
            cpa16(smw + row * KSTR + c * 4,
                  qg + (((size_t)(b * T_SEQ + qb * 128 + row) * D_MODEL + h * 64) >> 1) + c * 4);
        }
        cpa_commit();
        cpa_wait<0>();
        __syncthreads();
    }
    u32 qf[4][4];
#pragma unroll
    for (int kt = 0; kt < 4; kt++) {
        u32 off = ((wq * 16 + aRow) * KSTR + kt * 8 + aK4) * 4;
        ldsm4(qf[kt][0], qf[kt][1], qf[kt][2], qf[kt][3], sb + off);
    }
    __syncthreads();   // Q region reused by K staging

    auto stage_kv = [&](int kb, int buf) {
#pragma unroll
        for (int i = 0; i < 2; i++) {
            int idx = tid + i * 256;
            int row = idx >> 3, c = idx & 7;
            cpa16(smw + KH_OFF(buf) + row * KSTR + c * 4,
                  kg + (((size_t)(b * T_SEQ + kb * 64 + row) * D_MODEL + h * 64) >> 1) + c * 4);
        }
#pragma unroll
        for (int i = 0; i < 2; i++) {
            int idx = tid + i * 256;
            int row = idx >> 3, c = idx & 7;
            cpa16(smw + VH_OFF(buf) + row * KSTR + c * 4,
                  vg + (((size_t)(bh * 64 + row) * T_SEQ) >> 1) + kb * 32 + c * 4);
        }
    };

    stage_kv(0, 0);
    cpa_commit();

    float of[8][4] = {};
    float m0 = -INFINITY, m1 = -INFINITY, l0 = 0.f, l1 = 0.f;
    const int R = qb * 128 + wq * 16;
    const int kbmax = 2 * qb + 1;

    for (int kb = 0; kb <= kbmax; kb++) {
        cpa_wait<0>();
        __syncthreads();
        if (kb + 1 <= kbmax) { stage_kv(kb + 1, (kb + 1) & 1); cpa_commit(); }

        const bool active = (kb * 64 <= R + 15);
        if (active) {
            const u32 kshb = sb + (u32)KH_OFF(kb & 1) * 4;
            const u32 vshb = sb + (u32)VH_OFF(kb & 1) * 4;

            // S = Q K^T
            float sf[8][4] = {};
#pragma unroll
            for (int kt = 0; kt < 4; kt++) {
#pragma unroll
                for (int ntp = 0; ntp < 4; ntp++) {
                    u32 h0, h1, h2, h3;
                    u32 off = ((ntp * 16 + bRow) * KSTR + kt * 8 + bK4) * 4;
                    ldsm4(h0, h1, h2, h3, kshb + off);
                    fmma(sf[2 * ntp],     qf[kt], h0, h1);
                    fmma(sf[2 * ntp + 1], qf[kt], h2, h3);
                }
            }

            // mask (boundary tiles only) + scale
            if (kb * 64 + 63 > R) {
                int r0 = R + g, r1 = r0 + 8;
#pragma unroll
                for (int nt = 0; nt < 8; nt++) {
                    int c0 = kb * 64 + nt * 8 + 2 * q, c1 = c0 + 1;
                    if (c0 > r0) sf[nt][0] = -INFINITY;
                    if (c1 > r0) sf[nt][1] = -INFINITY;
                    if (c0 > r1) sf[nt][2] = -INFINITY;
                    if (c1 > r1) sf[nt][3] = -INFINITY;
                }
            }
#pragma unroll
            for (int nt = 0; nt < 8; nt++) {
                sf[nt][0] *= scale; sf[nt][1] *= scale;
                sf[nt][2] *= scale; sf[nt][3] *= scale;
            }

            // online softmax
            float mx0 = -INFINITY, mx1 = -INFINITY;
#pragma unroll
            for (int nt = 0; nt < 8; nt++) {
                mx0 = fmaxf(mx0, fmaxf(sf[nt][0], sf[nt][1]));
                mx1 = fmaxf(mx1, fmaxf(sf[nt][2], sf[nt][3]));
            }
            mx0 = fmaxf(mx0, __shfl_xor_sync(0xffffffffu, mx0, 1));
            mx0 = fmaxf(mx0, __shfl_xor_sync(0xffffffffu, mx0, 2));
            mx1 = fmaxf(mx1, __shfl_xor_sync(0xffffffffu, mx1, 1));
            mx1 = fmaxf(mx1, __shfl_xor_sync(0xffffffffu, mx1, 2));

            float mn0 = fmaxf(m0, mx0), mn1 = fmaxf(m1, mx1);
            float c0 = __expf(m0 - mn0), c1 = __expf(m1 - mn1);
            m0 = mn0; m1 = mn1;

            float ls0 = 0.f, ls1 = 0.f;
#pragma unroll
            for (int nt = 0; nt < 8; nt++) {
                sf[nt][0] = __expf(sf[nt][0] - mn0);
                sf[nt][1] = __expf(sf[nt][1] - mn0);
                sf[nt][2] = __expf(sf[nt][2] - mn1);
                sf[nt][3] = __expf(sf[nt][3] - mn1);
                ls0 += sf[nt][0] + sf[nt][1];
                ls1 += sf[nt][2] + sf[nt][3];
            }
#pragma unroll
            for (int nt = 0; nt < 8; nt++) {
                of[nt][0] *= c0; of[nt][1] *= c0;
                of[nt][2] *= c1; of[nt][3] *= c1;
            }
            ls0 += __shfl_xor_sync(0xffffffffu, ls0, 1);
            ls0 += __shfl_xor_sync(0xffffffffu, ls0, 2);
            ls1 += __shfl_xor_sync(0xffffffffu, ls1, 1);
            ls1 += __shfl_xor_sync(0xffffffffu, ls1, 2);
            l0 = l0 * c0 + ls0;
            l1 = l1 * c1 + ls1;

            // O += P V (P packed fp16 in registers)
#pragma unroll
            for (int jt = 0; jt < 4; jt++) {
                u32 pa[4];
                pa[0] = packf16(sf[2 * jt][0],     sf[2 * jt][1]);
                pa[1] = packf16(sf[2 * jt][2],     sf[2 * jt][3]);
                pa[2] = packf16(sf[2 * jt + 1][0], sf[2 * jt + 1][1]);
                pa[3] = packf16(sf[2 * jt + 1][2], sf[2 * jt + 1][3]);
#pragma unroll
                for (int ntp = 0; ntp < 4; ntp++) {
                    u32 h0, h1, h2, h3;
                    u32 off = ((ntp * 16 + bRow) * KSTR + jt * 8 + bK4) * 4;
                    ldsm4(h0, h1, h2, h3, vshb + off);
                    fmma(of[2 * ntp],     pa, h0, h1);
                    fmma(of[2 * ntp + 1], pa, h2, h3);
                }
            }
        }
    }

    // epilogue: normalize + fp16 write (input to fp16 O-proj)
    float inv0 = 1.0f / l0, inv1 = 1.0f / l1;
    u32* oa = reinterpret_cast<u32*>(g_ao);
    size_t m0i = (size_t)(b * T_SEQ + R + g) * D_MODEL + h * 64;
    size_t m1i = m0i + (size_t)8 * D_MODEL;
#pragma unroll
    for (int nt = 0; nt < 8; nt++) {
        int col = nt * 8 + 2 * q;
        oa[(m0i + col) >> 1] = packf16(of[nt][0] * inv0, of[nt][1] * inv0);
        oa[(m1i + col) >> 1] = packf16(of[nt][2] * inv1, of[nt][3] * inv1);
    }
}

// ---------------------------------------------------------------------------
extern "C" void kernel_launch(void* const* d_in, const int* in_sizes, int n_in,
                              void* d_out, int out_size)
{
    const float* q   = (const float*)d_in[0];
    const float* k   = (const float*)d_in[1];
    const float* v   = (const float*)d_in[2];
    const float* W_q = (const float*)d_in[4];
    const float* b_q = (const float*)d_in[5];
    const float* W_k = (const float*)d_in[6];
    const float* b_k = (const float*)d_in[7];
    const float* W_v = (const float*)d_in[8];
    const float* b_v = (const float*)d_in[9];
    const float* W_o = (const float*)d_in[10];
    const float* b_o = (const float*)d_in[11];
    float* out = (float*)d_out;

    const int attn_smem = ATTN_SMEM_W * 4;   // 36864
    cudaFuncSetAttribute(gemm_qkv, cudaFuncAttributeMaxDynamicSharedMemorySize, GEMM_SMEM);
    cudaFuncSetAttribute(gemm_o,   cudaFuncAttributeMaxDynamicSharedMemorySize, GEMM_SMEM);
    cudaFuncSetAttribute(attn_causal, cudaFuncAttributeMaxDynamicSharedMemorySize, attn_smem);

    dim3 sg(M_ROWS * D_MODEL / 4 / 256, 7);   // (8192, 7)
    split7_kernel<<<sg, 256>>>((const float4*)q, (const float4*)k, (const float4*)v,
                               (const float4*)W_q, (const float4*)W_k,
                               (const float4*)W_v, (const float4*)W_o);

    dim3 gg(D_MODEL / 128, M_ROWS / 128, 3);   // (8, 64, 3)
    gemm_qkv<<<gg, 256, GEMM_SMEM>>>(b_q, b_k, b_v);

    dim3 tg(T_SEQ / 32, B_SZ * N_HEADS);
    vtrans_kernel<<<tg, 256>>>();

    dim3 ag(T_SEQ / 128, B_SZ * N_HEADS);      // (16, 64)
    attn_causal<<<ag, 256, attn_smem>>>();

    dim3 go(D_MODEL / 128, M_ROWS / 128);
    gemm_o<<<go, 256, GEMM_SMEM>>>(b_o, out);
}

// round 14
// speedup vs baseline: 3.6728x; 1.0590x over previous
#include <cuda_runtime.h>
#include <cuda_bf16.h>
#include <cuda_fp16.h>
#include <math.h>
#include <stdint.h>

#define D_MODEL 1024
#define N_HEADS 16
#define B_SZ    4
#define T_SEQ   2048
#define M_ROWS  8192

typedef unsigned int u32;

// scratch (allocation-free rule: __device__ globals)
__device__ __half g_iq [M_ROWS * D_MODEL];                     // fp16 inputs
__device__ __half g_ik [M_ROWS * D_MODEL];
__device__ __half g_iv [M_ROWS * D_MODEL];
__device__ __half g_wqh[D_MODEL * D_MODEL], g_wql[D_MODEL * D_MODEL];  // fp16 hi/lo weights
__device__ __half g_wkh[D_MODEL * D_MODEL], g_wkl[D_MODEL * D_MODEL];
__device__ __half g_wvh[D_MODEL * D_MODEL], g_wvl[D_MODEL * D_MODEL];
__device__ __half g_woh[D_MODEL * D_MODEL], g_wol[D_MODEL * D_MODEL];
__device__ __half g_pq [M_ROWS * D_MODEL];                     // fp16 Q proj
__device__ __half g_pk [M_ROWS * D_MODEL];                     // fp16 K proj
__device__ float  g_V  [M_ROWS * D_MODEL];
__device__ __half g_vt [M_ROWS * D_MODEL];                     // fp16 V^T [bh][64][2048]
__device__ __half g_ao [M_ROWS * D_MODEL];                     // fp16 attention out

// ---------------------------------------------------------------------------
__device__ __forceinline__ u32 packf16(float x0, float x1) {
    u32 r;
    asm("cvt.rn.f16x2.f32 %0, %1, %2;" : "=r"(r) : "f"(x1), "f"(x0));
    return r;
}

// fp16 hi/lo split of (x0,x1) packed
__device__ __forceinline__ void fsplit2(float x0, float x1, u32& hi, u32& lo) {
    __half h0 = __float2half_rn(x0), h1 = __float2half_rn(x1);
    hi = (u32)__half_as_ushort(h0) | ((u32)__half_as_ushort(h1) << 16);
    float r0 = x0 - __half2float(h0), r1 = x1 - __half2float(h1);
    lo = packf16(r0, r1);
}

// fp16 mma
__device__ __forceinline__ void fmma(float d[4], const u32 a[4], u32 b0, u32 b1) {
    asm volatile(
        "mma.sync.aligned.m16n8k16.row.col.f32.f16.f16.f32 "
        "{%0,%1,%2,%3}, {%4,%5,%6,%7}, {%8,%9}, {%0,%1,%2,%3};\n"
        : "+f"(d[0]), "+f"(d[1]), "+f"(d[2]), "+f"(d[3])
        : "r"(a[0]), "r"(a[1]), "r"(a[2]), "r"(a[3]), "r"(b0), "r"(b1));
}

__device__ __forceinline__ void ldsm4(u32& r0, u32& r1, u32& r2, u32& r3, u32 addr) {
    asm volatile("ldmatrix.sync.aligned.m8n8.x4.shared.b16 {%0,%1,%2,%3}, [%4];"
                 : "=r"(r0), "=r"(r1), "=r"(r2), "=r"(r3) : "r"(addr));
}

__device__ __forceinline__ void cpa16(void* smem_ptr, const void* gptr) {
    u32 s = (u32)__cvta_generic_to_shared(smem_ptr);
    asm volatile("cp.async.cg.shared.global [%0], [%1], 16;\n" :: "r"(s), "l"(gptr));
}
__device__ __forceinline__ void cpa_commit() { asm volatile("cp.async.commit_group;\n"); }
template <int N>
__device__ __forceinline__ void cpa_wait() { asm volatile("cp.async.wait_group %0;\n" :: "n"(N)); }

__device__ __forceinline__ u32 smem_u32(const void* p) {
    return (u32)__cvta_generic_to_shared(p);
}

// ---------------------------------------------------------------------------
// fused prep: grid (8192, 7). seg 0-2: inputs -> single fp16.
// seg 3-6: weights -> fp16 hi/lo.
__global__ void __launch_bounds__(256) split7_kernel(
    const float4* __restrict__ q, const float4* __restrict__ k,
    const float4* __restrict__ v,
    const float4* __restrict__ wq, const float4* __restrict__ wk,
    const float4* __restrict__ wv, const float4* __restrict__ wo)
{
    const int seg = blockIdx.y;
    const int i = blockIdx.x * 256 + threadIdx.x;
    const int NI = M_ROWS * D_MODEL / 4, NW = D_MODEL * D_MODEL / 4;

    if (seg < 3) {
        if (i >= NI) return;
        const float4* src = (seg == 0) ? q : (seg == 1) ? k : v;
        u32* d = (seg == 0) ? (u32*)g_iq : (seg == 1) ? (u32*)g_ik : (u32*)g_iv;
        float4 val = src[i];
        d[2 * i]     = packf16(val.x, val.y);
        d[2 * i + 1] = packf16(val.z, val.w);
    } else {
        if (i >= NW) return;
        const float4* src; u32* dh; u32* dl;
        switch (seg) {
            case 3:  src = wq; dh = (u32*)g_wqh; dl = (u32*)g_wql; break;
            case 4:  src = wk; dh = (u32*)g_wkh; dl = (u32*)g_wkl; break;
            case 5:  src = wv; dh = (u32*)g_wvh; dl = (u32*)g_wvl; break;
            default: src = wo; dh = (u32*)g_woh; dl = (u32*)g_wol; break;
        }
        float4 val = src[i];
        u32 h0, l0, h1, l1;
        fsplit2(val.x, val.y, h0, l0);
        fsplit2(val.z, val.w, h1, l1);
        dh[2 * i] = h0; dh[2 * i + 1] = h1;
        dl[2 * i] = l0; dl[2 * i + 1] = l1;
    }
}

// transpose V per head to fp16: g_V[b][t][h*64+d] -> g_vt[bh][d][t]
__global__ void __launch_bounds__(256) vtrans_kernel()
{
    __shared__ float ts[32][65];
    const int j0 = blockIdx.x * 32;
    const int bh = blockIdx.y;
    const int b = bh >> 4, h = bh & 15;
    const int tid = threadIdx.x;
#pragma unroll
    for (int i = 0; i < 8; i++) {
        int idx = tid + i * 256;
        int r = idx >> 6, c = idx & 63;
        ts[r][c] = g_V[(size_t)(b * T_SEQ + j0 + r) * D_MODEL + h * 64 + c];
    }
    __syncthreads();
    u32* ov = reinterpret_cast<u32*>(g_vt);
#pragma unroll
    for (int i = 0; i < 4; i++) {
        int idx = tid + i * 256;
        int d = idx >> 4, jj = (idx & 15) * 2;
        size_t o = ((size_t)(bh * 64 + d) * T_SEQ + j0 + jj) >> 1;
        ov[o] = packf16(ts[jj][d], ts[jj + 1][d]);
    }
}

// ---------------------------------------------------------------------------
// GEMM body: 2-term FP16 (A single, W hi/lo), ldmatrix, 64-wide K stages,
// 2-stage pipeline, 2 CTAs/SM.  outmode: 0 = float, 2 = fp16 packed
// ---------------------------------------------------------------------------
#define GSTR 36
#define GT  (128 * GSTR)                 // 4608 words per array per stage
#define GEMM_SMEM (2 * 3 * GT * 4)       // 110592 B

__device__ __forceinline__ void gemm_body(
    char* smb,
    const __half* __restrict__ A,
    const __half* __restrict__ Bh, const __half* __restrict__ Bl,
    const float* __restrict__ bias,
    float* __restrict__ Cf, u32* __restrict__ Ch, int outmode)
{
    const u32 sb = smem_u32(smb);
    const int tid  = threadIdx.x;
    const int lane = tid & 31;
    const int wid  = tid >> 5;
    const int g    = lane >> 2;
    const int q    = lane & 3;
    const int wm   = wid >> 2;
    const int wn   = wid & 3;
    const int bm   = blockIdx.y * 128;
    const int bn   = blockIdx.x * 128;
    const int K = D_MODEL, N = D_MODEL;

    float acc[4][4][4] = {};

    u32* smw = reinterpret_cast<u32*>(smb);
    auto issue = [&](int t, int buf) {
        const int k0 = t * 64;
        u32* base = smw + buf * 3 * GT;
#pragma unroll
        for (int i = 0; i < 12; i++) {
            int idx = tid + i * 256;       // 3072 chunks of 16B
            int arr = idx >> 10;           // 0:A 1:Bh 2:Bl (1024 each)
            int w   = idx & 1023;
            int row = w >> 3, c = w & 7;
            const __half* gp;
            int rb;
            if      (arr == 0) { gp = A;  rb = bm; }
            else if (arr == 1) { gp = Bh; rb = bn; }
            else               { gp = Bl; rb = bn; }
            cpa16(base + arr * GT + row * GSTR + c * 4,
                  gp + (size_t)(rb + row) * K + k0 + c * 8);
        }
    };

    const int NT = K / 64;   // 16
    issue(0, 0); cpa_commit();
    issue(1, 1); cpa_commit();

    const int aRow = (lane & 7) + ((lane >> 3) & 1) * 8;
    const int aK4  = ((lane >> 4) & 1) * 4;
    const int bRow = (lane & 7) + ((lane >> 4) & 1) * 8;
    const int bK4  = ((lane >> 3) & 1) * 4;

    for (int s = 0; s < NT; s++) {
        const int buf = s & 1;
        if (s + 1 < NT) cpa_wait<1>(); else cpa_wait<0>();
        __syncthreads();

        const u32 ab  = sb + (u32)(buf * 3 * GT) * 4;
        const u32 bbh = ab + GT * 4;
        const u32 bbl = ab + 2 * GT * 4;

#pragma unroll
        for (int ks = 0; ks < 4; ks++) {
            u32 af[4][4];
#pragma unroll
            for (int mt = 0; mt < 4; mt++) {
                u32 off = ((wm * 64 + mt * 16 + aRow) * GSTR + ks * 8 + aK4) * 4;
                ldsm4(af[mt][0], af[mt][1], af[mt][2], af[mt][3], ab + off);
            }
#pragma unroll
            for (int ntp = 0; ntp < 2; ntp++) {
                u32 bh0, bh1, bh2, bh3, bl0, bl1, bl2, bl3;
                u32 off = ((wn * 32 + ntp * 16 + bRow) * GSTR + ks * 8 + bK4) * 4;
                ldsm4(bh0, bh1, bh2, bh3, bbh + off);
                ldsm4(bl0, bl1, bl2, bl3, bbl + off);
#pragma unroll
                for (int mt = 0; mt < 4; mt++) {
                    fmma(acc[mt][2 * ntp],     af[mt], bh0, bh1);
                    fmma(acc[mt][2 * ntp],     af[mt], bl0, bl1);
                    fmma(acc[mt][2 * ntp + 1], af[mt], bh2, bh3);
                    fmma(acc[mt][2 * ntp + 1], af[mt], bl2, bl3);
                }
            }
        }

        __syncthreads();
        if (s + 2 < NT) { issue(s + 2, buf); cpa_commit(); }
    }

#pragma unroll
    for (int mt = 0; mt < 4; mt++) {
        int row0 = bm + wm * 64 + mt * 16 + g;
#pragma unroll
        for (int nt = 0; nt < 4; nt++) {
            int col = bn + wn * 32 + nt * 8 + 2 * q;
            float b0 = bias[col], b1 = bias[col + 1];
            float v00 = acc[mt][nt][0] + b0, v01 = acc[mt][nt][1] + b1;
            float v10 = acc[mt][nt][2] + b0, v11 = acc[mt][nt][3] + b1;
            if (outmode == 2) {
                size_t o0 = ((size_t)row0 * N + col) >> 1;
                size_t o1 = ((size_t)(row0 + 8) * N + col) >> 1;
                Ch[o0] = packf16(v00, v01);
                Ch[o1] = packf16(v10, v11);
            } else {
                *(float2*)&Cf[(size_t)row0 * N + col]       = make_float2(v00, v01);
                *(float2*)&Cf[(size_t)(row0 + 8) * N + col] = make_float2(v10, v11);
            }
        }
    }
}

__global__ void __launch_bounds__(256, 2) gemm_qkv(
    const float* __restrict__ b_q, const float* __restrict__ b_k,
    const float* __restrict__ b_v)
{
    extern __shared__ char smb[];
    const int z = blockIdx.z;
    if (z == 0)
        gemm_body(smb, g_iq, g_wqh, g_wql, b_q, nullptr, (u32*)g_pq, 2);
    else if (z == 1)
        gemm_body(smb, g_ik, g_wkh, g_wkl, b_k, nullptr, (u32*)g_pk, 2);
    else
        gemm_body(smb, g_iv, g_wvh, g_wvl, b_v, g_V, nullptr, 0);
}

__global__ void __launch_bounds__(256, 2) gemm_o(
    const float* __restrict__ b_o, float* __restrict__ out)
{
    extern __shared__ char smb[];
    gemm_body(smb, g_ao, g_woh, g_wol, b_o, out, nullptr, 0);
}

// ---------------------------------------------------------------------------
// Causal flash attention, single-term FP16, 64-wide kv tiles, 2 CTAs/SM,
// exp2-domain softmax. Grid (T/128, B*H), 256 thr = 8 warps x 16 q-rows.
// ---------------------------------------------------------------------------
#define KSTR 36
#define ATW  (64 * KSTR)                   // 2304 words per tile
#define KH_OFF(b) ((b) * ATW)
#define VH_OFF(b) (2 * ATW + (b) * ATW)
#define ATTN_SMEM_W (4 * ATW)              // 9216 words = 36864 B

__global__ void __launch_bounds__(256, 2) attn_causal()
{
    extern __shared__ u32 smw[];
    const u32 sb = smem_u32(smw);

    const int qb = gridDim.x - 1 - blockIdx.x;   // heavy blocks first
    const int bh = blockIdx.y;
    const int b  = bh >> 4;
    const int h  = bh & 15;

    const int tid  = threadIdx.x;
    const int lane = tid & 31;
    const int wq   = tid >> 5;
    const int g    = lane >> 2;
    const int q    = lane & 3;

    const float scale2 = 0.125f * 1.44269504f;   // scale * log2(e)
    const u32* kg = reinterpret_cast<const u32*>(g_pk);
    const u32* vg = reinterpret_cast<const u32*>(g_vt);

    const int aRow = (lane & 7) + ((lane >> 3) & 1) * 8;
    const int aK4  = ((lane >> 4) & 1) * 4;
    const int bRow = (lane & 7) + ((lane >> 4) & 1) * 8;
    const int bK4  = ((lane >> 3) & 1) * 4;

    // ---- stage Q (128 rows x 32 words; overlaps K region) ----
    {
        const u32* qg = reinterpret_cast<const u32*>(g_pq);
#pragma unroll
        for (int i = 0; i < 4; i++) {
            int idx = tid + i * 256;         // 1024 chunks
            int row = idx >> 3, c = idx & 7;
            cpa16(smw + row * KSTR + c * 4,
                  qg + (((size_t)(b * T_SEQ + qb * 128 + row) * D_MODEL + h * 64) >> 1) + c * 4);
        }
        cpa_commit();
        cpa_wait<0>();
        __syncthreads();
    }
    u32 qf[4][4];
#pragma unroll
    for (int kt = 0; kt < 4; kt++) {
        u32 off = ((wq * 16 + aRow) * KSTR + kt * 8 + aK4) * 4;
        ldsm4(qf[kt][0], qf[kt][1], qf[kt][2], qf[kt][3], sb + off);
    }
    __syncthreads();   // Q region reused by K staging

    auto stage_kv = [&](int kb, int buf) {
#pragma unroll
        for (int i = 0; i < 2; i++) {
            int idx = tid + i * 256;
            int row = idx >> 3, c = idx & 7;
            cpa16(smw + KH_OFF(buf) + row * KSTR + c * 4,
                  kg + (((size_t)(b * T_SEQ + kb * 64 + row) * D_MODEL + h * 64) >> 1) + c * 4);
        }
#pragma unroll
        for (int i = 0; i < 2; i++) {
            int idx = tid + i * 256;
            int row = idx >> 3, c = idx & 7;
            cpa16(smw + VH_OFF(buf) + row * KSTR + c * 4,
                  vg + (((size_t)(bh * 64 + row) * T_SEQ) >> 1) + kb * 32 + c * 4);
        }
    };

    stage_kv(0, 0);
    cpa_commit();

    float of[8][4] = {};
    float m0 = -INFINITY, m1 = -INFINITY, l0 = 0.f, l1 = 0.f;
    const int R = qb * 128 + wq * 16;
    const int kbmax = 2 * qb + 1;

    for (int kb = 0; kb <= kbmax; kb++) {
        cpa_wait<0>();
        __syncthreads();
        if (kb + 1 <= kbmax) { stage_kv(kb + 1, (kb + 1) & 1); cpa_commit(); }

        const bool active = (kb * 64 <= R + 15);
        if (active) {
            const u32 kshb = sb + (u32)KH_OFF(kb & 1) * 4;
            const u32 vshb = sb + (u32)VH_OFF(kb & 1) * 4;

            // S = Q K^T
            float sf[8][4] = {};
#pragma unroll
            for (int kt = 0; kt < 4; kt++) {
#pragma unroll
                for (int ntp = 0; ntp < 4; ntp++) {
                    u32 h0, h1, h2, h3;
                    u32 off = ((ntp * 16 + bRow) * KSTR + kt * 8 + bK4) * 4;
                    ldsm4(h0, h1, h2, h3, kshb + off);
                    fmma(sf[2 * ntp],     qf[kt], h0, h1);
                    fmma(sf[2 * ntp + 1], qf[kt], h2, h3);
                }
            }

            // mask (boundary tiles only) + scale into log2 domain
            if (kb * 64 + 63 > R) {
                int r0 = R + g, r1 = r0 + 8;
#pragma unroll
                for (int nt = 0; nt < 8; nt++) {
                    int c0 = kb * 64 + nt * 8 + 2 * q, c1 = c0 + 1;
                    if (c0 > r0) sf[nt][0] = -INFINITY;
                    if (c1 > r0) sf[nt][1] = -INFINITY;
                    if (c0 > r1) sf[nt][2] = -INFINITY;
                    if (c1 > r1) sf[nt][3] = -INFINITY;
                }
            }
#pragma unroll
            for (int nt = 0; nt < 8; nt++) {
                sf[nt][0] *= scale2; sf[nt][1] *= scale2;
                sf[nt][2] *= scale2; sf[nt][3] *= scale2;
            }

            // online softmax (log2 domain)
            float mx0 = -INFINITY, mx1 = -INFINITY;
#pragma unroll
            for (int nt = 0; nt < 8; nt++) {
                mx0 = fmaxf(mx0, fmaxf(sf[nt][0], sf[nt][1]));
                mx1 = fmaxf(mx1, fmaxf(sf[nt][2], sf[nt][3]));
            }
            mx0 = fmaxf(mx0, __shfl_xor_sync(0xffffffffu, mx0, 1));
            mx0 = fmaxf(mx0, __shfl_xor_sync(0xffffffffu, mx0, 2));
            mx1 = fmaxf(mx1, __shfl_xor_sync(0xffffffffu, mx1, 1));
            mx1 = fmaxf(mx1, __shfl_xor_sync(0xffffffffu, mx1, 2));

            float mn0 = fmaxf(m0, mx0), mn1 = fmaxf(m1, mx1);
            float c0 = exp2f(m0 - mn0), c1 = exp2f(m1 - mn1);
            m0 = mn0; m1 = mn1;

            float ls0 = 0.f, ls1 = 0.f;
#pragma unroll
            for (int nt = 0; nt < 8; nt++) {
                sf[nt][0] = exp2f(sf[nt][0] - mn0);
                sf[nt][1] = exp2f(sf[nt][1] - mn0);
                sf[nt][2] = exp2f(sf[nt][2] - mn1);
                sf[nt][3] = exp2f(sf[nt][3] - mn1);
                ls0 += sf[nt][0] + sf[nt][1];
                ls1 += sf[nt][2] + sf[nt][3];
            }
#pragma unroll
            for (int nt = 0; nt < 8; nt++) {
                of[nt][0] *= c0; of[nt][1] *= c0;
                of[nt][2] *= c1; of[nt][3] *= c1;
            }
            ls0 += __shfl_xor_sync(0xffffffffu, ls0, 1);
            ls0 += __shfl_xor_sync(0xffffffffu, ls0, 2);
            ls1 += __shfl_xor_sync(0xffffffffu, ls1, 1);
            ls1 += __shfl_xor_sync(0xffffffffu, ls1, 2);
            l0 = l0 * c0 + ls0;
            l1 = l1 * c1 + ls1;

            // O += P V (P packed fp16 in registers)
#pragma unroll
            for (int jt = 0; jt < 4; jt++) {
                u32 pa[4];
                pa[0] = packf16(sf[2 * jt][0],     sf[2 * jt][1]);
                pa[1] = packf16(sf[2 * jt][2],     sf[2 * jt][3]);
                pa[2] = packf16(sf[2 * jt + 1][0], sf[2 * jt + 1][1]);
                pa[3] = packf16(sf[2 * jt + 1][2], sf[2 * jt + 1][3]);
#pragma unroll
                for (int ntp = 0; ntp < 4; ntp++) {
                    u32 h0, h1, h2, h3;
                    u32 off = ((ntp * 16 + bRow) * KSTR + jt * 8 + bK4) * 4;
                    ldsm4(h0, h1, h2, h3, vshb + off);
                    fmma(of[2 * ntp],     pa, h0, h1);
                    fmma(of[2 * ntp + 1], pa, h2, h3);
                }
            }
        }
    }

    // epilogue: normalize + fp16 write (input to fp16 O-proj)
    float inv0 = 1.0f / l0, inv1 = 1.0f / l1;
    u32* oa = reinterpret_cast<u32*>(g_ao);
    size_t m0i = (size_t)(b * T_SEQ + R + g) * D_MODEL + h * 64;
    size_t m1i = m0i + (size_t)8 * D_MODEL;
#pragma unroll
    for (int nt = 0; nt < 8; nt++) {
        int col = nt * 8 + 2 * q;
        oa[(m0i + col) >> 1] = packf16(of[nt][0] * inv0, of[nt][1] * inv0);
        oa[(m1i + col) >> 1] = packf16(of[nt][2] * inv1, of[nt][3] * inv1);
    }
}

// ---------------------------------------------------------------------------
extern "C" void kernel_launch(void* const* d_in, const int* in_sizes, int n_in,
                              void* d_out, int out_size)
{
    const float* q   = (const float*)d_in[0];
    const float* k   = (const float*)d_in[1];
    const float* v   = (const float*)d_in[2];
    const float* W_q = (const float*)d_in[4];
    const float* b_q = (const float*)d_in[5];
    const float* W_k = (const float*)d_in[6];
    const float* b_k = (const float*)d_in[7];
    const float* W_v = (const float*)d_in[8];
    const float* b_v = (const float*)d_in[9];
    const float* W_o = (const float*)d_in[10];
    const float* b_o = (const float*)d_in[11];
    float* out = (float*)d_out;

    const int attn_smem = ATTN_SMEM_W * 4;   // 36864
    cudaFuncSetAttribute(gemm_qkv, cudaFuncAttributeMaxDynamicSharedMemorySize, GEMM_SMEM);
    cudaFuncSetAttribute(gemm_o,   cudaFuncAttributeMaxDynamicSharedMemorySize, GEMM_SMEM);
    cudaFuncSetAttribute(attn_causal, cudaFuncAttributeMaxDynamicSharedMemorySize, attn_smem);

    dim3 sg(M_ROWS * D_MODEL / 4 / 256, 7);   // (8192, 7)
    split7_kernel<<<sg, 256>>>((const float4*)q, (const float4*)k, (const float4*)v,
                               (const float4*)W_q, (const float4*)W_k,
                               (const float4*)W_v, (const float4*)W_o);

    dim3 gg(D_MODEL / 128, M_ROWS / 128, 3);   // (8, 64, 3)
    gemm_qkv<<<gg, 256, GEMM_SMEM>>>(b_q, b_k, b_v);

    dim3 tg(T_SEQ / 32, B_SZ * N_HEADS);
    vtrans_kernel<<<tg, 256>>>();

    dim3 ag(T_SEQ / 128, B_SZ * N_HEADS);      // (16, 64)
    attn_causal<<<ag, 256, attn_smem>>>();

    dim3 go(D_MODEL / 128, M_ROWS / 128);
    gemm_o<<<go, 256, GEMM_SMEM>>>(b_o, out);
}

// round 15
// speedup vs baseline: 4.1885x; 1.1404x over previous
#include <cuda_runtime.h>
#include <cuda_bf16.h>
#include <cuda_fp16.h>
#include <math.h>
#include <stdint.h>

#define D_MODEL 1024
#define N_HEADS 16
#define B_SZ    4
#define T_SEQ   2048
#define M_ROWS  8192

typedef unsigned int u32;

// scratch (allocation-free rule: __device__ globals)
__device__ __half g_iq [M_ROWS * D_MODEL];                     // fp16 inputs
__device__ __half g_ik [M_ROWS * D_MODEL];
__device__ __half g_iv [M_ROWS * D_MODEL];
__device__ __half g_wqh[D_MODEL * D_MODEL], g_wql[D_MODEL * D_MODEL];  // fp16 hi/lo weights
__device__ __half g_wkh[D_MODEL * D_MODEL], g_wkl[D_MODEL * D_MODEL];
__device__ __half g_wvh[D_MODEL * D_MODEL], g_wvl[D_MODEL * D_MODEL];
__device__ __half g_woh[D_MODEL * D_MODEL], g_wol[D_MODEL * D_MODEL];
__device__ __half g_pq [M_ROWS * D_MODEL];                     // fp16 Q proj
__device__ __half g_pk [M_ROWS * D_MODEL];                     // fp16 K proj
__device__ float  g_V  [M_ROWS * D_MODEL];
__device__ __half g_vt [M_ROWS * D_MODEL];                     // fp16 V^T [bh][64][2048]
__device__ __half g_ao [M_ROWS * D_MODEL];                     // fp16 attention out

// ---------------------------------------------------------------------------
__device__ __forceinline__ u32 packf16(float x0, float x1) {
    u32 r;
    asm("cvt.rn.f16x2.f32 %0, %1, %2;" : "=r"(r) : "f"(x1), "f"(x0));
    return r;
}

// fp16 hi/lo split of (x0,x1) packed
__device__ __forceinline__ void fsplit2(float x0, float x1, u32& hi, u32& lo) {
    __half h0 = __float2half_rn(x0), h1 = __float2half_rn(x1);
    hi = (u32)__half_as_ushort(h0) | ((u32)__half_as_ushort(h1) << 16);
    float r0 = x0 - __half2float(h0), r1 = x1 - __half2float(h1);
    lo = packf16(r0, r1);
}

// fp16 mma
__device__ __forceinline__ void fmma(float d[4], const u32 a[4], u32 b0, u32 b1) {
    asm volatile(
        "mma.sync.aligned.m16n8k16.row.col.f32.f16.f16.f32 "
        "{%0,%1,%2,%3}, {%4,%5,%6,%7}, {%8,%9}, {%0,%1,%2,%3};\n"
        : "+f"(d[0]), "+f"(d[1]), "+f"(d[2]), "+f"(d[3])
        : "r"(a[0]), "r"(a[1]), "r"(a[2]), "r"(a[3]), "r"(b0), "r"(b1));
}

__device__ __forceinline__ void ldsm4(u32& r0, u32& r1, u32& r2, u32& r3, u32 addr) {
    asm volatile("ldmatrix.sync.aligned.m8n8.x4.shared.b16 {%0,%1,%2,%3}, [%4];"
                 : "=r"(r0), "=r"(r1), "=r"(r2), "=r"(r3) : "r"(addr));
}

__device__ __forceinline__ void cpa16(void* smem_ptr, const void* gptr) {
    u32 s = (u32)__cvta_generic_to_shared(smem_ptr);
    asm volatile("cp.async.cg.shared.global [%0], [%1], 16;\n" :: "r"(s), "l"(gptr));
}
__device__ __forceinline__ void cpa_commit() { asm volatile("cp.async.commit_group;\n"); }
template <int N>
__device__ __forceinline__ void cpa_wait() { asm volatile("cp.async.wait_group %0;\n" :: "n"(N)); }

__device__ __forceinline__ u32 smem_u32(const void* p) {
    return (u32)__cvta_generic_to_shared(p);
}

// ---------------------------------------------------------------------------
// fused prep: grid (8192, 7). seg 0-2: inputs -> single fp16.
// seg 3-6: weights -> fp16 hi/lo.
__global__ void __launch_bounds__(256) split7_kernel(
    const float4* __restrict__ q, const float4* __restrict__ k,
    const float4* __restrict__ v,
    const float4* __restrict__ wq, const float4* __restrict__ wk,
    const float4* __restrict__ wv, const float4* __restrict__ wo)
{
    const int seg = blockIdx.y;
    const int i = blockIdx.x * 256 + threadIdx.x;
    const int NI = M_ROWS * D_MODEL / 4, NW = D_MODEL * D_MODEL / 4;

    if (seg < 3) {
        if (i >= NI) return;
        const float4* src = (seg == 0) ? q : (seg == 1) ? k : v;
        u32* d = (seg == 0) ? (u32*)g_iq : (seg == 1) ? (u32*)g_ik : (u32*)g_iv;
        float4 val = src[i];
        d[2 * i]     = packf16(val.x, val.y);
        d[2 * i + 1] = packf16(val.z, val.w);
    } else {
        if (i >= NW) return;
        const float4* src; u32* dh; u32* dl;
        switch (seg) {
            case 3:  src = wq; dh = (u32*)g_wqh; dl = (u32*)g_wql; break;
            case 4:  src = wk; dh = (u32*)g_wkh; dl = (u32*)g_wkl; break;
            case 5:  src = wv; dh = (u32*)g_wvh; dl = (u32*)g_wvl; break;
            default: src = wo; dh = (u32*)g_woh; dl = (u32*)g_wol; break;
        }
        float4 val = src[i];
        u32 h0, l0, h1, l1;
        fsplit2(val.x, val.y, h0, l0);
        fsplit2(val.z, val.w, h1, l1);
        dh[2 * i] = h0; dh[2 * i + 1] = h1;
        dl[2 * i] = l0; dl[2 * i + 1] = l1;
    }
}

// transpose V per head to fp16: g_V[b][t][h*64+d] -> g_vt[bh][d][t]
__global__ void __launch_bounds__(256) vtrans_kernel()
{
    __shared__ float ts[32][65];
    const int j0 = blockIdx.x * 32;
    const int bh = blockIdx.y;
    const int b = bh >> 4, h = bh & 15;
    const int tid = threadIdx.x;
#pragma unroll
    for (int i = 0; i < 8; i++) {
        int idx = tid + i * 256;
        int r = idx >> 6, c = idx & 63;
        ts[r][c] = g_V[(size_t)(b * T_SEQ + j0 + r) * D_MODEL + h * 64 + c];
    }
    __syncthreads();
    u32* ov = reinterpret_cast<u32*>(g_vt);
#pragma unroll
    for (int i = 0; i < 4; i++) {
        int idx = tid + i * 256;
        int d = idx >> 4, jj = (idx & 15) * 2;
        size_t o = ((size_t)(bh * 64 + d) * T_SEQ + j0 + jj) >> 1;
        ov[o] = packf16(ts[jj][d], ts[jj + 1][d]);
    }
}

// ---------------------------------------------------------------------------
// GEMM body: NTERMS-term FP16 (A single, W hi [+lo]), ldmatrix, 64-wide K
// stages, 2-stage pipeline, 2 CTAs/SM.  outmode: 0 = float, 2 = fp16 packed
// ---------------------------------------------------------------------------
#define GSTR 36
#define GT  (128 * GSTR)                 // 4608 words per array per stage
#define GEMM_SMEM (2 * 3 * GT * 4)       // 110592 B

template <int NTERMS>
__device__ __forceinline__ void gemm_body(
    char* smb,
    const __half* __restrict__ A,
    const __half* __restrict__ Bh, const __half* __restrict__ Bl,
    const float* __restrict__ bias,
    float* __restrict__ Cf, u32* __restrict__ Ch, int outmode)
{
    const u32 sb = smem_u32(smb);
    const int tid  = threadIdx.x;
    const int lane = tid & 31;
    const int wid  = tid >> 5;
    const int g    = lane >> 2;
    const int q    = lane & 3;
    const int wm   = wid >> 2;
    const int wn   = wid & 3;
    const int bm   = blockIdx.y * 128;
    const int bn   = blockIdx.x * 128;
    const int K = D_MODEL, N = D_MODEL;

    float acc[4][4][4] = {};

    u32* smw = reinterpret_cast<u32*>(smb);
    auto issue = [&](int t, int buf) {
        const int k0 = t * 64;
        u32* base = smw + buf * 3 * GT;
        const int NARR = (NTERMS == 2) ? 12 : 8;   // 3 or 2 arrays x 1024 chunks
#pragma unroll
        for (int i = 0; i < NARR; i++) {
            int idx = tid + i * 256;
            int arr = idx >> 10;           // 0:A 1:Bh 2:Bl
            int w   = idx & 1023;
            int row = w >> 3, c = w & 7;
            const __half* gp;
            int rb;
            if      (arr == 0) { gp = A;  rb = bm; }
            else if (arr == 1) { gp = Bh; rb = bn; }
            else               { gp = Bl; rb = bn; }
            cpa16(base + arr * GT + row * GSTR + c * 4,
                  gp + (size_t)(rb + row) * K + k0 + c * 8);
        }
    };

    const int NT = K / 64;   // 16
    issue(0, 0); cpa_commit();
    issue(1, 1); cpa_commit();

    const int aRow = (lane & 7) + ((lane >> 3) & 1) * 8;
    const int aK4  = ((lane >> 4) & 1) * 4;
    const int bRow = (lane & 7) + ((lane >> 4) & 1) * 8;
    const int bK4  = ((lane >> 3) & 1) * 4;

    for (int s = 0; s < NT; s++) {
        const int buf = s & 1;
        if (s + 1 < NT) cpa_wait<1>(); else cpa_wait<0>();
        __syncthreads();

        const u32 ab  = sb + (u32)(buf * 3 * GT) * 4;
        const u32 bbh = ab + GT * 4;
        const u32 bbl = ab + 2 * GT * 4;

#pragma unroll
        for (int ks = 0; ks < 4; ks++) {
            u32 af[4][4];
#pragma unroll
            for (int mt = 0; mt < 4; mt++) {
                u32 off = ((wm * 64 + mt * 16 + aRow) * GSTR + ks * 8 + aK4) * 4;
                ldsm4(af[mt][0], af[mt][1], af[mt][2], af[mt][3], ab + off);
            }
#pragma unroll
            for (int ntp = 0; ntp < 2; ntp++) {
                u32 off = ((wn * 32 + ntp * 16 + bRow) * GSTR + ks * 8 + bK4) * 4;
                u32 bh0, bh1, bh2, bh3;
                ldsm4(bh0, bh1, bh2, bh3, bbh + off);
                if (NTERMS == 2) {
                    u32 bl0, bl1, bl2, bl3;
                    ldsm4(bl0, bl1, bl2, bl3, bbl + off);
#pragma unroll
                    for (int mt = 0; mt < 4; mt++) {
                        fmma(acc[mt][2 * ntp],     af[mt], bh0, bh1);
                        fmma(acc[mt][2 * ntp],     af[mt], bl0, bl1);
                        fmma(acc[mt][2 * ntp + 1], af[mt], bh2, bh3);
                        fmma(acc[mt][2 * ntp + 1], af[mt], bl2, bl3);
                    }
                } else {
#pragma unroll
                    for (int mt = 0; mt < 4; mt++) {
                        fmma(acc[mt][2 * ntp],     af[mt], bh0, bh1);
                        fmma(acc[mt][2 * ntp + 1], af[mt], bh2, bh3);
                    }
                }
            }
        }

        __syncthreads();
        if (s + 2 < NT) { issue(s + 2, buf); cpa_commit(); }
    }

#pragma unroll
    for (int mt = 0; mt < 4; mt++) {
        int row0 = bm + wm * 64 + mt * 16 + g;
#pragma unroll
        for (int nt = 0; nt < 4; nt++) {
            int col = bn + wn * 32 + nt * 8 + 2 * q;
            float b0 = bias[col], b1 = bias[col + 1];
            float v00 = acc[mt][nt][0] + b0, v01 = acc[mt][nt][1] + b1;
            float v10 = acc[mt][nt][2] + b0, v11 = acc[mt][nt][3] + b1;
            if (outmode == 2) {
                size_t o0 = ((size_t)row0 * N + col) >> 1;
                size_t o1 = ((size_t)(row0 + 8) * N + col) >> 1;
                Ch[o0] = packf16(v00, v01);
                Ch[o1] = packf16(v10, v11);
            } else {
                *(float2*)&Cf[(size_t)row0 * N + col]       = make_float2(v00, v01);
                *(float2*)&Cf[(size_t)(row0 + 8) * N + col] = make_float2(v10, v11);
            }
        }
    }
}

__global__ void __launch_bounds__(256, 2) gemm_qkv(
    const float* __restrict__ b_q, const float* __restrict__ b_k,
    const float* __restrict__ b_v)
{
    extern __shared__ char smb[];
    const int z = blockIdx.z;
    if (z == 0)
        gemm_body<1>(smb, g_iq, g_wqh, g_wql, b_q, nullptr, (u32*)g_pq, 2);
    else if (z == 1)
        gemm_body<1>(smb, g_ik, g_wkh, g_wkl, b_k, nullptr, (u32*)g_pk, 2);
    else
        gemm_body<2>(smb, g_iv, g_wvh, g_wvl, b_v, g_V, nullptr, 0);
}

__global__ void __launch_bounds__(256, 2) gemm_o(
    const float* __restrict__ b_o, float* __restrict__ out)
{
    extern __shared__ char smb[];
    gemm_body<2>(smb, g_ao, g_woh, g_wol, b_o, out, nullptr, 0);
}

// ---------------------------------------------------------------------------
// Causal flash attention, single-term FP16, 64-wide kv tiles, 2 CTAs/SM,
// exp2-domain softmax. Grid (T/128, B*H), 256 thr = 8 warps x 16 q-rows.
// ---------------------------------------------------------------------------
#define KSTR 36
#define ATW  (64 * KSTR)                   // 2304 words per tile
#define KH_OFF(b) ((b) * ATW)
#define VH_OFF(b) (2 * ATW + (b) * ATW)
#define ATTN_SMEM_W (4 * ATW)              // 9216 words = 36864 B

__global__ void __launch_bounds__(256, 2) attn_causal()
{
    extern __shared__ u32 smw[];
    const u32 sb = smem_u32(smw);

    const int qb = gridDim.x - 1 - blockIdx.x;   // heavy blocks first
    const int bh = blockIdx.y;
    const int b  = bh >> 4;
    const int h  = bh & 15;

    const int tid  = threadIdx.x;
    const int lane = tid & 31;
    const int wq   = tid >> 5;
    const int g    = lane >> 2;
    const int q    = lane & 3;

    const float scale2 = 0.125f * 1.44269504f;   // scale * log2(e)
    const u32* kg = reinterpret_cast<const u32*>(g_pk);
    const u32* vg = reinterpret_cast<const u32*>(g_vt);

    const int aRow = (lane & 7) + ((lane >> 3) & 1) * 8;
    const int aK4  = ((lane >> 4) & 1) * 4;
    const int bRow = (lane & 7) + ((lane >> 4) & 1) * 8;
    const int bK4  = ((lane >> 3) & 1) * 4;

    // ---- stage Q (128 rows x 32 words; overlaps K region) ----
    {
        const u32* qg = reinterpret_cast<const u32*>(g_pq);
#pragma unroll
        for (int i = 0; i < 4; i++) {
            int idx = tid + i * 256;         // 1024 chunks
            int row = idx >> 3, c = idx & 7;
            cpa16(smw + row * KSTR + c * 4,
                  qg + (((size_t)(b * T_SEQ + qb * 128 + row) * D_MODEL + h * 64) >> 1) + c * 4);
        }
        cpa_commit();
        cpa_wait<0>();
        __syncthreads();
    }
    u32 qf[4][4];
#pragma unroll
    for (int kt = 0; kt < 4; kt++) {
        u32 off = ((wq * 16 + aRow) * KSTR + kt * 8 + aK4) * 4;
        ldsm4(qf[kt][0], qf[kt][1], qf[kt][2], qf[kt][3], sb + off);
    }
    __syncthreads();   // Q region reused by K staging

    auto stage_kv = [&](int kb, int buf) {
#pragma unroll
        for (int i = 0; i < 2; i++) {
            int idx = tid + i * 256;
            int row = idx >> 3, c = idx & 7;
            cpa16(smw + KH_OFF(buf) + row * KSTR + c * 4,
                  kg + (((size_t)(b * T_SEQ + kb * 64 + row) * D_MODEL + h * 64) >> 1) + c * 4);
        }
#pragma unroll
        for (int i = 0; i < 2; i++) {
            int idx = tid + i * 256;
            int row = idx >> 3, c = idx & 7;
            cpa16(smw + VH_OFF(buf) + row * KSTR + c * 4,
                  vg + (((size_t)(bh * 64 + row) * T_SEQ) >> 1) + kb * 32 + c * 4);
        }
    };

    stage_kv(0, 0);
    cpa_commit();

    float of[8][4] = {};
    float m0 = -INFINITY, m1 = -INFINITY, l0 = 0.f, l1 = 0.f;
    const int R = qb * 128 + wq * 16;
    const int kbmax = 2 * qb + 1;

    for (int kb = 0; kb <= kbmax; kb++) {
        cpa_wait<0>();
        __syncthreads();
        if (kb + 1 <= kbmax) { stage_kv(kb + 1, (kb + 1) & 1); cpa_commit(); }

        const bool active = (kb * 64 <= R + 15);
        if (active) {
            const u32 kshb = sb + (u32)KH_OFF(kb & 1) * 4;
            const u32 vshb = sb + (u32)VH_OFF(kb & 1) * 4;

            // S = Q K^T
            float sf[8][4] = {};
#pragma unroll
            for (int kt = 0; kt < 4; kt++) {
#pragma unroll
                for (int ntp = 0; ntp < 4; ntp++) {
                    u32 h0, h1, h2, h3;
                    u32 off = ((ntp * 16 + bRow) * KSTR + kt * 8 + bK4) * 4;
                    ldsm4(h0, h1, h2, h3, kshb + off);
                    fmma(sf[2 * ntp],     qf[kt], h0, h1);
                    fmma(sf[2 * ntp + 1], qf[kt], h2, h3);
                }
            }

            // mask (boundary tiles only) + scale into log2 domain
            if (kb * 64 + 63 > R) {
                int r0 = R + g, r1 = r0 + 8;
#pragma unroll
                for (int nt = 0; nt < 8; nt++) {
                    int c0 = kb * 64 + nt * 8 + 2 * q, c1 = c0 + 1;
                    if (c0 > r0) sf[nt][0] = -INFINITY;
                    if (c1 > r0) sf[nt][1] = -INFINITY;
                    if (c0 > r1) sf[nt][2] = -INFINITY;
                    if (c1 > r1) sf[nt][3] = -INFINITY;
                }
            }
#pragma unroll
            for (int nt = 0; nt < 8; nt++) {
                sf[nt][0] *= scale2; sf[nt][1] *= scale2;
                sf[nt][2] *= scale2; sf[nt][3] *= scale2;
            }

            // online softmax (log2 domain)
            float mx0 = -INFINITY, mx1 = -INFINITY;
#pragma unroll
            for (int nt = 0; nt < 8; nt++) {
                mx0 = fmaxf(mx0, fmaxf(sf[nt][0], sf[nt][1]));
                mx1 = fmaxf(mx1, fmaxf(sf[nt][2], sf[nt][3]));
            }
            mx0 = fmaxf(mx0, __shfl_xor_sync(0xffffffffu, mx0, 1));
            mx0 = fmaxf(mx0, __shfl_xor_sync(0xffffffffu, mx0, 2));
            mx1 = fmaxf(mx1, __shfl_xor_sync(0xffffffffu, mx1, 1));
            mx1 = fmaxf(mx1, __shfl_xor_sync(0xffffffffu, mx1, 2));

            float mn0 = fmaxf(m0, mx0), mn1 = fmaxf(m1, mx1);
            float c0 = exp2f(m0 - mn0), c1 = exp2f(m1 - mn1);
            m0 = mn0; m1 = mn1;

            float ls0 = 0.f, ls1 = 0.f;
#pragma unroll
            for (int nt = 0; nt < 8; nt++) {
                sf[nt][0] = exp2f(sf[nt][0] - mn0);
                sf[nt][1] = exp2f(sf[nt][1] - mn0);
                sf[nt][2] = exp2f(sf[nt][2] - mn1);
                sf[nt][3] = exp2f(sf[nt][3] - mn1);
                ls0 += sf[nt][0] + sf[nt][1];
                ls1 += sf[nt][2] + sf[nt][3];
            }
#pragma unroll
            for (int nt = 0; nt < 8; nt++) {
                of[nt][0] *= c0; of[nt][1] *= c0;
                of[nt][2] *= c1; of[nt][3] *= c1;
            }
            ls0 += __shfl_xor_sync(0xffffffffu, ls0, 1);
            ls0 += __shfl_xor_sync(0xffffffffu, ls0, 2);
            ls1 += __shfl_xor_sync(0xffffffffu, ls1, 1);
            ls1 += __shfl_xor_sync(0xffffffffu, ls1, 2);
            l0 = l0 * c0 + ls0;
            l1 = l1 * c1 + ls1;

            // O += P V (P packed fp16 in registers)
#pragma unroll
            for (int jt = 0; jt < 4; jt++) {
                u32 pa[4];
                pa[0] = packf16(sf[2 * jt][0],     sf[2 * jt][1]);
                pa[1] = packf16(sf[2 * jt][2],     sf[2 * jt][3]);
                pa[2] = packf16(sf[2 * jt + 1][0], sf[2 * jt + 1][1]);
                pa[3] = packf16(sf[2 * jt + 1][2], sf[2 * jt + 1][3]);
#pragma unroll
                for (int ntp = 0; ntp < 4; ntp++) {
                    u32 h0, h1, h2, h3;
                    u32 off = ((ntp * 16 + bRow) * KSTR + jt * 8 + bK4) * 4;
                    ldsm4(h0, h1, h2, h3, vshb + off);
                    fmma(of[2 * ntp],     pa, h0, h1);
                    fmma(of[2 * ntp + 1], pa, h2, h3);
                }
            }
        }
    }

    // epilogue: normalize + fp16 write (input to fp16 O-proj)
    float inv0 = 1.0f / l0, inv1 = 1.0f / l1;
    u32* oa = reinterpret_cast<u32*>(g_ao);
    size_t m0i = (size_t)(b * T_SEQ + R + g) * D_MODEL + h * 64;
    size_t m1i = m0i + (size_t)8 * D_MODEL;
#pragma unroll
    for (int nt = 0; nt < 8; nt++) {
        int col = nt * 8 + 2 * q;
        oa[(m0i + col) >> 1] = packf16(of[nt][0] * inv0, of[nt][1] * inv0);
        oa[(m1i + col) >> 1] = packf16(of[nt][2] * inv1, of[nt][3] * inv1);
    }
}

// ---------------------------------------------------------------------------
extern "C" void kernel_launch(void* const* d_in, const int* in_sizes, int n_in,
                              void* d_out, int out_size)
{
    const float* q   = (const float*)d_in[0];
    const float* k   = (const float*)d_in[1];
    const float* v   = (const float*)d_in[2];
    const float* W_q = (const float*)d_in[4];
    const float* b_q = (const float*)d_in[5];
    const float* W_k = (const float*)d_in[6];
    const float* b_k = (const float*)d_in[7];
    const float* W_v = (const float*)d_in[8];
    const float* b_v = (const float*)d_in[9];
    const float* W_o = (const float*)d_in[10];
    const float* b_o = (const float*)d_in[11];
    float* out = (float*)d_out;

    const int attn_smem = ATTN_SMEM_W * 4;   // 36864
    cudaFuncSetAttribute(gemm_qkv, cudaFuncAttributeMaxDynamicSharedMemorySize, GEMM_SMEM);
    cudaFuncSetAttribute(gemm_o,   cudaFuncAttributeMaxDynamicSharedMemorySize, GEMM_SMEM);
    cudaFuncSetAttribute(attn_causal, cudaFuncAttributeMaxDynamicSharedMemorySize, attn_smem);

    dim3 sg(M_ROWS * D_MODEL / 4 / 256, 7);   // (8192, 7)
    split7_kernel<<<sg, 256>>>((const float4*)q, (const float4*)k, (const float4*)v,
                               (const float4*)W_q, (const float4*)W_k,
                               (const float4*)W_v, (const float4*)W_o);

    dim3 gg(D_MODEL / 128, M_ROWS / 128, 3);   // (8, 64, 3)
    gemm_qkv<<<gg, 256, GEMM_SMEM>>>(b_q, b_k, b_v);

    dim3 tg(T_SEQ / 32, B_SZ * N_HEADS);
    vtrans_kernel<<<tg, 256>>>();

    dim3 ag(T_SEQ / 128, B_SZ * N_HEADS);      // (16, 64)
    attn_causal<<<ag, 256, attn_smem>>>();

    dim3 go(D_MODEL / 128, M_ROWS / 128);
    gemm_o<<<go, 256, GEMM_SMEM>>>(b_o, out);
}

// round 16
// speedup vs baseline: 5.0240x; 1.1995x over previous
#include <cuda_runtime.h>
#include <cuda_fp16.h>
#include <math.h>
#include <stdint.h>

#define D_MODEL 1024
#define N_HEADS 16
#define B_SZ    4
#define T_SEQ   2048
#define M_ROWS  8192

typedef unsigned int u32;

// scratch (allocation-free rule: __device__ globals)
__device__ __half g_iq [M_ROWS * D_MODEL];                     // fp16 inputs
__device__ __half g_ik [M_ROWS * D_MODEL];
__device__ __half g_iv [M_ROWS * D_MODEL];
__device__ __half g_wq [D_MODEL * D_MODEL];                    // fp16 weights
__device__ __half g_wk [D_MODEL * D_MODEL];
__device__ __half g_wv [D_MODEL * D_MODEL];
__device__ __half g_wo [D_MODEL * D_MODEL];
__device__ __half g_pq [M_ROWS * D_MODEL];                     // fp16 Q proj
__device__ __half g_pk [M_ROWS * D_MODEL];                     // fp16 K proj
__device__ float  g_V  [M_ROWS * D_MODEL];
__device__ __half g_vt [M_ROWS * D_MODEL];                     // fp16 V^T [bh][64][2048]
__device__ __half g_ao [M_ROWS * D_MODEL];                     // fp16 attention out

// ---------------------------------------------------------------------------
__device__ __forceinline__ u32 packf16(float x0, float x1) {
    u32 r;
    asm("cvt.rn.f16x2.f32 %0, %1, %2;" : "=r"(r) : "f"(x1), "f"(x0));
    return r;
}

// fp16 mma
__device__ __forceinline__ void fmma(float d[4], const u32 a[4], u32 b0, u32 b1) {
    asm volatile(
        "mma.sync.aligned.m16n8k16.row.col.f32.f16.f16.f32 "
        "{%0,%1,%2,%3}, {%4,%5,%6,%7}, {%8,%9}, {%0,%1,%2,%3};\n"
        : "+f"(d[0]), "+f"(d[1]), "+f"(d[2]), "+f"(d[3])
        : "r"(a[0]), "r"(a[1]), "r"(a[2]), "r"(a[3]), "r"(b0), "r"(b1));
}

__device__ __forceinline__ void ldsm4(u32& r0, u32& r1, u32& r2, u32& r3, u32 addr) {
    asm volatile("ldmatrix.sync.aligned.m8n8.x4.shared.b16 {%0,%1,%2,%3}, [%4];"
                 : "=r"(r0), "=r"(r1), "=r"(r2), "=r"(r3) : "r"(addr));
}

__device__ __forceinline__ void cpa16(void* smem_ptr, const void* gptr) {
    u32 s = (u32)__cvta_generic_to_shared(smem_ptr);
    asm volatile("cp.async.cg.shared.global [%0], [%1], 16;\n" :: "r"(s), "l"(gptr));
}
__device__ __forceinline__ void cpa_commit() { asm volatile("cp.async.commit_group;\n"); }
template <int N>
__device__ __forceinline__ void cpa_wait() { asm volatile("cp.async.wait_group %0;\n" :: "n"(N)); }

__device__ __forceinline__ u32 smem_u32(const void* p) {
    return (u32)__cvta_generic_to_shared(p);
}

// ---------------------------------------------------------------------------
// fused prep: grid (8192, 7). all segments -> single fp16.
__global__ void __launch_bounds__(256) split7_kernel(
    const float4* __restrict__ q, const float4* __restrict__ k,
    const float4* __restrict__ v,
    const float4* __restrict__ wq, const float4* __restrict__ wk,
    const float4* __restrict__ wv, const float4* __restrict__ wo)
{
    const int seg = blockIdx.y;
    const int i = blockIdx.x * 256 + threadIdx.x;
    const int NI = M_ROWS * D_MODEL / 4, NW = D_MODEL * D_MODEL / 4;

    const float4* src; u32* d; int n4;
    switch (seg) {
        case 0:  src = q;  d = (u32*)g_iq; n4 = NI; break;
        case 1:  src = k;  d = (u32*)g_ik; n4 = NI; break;
        case 2:  src = v;  d = (u32*)g_iv; n4 = NI; break;
        case 3:  src = wq; d = (u32*)g_wq; n4 = NW; break;
        case 4:  src = wk; d = (u32*)g_wk; n4 = NW; break;
        case 5:  src = wv; d = (u32*)g_wv; n4 = NW; break;
        default: src = wo; d = (u32*)g_wo; n4 = NW; break;
    }
    if (i >= n4) return;
    float4 val = src[i];
    d[2 * i]     = packf16(val.x, val.y);
    d[2 * i + 1] = packf16(val.z, val.w);
}

// transpose V per head to fp16: g_V[b][t][h*64+d] -> g_vt[bh][d][t]
__global__ void __launch_bounds__(256) vtrans_kernel()
{
    __shared__ float ts[32][65];
    const int j0 = blockIdx.x * 32;
    const int bh = blockIdx.y;
    const int b = bh >> 4, h = bh & 15;
    const int tid = threadIdx.x;
#pragma unroll
    for (int i = 0; i < 8; i++) {
        int idx = tid + i * 256;
        int r = idx >> 6, c = idx & 63;
        ts[r][c] = g_V[(size_t)(b * T_SEQ + j0 + r) * D_MODEL + h * 64 + c];
    }
    __syncthreads();
    u32* ov = reinterpret_cast<u32*>(g_vt);
#pragma unroll
    for (int i = 0; i < 4; i++) {
        int idx = tid + i * 256;
        int d = idx >> 4, jj = (idx & 15) * 2;
        size_t o = ((size_t)(bh * 64 + d) * T_SEQ + j0 + jj) >> 1;
        ov[o] = packf16(ts[jj][d], ts[jj + 1][d]);
    }
}

// ---------------------------------------------------------------------------
// GEMM body: 1-term FP16, ldmatrix, 64-wide K stages, 2-stage pipeline,
// 2 CTAs/SM.  outmode: 0 = float, 2 = fp16 packed
// ---------------------------------------------------------------------------
#define GSTR 36
#define GT  (128 * GSTR)                 // 4608 words per array per stage
#define GEMM_SMEM (2 * 2 * GT * 4)       // 73728 B

__device__ __forceinline__ void gemm_body(
    char* smb,
    const __half* __restrict__ A, const __half* __restrict__ B,
    const float* __restrict__ bias,
    float* __restrict__ Cf, u32* __restrict__ Ch, int outmode)
{
    const u32 sb = smem_u32(smb);
    const int tid  = threadIdx.x;
    const int lane = tid & 31;
    const int wid  = tid >> 5;
    const int g    = lane >> 2;
    const int q    = lane & 3;
    const int wm   = wid >> 2;
    const int wn   = wid & 3;
    const int bm   = blockIdx.y * 128;
    const int bn   = blockIdx.x * 128;
    const int K = D_MODEL, N = D_MODEL;

    float acc[4][4][4] = {};

    u32* smw = reinterpret_cast<u32*>(smb);
    auto issue = [&](int t, int buf) {
        const int k0 = t * 64;
        u32* base = smw + buf * 2 * GT;
#pragma unroll
        for (int i = 0; i < 8; i++) {
            int idx = tid + i * 256;       // 2048 chunks of 16B
            int arr = idx >> 10;           // 0:A 1:B
            int w   = idx & 1023;
            int row = w >> 3, c = w & 7;
            const __half* gp = arr ? B : A;
            int rb = arr ? bn : bm;
            cpa16(base + arr * GT + row * GSTR + c * 4,
                  gp + (size_t)(rb + row) * K + k0 + c * 8);
        }
    };

    const int NT = K / 64;   // 16
    issue(0, 0); cpa_commit();
    issue(1, 1); cpa_commit();

    const int aRow = (lane & 7) + ((lane >> 3) & 1) * 8;
    const int aK4  = ((lane >> 4) & 1) * 4;
    const int bRow = (lane & 7) + ((lane >> 4) & 1) * 8;
    const int bK4  = ((lane >> 3) & 1) * 4;

    for (int s = 0; s < NT; s++) {
        const int buf = s & 1;
        if (s + 1 < NT) cpa_wait<1>(); else cpa_wait<0>();
        __syncthreads();

        const u32 ab = sb + (u32)(buf * 2 * GT) * 4;
        const u32 bb = ab + GT * 4;

#pragma unroll
        for (int ks = 0; ks < 4; ks++) {
            u32 af[4][4];
#pragma unroll
            for (int mt = 0; mt < 4; mt++) {
                u32 off = ((wm * 64 + mt * 16 + aRow) * GSTR + ks * 8 + aK4) * 4;
                ldsm4(af[mt][0], af[mt][1], af[mt][2], af[mt][3], ab + off);
            }
#pragma unroll
            for (int ntp = 0; ntp < 2; ntp++) {
                u32 off = ((wn * 32 + ntp * 16 + bRow) * GSTR + ks * 8 + bK4) * 4;
                u32 b0, b1, b2, b3;
                ldsm4(b0, b1, b2, b3, bb + off);
#pragma unroll
                for (int mt = 0; mt < 4; mt++) {
                    fmma(acc[mt][2 * ntp],     af[mt], b0, b1);
                    fmma(acc[mt][2 * ntp + 1], af[mt], b2, b3);
                }
            }
        }

        __syncthreads();
        if (s + 2 < NT) { issue(s + 2, buf); cpa_commit(); }
    }

#pragma unroll
    for (int mt = 0; mt < 4; mt++) {
        int row0 = bm + wm * 64 + mt * 16 + g;
#pragma unroll
        for (int nt = 0; nt < 4; nt++) {
            int col = bn + wn * 32 + nt * 8 + 2 * q;
            float b0 = bias[col], b1 = bias[col + 1];
            float v00 = acc[mt][nt][0] + b0, v01 = acc[mt][nt][1] + b1;
            float v10 = acc[mt][nt][2] + b0, v11 = acc[mt][nt][3] + b1;
            if (outmode == 2) {
                size_t o0 = ((size_t)row0 * N + col) >> 1;
                size_t o1 = ((size_t)(row0 + 8) * N + col) >> 1;
                Ch[o0] = packf16(v00, v01);
                Ch[o1] = packf16(v10, v11);
            } else {
                *(float2*)&Cf[(size_t)row0 * N + col]       = make_float2(v00, v01);
                *(float2*)&Cf[(size_t)(row0 + 8) * N + col] = make_float2(v10, v11);
            }
        }
    }
}

__global__ void __launch_bounds__(256, 2) gemm_qkv(
    const float* __restrict__ b_q, const float* __restrict__ b_k,
    const float* __restrict__ b_v)
{
    extern __shared__ char smb[];
    const int z = blockIdx.z;
    if (z == 0)
        gemm_body(smb, g_iq, g_wq, b_q, nullptr, (u32*)g_pq, 2);
    else if (z == 1)
        gemm_body(smb, g_ik, g_wk, b_k, nullptr, (u32*)g_pk, 2);
    else
        gemm_body(smb, g_iv, g_wv, b_v, g_V, nullptr, 0);
}

__global__ void __launch_bounds__(256, 2) gemm_o(
    const float* __restrict__ b_o, float* __restrict__ out)
{
    extern __shared__ char smb[];
    gemm_body(smb, g_ao, g_wo, b_o, out, nullptr, 0);
}

// ---------------------------------------------------------------------------
// Causal flash attention, single-term FP16, 64-wide kv tiles, 2 CTAs/SM,
// exp2-domain softmax. Grid (T/128, B*H), 256 thr = 8 warps x 16 q-rows.
// ---------------------------------------------------------------------------
#define KSTR 36
#define ATW  (64 * KSTR)                   // 2304 words per tile
#define KH_OFF(b) ((b) * ATW)
#define VH_OFF(b) (2 * ATW + (b) * ATW)
#define ATTN_SMEM_W (4 * ATW)              // 9216 words = 36864 B

__global__ void __launch_bounds__(256, 2) attn_causal()
{
    extern __shared__ u32 smw[];
    const u32 sb = smem_u32(smw);

    const int qb = gridDim.x - 1 - blockIdx.x;   // heavy blocks first
    const int bh = blockIdx.y;
    const int b  = bh >> 4;
    const int h  = bh & 15;

    const int tid  = threadIdx.x;
    const int lane = tid & 31;
    const int wq   = tid >> 5;
    const int g    = lane >> 2;
    const int q    = lane & 3;

    const float scale2 = 0.125f * 1.44269504f;   // scale * log2(e)
    const u32* kg = reinterpret_cast<const u32*>(g_pk);
    const u32* vg = reinterpret_cast<const u32*>(g_vt);

    const int aRow = (lane & 7) + ((lane >> 3) & 1) * 8;
    const int aK4  = ((lane >> 4) & 1) * 4;
    const int bRow = (lane & 7) + ((lane >> 4) & 1) * 8;
    const int bK4  = ((lane >> 3) & 1) * 4;

    // ---- stage Q (128 rows x 32 words; overlaps K region) ----
    {
        const u32* qg = reinterpret_cast<const u32*>(g_pq);
#pragma unroll
        for (int i = 0; i < 4; i++) {
            int idx = tid + i * 256;         // 1024 chunks
            int row = idx >> 3, c = idx & 7;
            cpa16(smw + row * KSTR + c * 4,
                  qg + (((size_t)(b * T_SEQ + qb * 128 + row) * D_MODEL + h * 64) >> 1) + c * 4);
        }
        cpa_commit();
        cpa_wait<0>();
        __syncthreads();
    }
    u32 qf[4][4];
#pragma unroll
    for (int kt = 0; kt < 4; kt++) {
        u32 off = ((wq * 16 + aRow) * KSTR + kt * 8 + aK4) * 4;
        ldsm4(qf[kt][0], qf[kt][1], qf[kt][2], qf[kt][3], sb + off);
    }
    __syncthreads();   // Q region reused by K staging

    auto stage_kv = [&](int kb, int buf) {
#pragma unroll
        for (int i = 0; i < 2; i++) {
            int idx = tid + i * 256;
            int row = idx >> 3, c = idx & 7;
            cpa16(smw + KH_OFF(buf) + row * KSTR + c * 4,
                  kg + (((size_t)(b * T_SEQ + kb * 64 + row) * D_MODEL + h * 64) >> 1) + c * 4);
        }
#pragma unroll
        for (int i = 0; i < 2; i++) {
            int idx = tid + i * 256;
            int row = idx >> 3, c = idx & 7;
            cpa16(smw + VH_OFF(buf) + row * KSTR + c * 4,
                  vg + (((size_t)(bh * 64 + row) * T_SEQ) >> 1) + kb * 32 + c * 4);
        }
    };

    stage_kv(0, 0);
    cpa_commit();

    float of[8][4] = {};
    float m0 = -INFINITY, m1 = -INFINITY, l0 = 0.f, l1 = 0.f;
    const int R = qb * 128 + wq * 16;
    const int kbmax = 2 * qb + 1;

    for (int kb = 0; kb <= kbmax; kb++) {
        cpa_wait<0>();
        __syncthreads();
        if (kb + 1 <= kbmax) { stage_kv(kb + 1, (kb + 1) & 1); cpa_commit(); }

        const bool active = (kb * 64 <= R + 15);
        if (active) {
            const u32 kshb = sb + (u32)KH_OFF(kb & 1) * 4;
            const u32 vshb = sb + (u32)VH_OFF(kb & 1) * 4;

            // S = Q K^T
            float sf[8][4] = {};
#pragma unroll
            for (int kt = 0; kt < 4; kt++) {
#pragma unroll
                for (int ntp = 0; ntp < 4; ntp++) {
                    u32 h0, h1, h2, h3;
                    u32 off = ((ntp * 16 + bRow) * KSTR + kt * 8 + bK4) * 4;
                    ldsm4(h0, h1, h2, h3, kshb + off);
                    fmma(sf[2 * ntp],     qf[kt], h0, h1);
                    fmma(sf[2 * ntp + 1], qf[kt], h2, h3);
                }
            }

            // mask (boundary tiles only) + scale into log2 domain
            if (kb * 64 + 63 > R) {
                int r0 = R + g, r1 = r0 + 8;
#pragma unroll
                for (int nt = 0; nt < 8; nt++) {
                    int c0 = kb * 64 + nt * 8 + 2 * q, c1 = c0 + 1;
                    if (c0 > r0) sf[nt][0] = -INFINITY;
                    if (c1 > r0) sf[nt][1] = -INFINITY;
                    if (c0 > r1) sf[nt][2] = -INFINITY;
                    if (c1 > r1) sf[nt][3] = -INFINITY;
                }
            }
#pragma unroll
            for (int nt = 0; nt < 8; nt++) {
                sf[nt][0] *= scale2; sf[nt][1] *= scale2;
                sf[nt][2] *= scale2; sf[nt][3] *= scale2;
            }

            // online softmax (log2 domain)
            float mx0 = -INFINITY, mx1 = -INFINITY;
#pragma unroll
            for (int nt = 0; nt < 8; nt++) {
                mx0 = fmaxf(mx0, fmaxf(sf[nt][0], sf[nt][1]));
                mx1 = fmaxf(mx1, fmaxf(sf[nt][2], sf[nt][3]));
            }
            mx0 = fmaxf(mx0, __shfl_xor_sync(0xffffffffu, mx0, 1));
            mx0 = fmaxf(mx0, __shfl_xor_sync(0xffffffffu, mx0, 2));
            mx1 = fmaxf(mx1, __shfl_xor_sync(0xffffffffu, mx1, 1));
            mx1 = fmaxf(mx1, __shfl_xor_sync(0xffffffffu, mx1, 2));

            float mn0 = fmaxf(m0, mx0), mn1 = fmaxf(m1, mx1);
            float c0 = exp2f(m0 - mn0), c1 = exp2f(m1 - mn1);
            m0 = mn0; m1 = mn1;

            float ls0 = 0.f, ls1 = 0.f;
#pragma unroll
            for (int nt = 0; nt < 8; nt++) {
                sf[nt][0] = exp2f(sf[nt][0] - mn0);
                sf[nt][1] = exp2f(sf[nt][1] - mn0);
                sf[nt][2] = exp2f(sf[nt][2] - mn1);
                sf[nt][3] = exp2f(sf[nt][3] - mn1);
                ls0 += sf[nt][0] + sf[nt][1];
                ls1 += sf[nt][2] + sf[nt][3];
            }
#pragma unroll
            for (int nt = 0; nt < 8; nt++) {
                of[nt][0] *= c0; of[nt][1] *= c0;
                of[nt][2] *= c1; of[nt][3] *= c1;
            }
            ls0 += __shfl_xor_sync(0xffffffffu, ls0, 1);
            ls0 += __shfl_xor_sync(0xffffffffu, ls0, 2);
            ls1 += __shfl_xor_sync(0xffffffffu, ls1, 1);
            ls1 += __shfl_xor_sync(0xffffffffu, ls1, 2);
            l0 = l0 * c0 + ls0;
            l1 = l1 * c1 + ls1;

            // O += P V (P packed fp16 in registers)
#pragma unroll
            for (int jt = 0; jt < 4; jt++) {
                u32 pa[4];
                pa[0] = packf16(sf[2 * jt][0],     sf[2 * jt][1]);
                pa[1] = packf16(sf[2 * jt][2],     sf[2 * jt][3]);
                pa[2] = packf16(sf[2 * jt + 1][0], sf[2 * jt + 1][1]);
                pa[3] = packf16(sf[2 * jt + 1][2], sf[2 * jt + 1][3]);
#pragma unroll
                for (int ntp = 0; ntp < 4; ntp++) {
                    u32 h0, h1, h2, h3;
                    u32 off = ((ntp * 16 + bRow) * KSTR + jt * 8 + bK4) * 4;
                    ldsm4(h0, h1, h2, h3, vshb + off);
                    fmma(of[2 * ntp],     pa, h0, h1);
                    fmma(of[2 * ntp + 1], pa, h2, h3);
                }
            }
        }
    }

    // epilogue: normalize + fp16 write (input to fp16 O-proj)
    float inv0 = 1.0f / l0, inv1 = 1.0f / l1;
    u32* oa = reinterpret_cast<u32*>(g_ao);
    size_t m0i = (size_t)(b * T_SEQ + R + g) * D_MODEL + h * 64;
    size_t m1i = m0i + (size_t)8 * D_MODEL;
#pragma unroll
    for (int nt = 0; nt < 8; nt++) {
        int col = nt * 8 + 2 * q;
        oa[(m0i + col) >> 1] = packf16(of[nt][0] * inv0, of[nt][1] * inv0);
        oa[(m1i + col) >> 1] = packf16(of[nt][2] * inv1, of[nt][3] * inv1);
    }
}

// ---------------------------------------------------------------------------
extern "C" void kernel_launch(void* const* d_in, const int* in_sizes, int n_in,
                              void* d_out, int out_size)
{
    const float* q   = (const float*)d_in[0];
    const float* k   = (const float*)d_in[1];
    const float* v   = (const float*)d_in[2];
    const float* W_q = (const float*)d_in[4];
    const float* b_q = (const float*)d_in[5];
    const float* W_k = (const float*)d_in[6];
    const float* b_k = (const float*)d_in[7];
    const float* W_v = (const float*)d_in[8];
    const float* b_v = (const float*)d_in[9];
    const float* W_o = (const float*)d_in[10];
    const float* b_o = (const float*)d_in[11];
    float* out = (float*)d_out;

    const int attn_smem = ATTN_SMEM_W * 4;   // 36864
    cudaFuncSetAttribute(gemm_qkv, cudaFuncAttributeMaxDynamicSharedMemorySize, GEMM_SMEM);
    cudaFuncSetAttribute(gemm_o,   cudaFuncAttributeMaxDynamicSharedMemorySize, GEMM_SMEM);
    cudaFuncSetAttribute(attn_causal, cudaFuncAttributeMaxDynamicSharedMemorySize, attn_smem);

    dim3 sg(M_ROWS * D_MODEL / 4 / 256, 7);   // (8192, 7)
    split7_kernel<<<sg, 256>>>((const float4*)q, (const float4*)k, (const float4*)v,
                               (const float4*)W_q, (const float4*)W_k,
                               (const float4*)W_v, (const float4*)W_o);

    dim3 gg(D_MODEL / 128, M_ROWS / 128, 3);   // (8, 64, 3)
    gemm_qkv<<<gg, 256, GEMM_SMEM>>>(b_q, b_k, b_v);

    dim3 tg(T_SEQ / 32, B_SZ * N_HEADS);
    vtrans_kernel<<<tg, 256>>>();

    dim3 ag(T_SEQ / 128, B_SZ * N_HEADS);      // (16, 64)
    attn_causal<<<ag, 256, attn_smem>>>();

    dim3 go(D_MODEL / 128, M_ROWS / 128);
    gemm_o<<<go, 256, GEMM_SMEM>>>(b_o, out);
}

// round 17
// speedup vs baseline: 5.1064x; 1.0164x over previous
#include <cuda_runtime.h>
#include <cuda_fp16.h>
#include <math.h>
#include <stdint.h>

#define D_MODEL 1024
#define N_HEADS 16
#define B_SZ    4
#define T_SEQ   2048
#define M_ROWS  8192

typedef unsigned int u32;

// scratch (allocation-free rule: __device__ globals)
__device__ __half g_iq [M_ROWS * D_MODEL];                     // fp16 inputs
__device__ __half g_ik [M_ROWS * D_MODEL];
__device__ __half g_iv [M_ROWS * D_MODEL];
__device__ __half g_wq [D_MODEL * D_MODEL];                    // fp16 weights
__device__ __half g_wk [D_MODEL * D_MODEL];
__device__ __half g_wv [D_MODEL * D_MODEL];
__device__ __half g_wo [D_MODEL * D_MODEL];
__device__ __half g_pq [M_ROWS * D_MODEL];                     // fp16 Q proj
__device__ __half g_pk [M_ROWS * D_MODEL];                     // fp16 K proj
__device__ __half g_vt [M_ROWS * D_MODEL];                     // fp16 V^T [bh][64][2048]
__device__ __half g_ao [M_ROWS * D_MODEL];                     // fp16 attention out

// ---------------------------------------------------------------------------
__device__ __forceinline__ u32 packf16(float x0, float x1) {
    u32 r;
    asm("cvt.rn.f16x2.f32 %0, %1, %2;" : "=r"(r) : "f"(x1), "f"(x0));
    return r;
}

// fp16 mma
__device__ __forceinline__ void fmma(float d[4], const u32 a[4], u32 b0, u32 b1) {
    asm volatile(
        "mma.sync.aligned.m16n8k16.row.col.f32.f16.f16.f32 "
        "{%0,%1,%2,%3}, {%4,%5,%6,%7}, {%8,%9}, {%0,%1,%2,%3};\n"
        : "+f"(d[0]), "+f"(d[1]), "+f"(d[2]), "+f"(d[3])
        : "r"(a[0]), "r"(a[1]), "r"(a[2]), "r"(a[3]), "r"(b0), "r"(b1));
}

__device__ __forceinline__ void ldsm4(u32& r0, u32& r1, u32& r2, u32& r3, u32 addr) {
    asm volatile("ldmatrix.sync.aligned.m8n8.x4.shared.b16 {%0,%1,%2,%3}, [%4];"
                 : "=r"(r0), "=r"(r1), "=r"(r2), "=r"(r3) : "r"(addr));
}

__device__ __forceinline__ void cpa16(void* smem_ptr, const void* gptr) {
    u32 s = (u32)__cvta_generic_to_shared(smem_ptr);
    asm volatile("cp.async.cg.shared.global [%0], [%1], 16;\n" :: "r"(s), "l"(gptr));
}
__device__ __forceinline__ void cpa_commit() { asm volatile("cp.async.commit_group;\n"); }
template <int N>
__device__ __forceinline__ void cpa_wait() { asm volatile("cp.async.wait_group %0;\n" :: "n"(N)); }

__device__ __forceinline__ u32 smem_u32(const void* p) {
    return (u32)__cvta_generic_to_shared(p);
}

// ---------------------------------------------------------------------------
// fused prep: grid (8192, 7). all segments -> single fp16.
__global__ void __launch_bounds__(256) split7_kernel(
    const float4* __restrict__ q, const float4* __restrict__ k,
    const float4* __restrict__ v,
    const float4* __restrict__ wq, const float4* __restrict__ wk,
    const float4* __restrict__ wv, const float4* __restrict__ wo)
{
    const int seg = blockIdx.y;
    const int i = blockIdx.x * 256 + threadIdx.x;
    const int NI = M_ROWS * D_MODEL / 4, NW = D_MODEL * D_MODEL / 4;

    const float4* src; u32* d; int n4;
    switch (seg) {
        case 0:  src = q;  d = (u32*)g_iq; n4 = NI; break;
        case 1:  src = k;  d = (u32*)g_ik; n4 = NI; break;
        case 2:  src = v;  d = (u32*)g_iv; n4 = NI; break;
        case 3:  src = wq; d = (u32*)g_wq; n4 = NW; break;
        case 4:  src = wk; d = (u32*)g_wk; n4 = NW; break;
        case 5:  src = wv; d = (u32*)g_wv; n4 = NW; break;
        default: src = wo; d = (u32*)g_wo; n4 = NW; break;
    }
    if (i >= n4) return;
    float4 val = src[i];
    d[2 * i]     = packf16(val.x, val.y);
    d[2 * i + 1] = packf16(val.z, val.w);
}

// ---------------------------------------------------------------------------
// GEMM body: 1-term FP16, ldmatrix, 64-wide K stages, 3-stage pipeline
// (issue-before-compute), 2 CTAs/SM.
// outmode: 0 = float, 2 = fp16 packed, 3 = fp16 transposed per-head (V path)
// ---------------------------------------------------------------------------
#define GSTR 36
#define GT  (128 * GSTR)                 // 4608 words per array per stage
#define GEMM_SMEM (3 * 2 * GT * 4)       // 110592 B

__device__ __forceinline__ void gemm_body(
    char* smb,
    const __half* __restrict__ A, const __half* __restrict__ B,
    const float* __restrict__ bias,
    float* __restrict__ Cf, u32* __restrict__ Ch, int outmode)
{
    const u32 sb = smem_u32(smb);
    const int tid  = threadIdx.x;
    const int lane = tid & 31;
    const int wid  = tid >> 5;
    const int g    = lane >> 2;
    const int q    = lane & 3;
    const int wm   = wid >> 2;
    const int wn   = wid & 3;
    const int bm   = blockIdx.y * 128;
    const int bn   = blockIdx.x * 128;
    const int K = D_MODEL, N = D_MODEL;

    float acc[4][4][4] = {};

    u32* smw = reinterpret_cast<u32*>(smb);
    auto issue = [&](int t, int buf) {
        const int k0 = t * 64;
        u32* base = smw + buf * 2 * GT;
#pragma unroll
        for (int i = 0; i < 8; i++) {
            int idx = tid + i * 256;       // 2048 chunks of 16B
            int arr = idx >> 10;           // 0:A 1:B
            int w   = idx & 1023;
            int row = w >> 3, c = w & 7;
            const __half* gp = arr ? B : A;
            int rb = arr ? bn : bm;
            cpa16(base + arr * GT + row * GSTR + c * 4,
                  gp + (size_t)(rb + row) * K + k0 + c * 8);
        }
    };

    const int NT = K / 64;   // 16
    issue(0, 0); cpa_commit();
    issue(1, 1); cpa_commit();

    const int aRow = (lane & 7) + ((lane >> 3) & 1) * 8;
    const int aK4  = ((lane >> 4) & 1) * 4;
    const int bRow = (lane & 7) + ((lane >> 4) & 1) * 8;
    const int bK4  = ((lane >> 3) & 1) * 4;

    for (int s = 0; s < NT; s++) {
        const int buf = s % 3;
        if (s + 1 < NT) cpa_wait<1>(); else cpa_wait<0>();
        __syncthreads();
        if (s + 2 < NT) { issue(s + 2, (s + 2) % 3); cpa_commit(); }

        const u32 ab = sb + (u32)(buf * 2 * GT) * 4;
        const u32 bb = ab + GT * 4;

#pragma unroll
        for (int ks = 0; ks < 4; ks++) {
            u32 af[4][4];
#pragma unroll
            for (int mt = 0; mt < 4; mt++) {
                u32 off = ((wm * 64 + mt * 16 + aRow) * GSTR + ks * 8 + aK4) * 4;
                ldsm4(af[mt][0], af[mt][1], af[mt][2], af[mt][3], ab + off);
            }
#pragma unroll
            for (int ntp = 0; ntp < 2; ntp++) {
                u32 off = ((wn * 32 + ntp * 16 + bRow) * GSTR + ks * 8 + bK4) * 4;
                u32 b0, b1, b2, b3;
                ldsm4(b0, b1, b2, b3, bb + off);
#pragma unroll
                for (int mt = 0; mt < 4; mt++) {
                    fmma(acc[mt][2 * ntp],     af[mt], b0, b1);
                    fmma(acc[mt][2 * ntp + 1], af[mt], b2, b3);
                }
            }
        }
    }

    if (outmode == 3) {
        // transpose epilogue: acc -> smem [n][t] fp16 -> g_vt[bh][d][t]
        __syncthreads();   // mainloop smem dead; reuse for transpose
        __half* st = reinterpret_cast<__half*>(smb);
        const int TS = 136;   // half stride (128 + 8 pad)
#pragma unroll
        for (int mt = 0; mt < 4; mt++) {
            int r0 = wm * 64 + mt * 16 + g;
#pragma unroll
            for (int nt = 0; nt < 4; nt++) {
                int cl = wn * 32 + nt * 8 + 2 * q;
                float b0 = bias[bn + cl], b1 = bias[bn + cl + 1];
                st[cl * TS + r0]           = __float2half_rn(acc[mt][nt][0] + b0);
                st[(cl + 1) * TS + r0]     = __float2half_rn(acc[mt][nt][1] + b1);
                st[cl * TS + r0 + 8]       = __float2half_rn(acc[mt][nt][2] + b0);
                st[(cl + 1) * TS + r0 + 8] = __float2half_rn(acc[mt][nt][3] + b1);
            }
        }
        __syncthreads();
        const u32* stw = reinterpret_cast<const u32*>(st);
        u32* gv = reinterpret_cast<u32*>(g_vt);
        const int bb2 = bm / T_SEQ;          // batch
        const int tb  = bm % T_SEQ;          // t base
#pragma unroll
        for (int i = 0; i < 32; i++) {
            int idx = tid + i * 256;          // 8192 u32
            int n = idx >> 6;                 // local n 0..127
            int c = idx & 63;                 // t-pair index
            u32 val = stw[n * 68 + c];        // TS/2 = 68 u32 stride
            int gn = bn + n;
            int hl = gn >> 6, dd = gn & 63;
            size_t o = (((size_t)((bb2 * 16 + hl) * 64 + dd)) * T_SEQ + tb) / 2 + c;
            gv[o] = val;
        }
        return;
    }

#pragma unroll
    for (int mt = 0; mt < 4; mt++) {
        int row0 = bm + wm * 64 + mt * 16 + g;
#pragma unroll
        for (int nt = 0; nt < 4; nt++) {
            int col = bn + wn * 32 + nt * 8 + 2 * q;
            float b0 = bias[col], b1 = bias[col + 1];
            float v00 = acc[mt][nt][0] + b0, v01 = acc[mt][nt][1] + b1;
            float v10 = acc[mt][nt][2] + b0, v11 = acc[mt][nt][3] + b1;
            if (outmode == 2) {
                size_t o0 = ((size_t)row0 * N + col) >> 1;
                size_t o1 = ((size_t)(row0 + 8) * N + col) >> 1;
                Ch[o0] = packf16(v00, v01);
                Ch[o1] = packf16(v10, v11);
            } else {
                *(float2*)&Cf[(size_t)row0 * N + col]       = make_float2(v00, v01);
                *(float2*)&Cf[(size_t)(row0 + 8) * N + col] = make_float2(v10, v11);
            }
        }
    }
}

__global__ void __launch_bounds__(256, 2) gemm_qkv(
    const float* __restrict__ b_q, const float* __restrict__ b_k,
    const float* __restrict__ b_v)
{
    extern __shared__ char smb[];
    const int z = blockIdx.z;
    if (z == 0)
        gemm_body(smb, g_iq, g_wq, b_q, nullptr, (u32*)g_pq, 2);
    else if (z == 1)
        gemm_body(smb, g_ik, g_wk, b_k, nullptr, (u32*)g_pk, 2);
    else
        gemm_body(smb, g_iv, g_wv, b_v, nullptr, nullptr, 3);
}

__global__ void __launch_bounds__(256, 2) gemm_o(
    const float* __restrict__ b_o, float* __restrict__ out)
{
    extern __shared__ char smb[];
    gemm_body(smb, g_ao, g_wo, b_o, out, nullptr, 0);
}

// ---------------------------------------------------------------------------
// Causal flash attention, single-term FP16, 64-wide kv tiles, 2 CTAs/SM,
// exp2-domain softmax. Grid (T/128, B*H), 256 thr = 8 warps x 16 q-rows.
// ---------------------------------------------------------------------------
#define KSTR 36
#define ATW  (64 * KSTR)                   // 2304 words per tile
#define KH_OFF(b) ((b) * ATW)
#define VH_OFF(b) (2 * ATW + (b) * ATW)
#define ATTN_SMEM_W (4 * ATW)              // 9216 words = 36864 B

__global__ void __launch_bounds__(256, 2) attn_causal()
{
    extern __shared__ u32 smw[];
    const u32 sb = smem_u32(smw);

    const int qb = gridDim.x - 1 - blockIdx.x;   // heavy blocks first
    const int bh = blockIdx.y;
    const int b  = bh >> 4;
    const int h  = bh & 15;

    const int tid  = threadIdx.x;
    const int lane = tid & 31;
    const int wq   = tid >> 5;
    const int g    = lane >> 2;
    const int q    = lane & 3;

    const float scale2 = 0.125f * 1.44269504f;   // scale * log2(e)
    const u32* kg = reinterpret_cast<const u32*>(g_pk);
    const u32* vg = reinterpret_cast<const u32*>(g_vt);

    const int aRow = (lane & 7) + ((lane >> 3) & 1) * 8;
    const int aK4  = ((lane >> 4) & 1) * 4;
    const int bRow = (lane & 7) + ((lane >> 4) & 1) * 8;
    const int bK4  = ((lane >> 3) & 1) * 4;

    // ---- stage Q (128 rows x 32 words; overlaps K region) ----
    {
        const u32* qg = reinterpret_cast<const u32*>(g_pq);
#pragma unroll
        for (int i = 0; i < 4; i++) {
            int idx = tid + i * 256;         // 1024 chunks
            int row = idx >> 3, c = idx & 7;
            cpa16(smw + row * KSTR + c * 4,
                  qg + (((size_t)(b * T_SEQ + qb * 128 + row) * D_MODEL + h * 64) >> 1) + c * 4);
        }
        cpa_commit();
        cpa_wait<0>();
        __syncthreads();
    }
    u32 qf[4][4];
#pragma unroll
    for (int kt = 0; kt < 4; kt++) {
        u32 off = ((wq * 16 + aRow) * KSTR + kt * 8 + aK4) * 4;
        ldsm4(qf[kt][0], qf[kt][1], qf[kt][2], qf[kt][3], sb + off);
    }
    __syncthreads();   // Q region reused by K staging

    auto stage_kv = [&](int kb, int buf) {
#pragma unroll
        for (int i = 0; i < 2; i++) {
            int idx = tid + i * 256;
            int row = idx >> 3, c = idx & 7;
            cpa16(smw + KH_OFF(buf) + row * KSTR + c * 4,
                  kg + (((size_t)(b * T_SEQ + kb * 64 + row) * D_MODEL + h * 64) >> 1) + c * 4);
        }
#pragma unroll
        for (int i = 0; i < 2; i++) {
            int idx = tid + i * 256;
            int row = idx >> 3, c = idx & 7;
            cpa16(smw + VH_OFF(buf) + row * KSTR + c * 4,
                  vg + (((size_t)(bh * 64 + row) * T_SEQ) >> 1) + kb * 32 + c * 4);
        }
    };

    stage_kv(0, 0);
    cpa_commit();

    float of[8][4] = {};
    float m0 = -INFINITY, m1 = -INFINITY, l0 = 0.f, l1 = 0.f;
    const int R = qb * 128 + wq * 16;
    const int kbmax = 2 * qb + 1;

    for (int kb = 0; kb <= kbmax; kb++) {
        cpa_wait<0>();
        __syncthreads();
        if (kb + 1 <= kbmax) { stage_kv(kb + 1, (kb + 1) & 1); cpa_commit(); }

        const bool active = (kb * 64 <= R + 15);
        if (active) {
            const u32 kshb = sb + (u32)KH_OFF(kb & 1) * 4;
            const u32 vshb = sb + (u32)VH_OFF(kb & 1) * 4;

            // S = Q K^T
            float sf[8][4] = {};
#pragma unroll
            for (int kt = 0; kt < 4; kt++) {
#pragma unroll
                for (int ntp = 0; ntp < 4; ntp++) {
                    u32 h0, h1, h2, h3;
                    u32 off = ((ntp * 16 + bRow) * KSTR + kt * 8 + bK4) * 4;
                    ldsm4(h0, h1, h2, h3, kshb + off);
                    fmma(sf[2 * ntp],     qf[kt], h0, h1);
                    fmma(sf[2 * ntp + 1], qf[kt], h2, h3);
                }
            }

            // mask (boundary tiles only) + scale into log2 domain
            if (kb * 64 + 63 > R) {
                int r0 = R + g, r1 = r0 + 8;
#pragma unroll
                for (int nt = 0; nt < 8; nt++) {
                    int c0 = kb * 64 + nt * 8 + 2 * q, c1 = c0 + 1;
                    if (c0 > r0) sf[nt][0] = -INFINITY;
                    if (c1 > r0) sf[nt][1] = -INFINITY;
                    if (c0 > r1) sf[nt][2] = -INFINITY;
                    if (c1 > r1) sf[nt][3] = -INFINITY;
                }
            }
#pragma unroll
            for (int nt = 0; nt < 8; nt++) {
                sf[nt][0] *= scale2; sf[nt][1] *= scale2;
                sf[nt][2] *= scale2; sf[nt][3] *= scale2;
            }

            // online softmax (log2 domain)
            float mx0 = -INFINITY, mx1 = -INFINITY;
#pragma unroll
            for (int nt = 0; nt < 8; nt++) {
                mx0 = fmaxf(mx0, fmaxf(sf[nt][0], sf[nt][1]));
                mx1 = fmaxf(mx1, fmaxf(sf[nt][2], sf[nt][3]));
            }
            mx0 = fmaxf(mx0, __shfl_xor_sync(0xffffffffu, mx0, 1));
            mx0 = fmaxf(mx0, __shfl_xor_sync(0xffffffffu, mx0, 2));
            mx1 = fmaxf(mx1, __shfl_xor_sync(0xffffffffu, mx1, 1));
            mx1 = fmaxf(mx1, __shfl_xor_sync(0xffffffffu, mx1, 2));

            float mn0 = fmaxf(m0, mx0), mn1 = fmaxf(m1, mx1);
            float c0 = exp2f(m0 - mn0), c1 = exp2f(m1 - mn1);
            m0 = mn0; m1 = mn1;

            float ls0 = 0.f, ls1 = 0.f;
#pragma unroll
            for (int nt = 0; nt < 8; nt++) {
                sf[nt][0] = exp2f(sf[nt][0] - mn0);
                sf[nt][1] = exp2f(sf[nt][1] - mn0);
                sf[nt][2] = exp2f(sf[nt][2] - mn1);
                sf[nt][3] = exp2f(sf[nt][3] - mn1);
                ls0 += sf[nt][0] + sf[nt][1];
                ls1 += sf[nt][2] + sf[nt][3];
            }
#pragma unroll
            for (int nt = 0; nt < 8; nt++) {
                of[nt][0] *= c0; of[nt][1] *= c0;
                of[nt][2] *= c1; of[nt][3] *= c1;
            }
            ls0 += __shfl_xor_sync(0xffffffffu, ls0, 1);
            ls0 += __shfl_xor_sync(0xffffffffu, ls0, 2);
            ls1 += __shfl_xor_sync(0xffffffffu, ls1, 1);
            ls1 += __shfl_xor_sync(0xffffffffu, ls1, 2);
            l0 = l0 * c0 + ls0;
            l1 = l1 * c1 + ls1;

            // O += P V (P packed fp16 in registers)
#pragma unroll
            for (int jt = 0; jt < 4; jt++) {
                u32 pa[4];
                pa[0] = packf16(sf[2 * jt][0],     sf[2 * jt][1]);
                pa[1] = packf16(sf[2 * jt][2],     sf[2 * jt][3]);
                pa[2] = packf16(sf[2 * jt + 1][0], sf[2 * jt + 1][1]);
                pa[3] = packf16(sf[2 * jt + 1][2], sf[2 * jt + 1][3]);
#pragma unroll
                for (int ntp = 0; ntp < 4; ntp++) {
                    u32 h0, h1, h2, h3;
                    u32 off = ((ntp * 16 + bRow) * KSTR + jt * 8 + bK4) * 4;
                    ldsm4(h0, h1, h2, h3, vshb + off);
                    fmma(of[2 * ntp],     pa, h0, h1);
                    fmma(of[2 * ntp + 1], pa, h2, h3);
                }
            }
        }
    }

    // epilogue: normalize + fp16 write (input to fp16 O-proj)
    float inv0 = 1.0f / l0, inv1 = 1.0f / l1;
    u32* oa = reinterpret_cast<u32*>(g_ao);
    size_t m0i = (size_t)(b * T_SEQ + R + g) * D_MODEL + h * 64;
    size_t m1i = m0i + (size_t)8 * D_MODEL;
#pragma unroll
    for (int nt = 0; nt < 8; nt++) {
        int col = nt * 8 + 2 * q;
        oa[(m0i + col) >> 1] = packf16(of[nt][0] * inv0, of[nt][1] * inv0);
        oa[(m1i + col) >> 1] = packf16(of[nt][2] * inv1, of[nt][3] * inv1);
    }
}

// ---------------------------------------------------------------------------
extern "C" void kernel_launch(void* const* d_in, const int* in_sizes, int n_in,
                              void* d_out, int out_size)
{
    const float* q   = (const float*)d_in[0];
    const float* k   = (const float*)d_in[1];
    const float* v   = (const float*)d_in[2];
    const float* W_q = (const float*)d_in[4];
    const float* b_q = (const float*)d_in[5];
    const float* W_k = (const float*)d_in[6];
    const float* b_k = (const float*)d_in[7];
    const float* W_v = (const float*)d_in[8];
    const float* b_v = (const float*)d_in[9];
    const float* W_o = (const float*)d_in[10];
    const float* b_o = (const float*)d_in[11];
    float* out = (float*)d_out;

    const int attn_smem = ATTN_SMEM_W * 4;   // 36864
    cudaFuncSetAttribute(gemm_qkv, cudaFuncAttributeMaxDynamicSharedMemorySize, GEMM_SMEM);
    cudaFuncSetAttribute(gemm_o,   cudaFuncAttributeMaxDynamicSharedMemorySize, GEMM_SMEM);
    cudaFuncSetAttribute(attn_causal, cudaFuncAttributeMaxDynamicSharedMemorySize, attn_smem);

    dim3 sg(M_ROWS * D_MODEL / 4 / 256, 7);   // (8192, 7)
    split7_kernel<<<sg, 256>>>((const float4*)q, (const float4*)k, (const float4*)v,
                               (const float4*)W_q, (const float4*)W_k,
                               (const float4*)W_v, (const float4*)W_o);

    dim3 gg(D_MODEL / 128, M_ROWS / 128, 3);   // (8, 64, 3)
    gemm_qkv<<<gg, 256, GEMM_SMEM>>>(b_q, b_k, b_v);

    dim3 ag(T_SEQ / 128, B_SZ * N_HEADS);      // (16, 64)
    attn_causal<<<ag, 256, attn_smem>>>();

    dim3 go(D_MODEL / 128, M_ROWS / 128);
    gemm_o<<<go, 256, GEMM_SMEM>>>(b_o, out);
}